// round 11
// baseline (speedup 1.0000x reference)
#include <cuda_runtime.h>
#include <cuda_bf16.h>
#include <stdint.h>
#include <math.h>

// Problem constants
constexpr int cB  = 4;
constexpr int cS  = 2048;
constexpr int cD  = 1024;
constexpr int cH  = 16;
constexpr int cDK = 64;
constexpr int cBH = cB * cH;   // 64

constexpr size_t N_X   = (size_t)3 * cB * cS * cD;
constexpr size_t N_W   = (size_t)4 * cD * cD;
constexpr size_t N_QK  = (size_t)cBH * cS * cDK;
constexpr size_t N_CTX = (size_t)cB * cS * cD;

// bf16 hi/lo planes + flash stats
__device__ __nv_bfloat16 g_xhi[N_X],  g_xlo[N_X];
__device__ __nv_bfloat16 g_whi[N_W],  g_wlo[N_W];
__device__ __nv_bfloat16 g_qhi[N_QK], g_qlo[N_QK];      // (B,H,S,DK) q pre-scaled 0.125
__device__ __nv_bfloat16 g_khi[N_QK], g_klo[N_QK];      // (B,H,S,DK)
__device__ __nv_bfloat16 g_vhi[N_QK], g_vlo[N_QK];      // (B,H,DK,S) transposed
__device__ __nv_bfloat16 g_chi[N_CTX], g_clo[N_CTX];    // ctx planes (B,S,H*DK)
__device__ float g_m[(size_t)cBH * cS];                 // row max of scores
__device__ float g_l[(size_t)cBH * cS];                 // row sum exp

// ---------------------------------------------------------------------------
// helpers
// ---------------------------------------------------------------------------
__device__ __forceinline__ uint32_t smem_u32(const void* p) {
    uint32_t a;
    asm("{ .reg .u64 t; cvta.to.shared.u64 t, %1; cvt.u32.u64 %0, t; }" : "=r"(a) : "l"(p));
    return a;
}
__device__ __forceinline__ void cpa16(uint32_t dst, const void* src) {
    asm volatile("cp.async.cg.shared.global [%0], [%1], 16;" :: "r"(dst), "l"(src));
}
__device__ __forceinline__ void cpa_commit() {
    asm volatile("cp.async.commit_group;" ::: "memory");
}
__device__ __forceinline__ void ldsm4(uint32_t (&r)[4], uint32_t addr) {
    asm volatile("ldmatrix.sync.aligned.m8n8.x4.shared.b16 {%0,%1,%2,%3}, [%4];"
        : "=r"(r[0]), "=r"(r[1]), "=r"(r[2]), "=r"(r[3]) : "r"(addr));
}
__device__ __forceinline__ void mma16816(float (&d)[4], const uint32_t (&a)[4],
                                         uint32_t b0, uint32_t b1) {
    asm volatile("mma.sync.aligned.m16n8k16.row.col.f32.bf16.bf16.f32 "
        "{%0,%1,%2,%3},{%4,%5,%6,%7},{%8,%9},{%0,%1,%2,%3};"
        : "+f"(d[0]), "+f"(d[1]), "+f"(d[2]), "+f"(d[3])
        : "r"(a[0]), "r"(a[1]), "r"(a[2]), "r"(a[3]), "r"(b0), "r"(b1));
}
__device__ __forceinline__ void bf16split(float x, __nv_bfloat16& h, __nv_bfloat16& l) {
    h = __float2bfloat16_rn(x);
    l = __float2bfloat16_rn(x - __bfloat162float(h));
}
// pack two fp32 -> bf16x2 hi word, bf16x2 lo word
__device__ __forceinline__ uint32_t pack_hilo(float a, float b, uint32_t& lo) {
    __nv_bfloat16 ha, la, hb, lb;
    bf16split(a, ha, la);
    bf16split(b, hb, lb);
    lo = (uint32_t)__bfloat16_as_ushort(la) | ((uint32_t)__bfloat16_as_ushort(lb) << 16);
    return (uint32_t)__bfloat16_as_ushort(ha) | ((uint32_t)__bfloat16_as_ushort(hb) << 16);
}

// ---------------------------------------------------------------------------
// Elementwise fp32 -> (hi, lo) bf16 planes
// ---------------------------------------------------------------------------
__global__ __launch_bounds__(256)
void split_kernel(const float* __restrict__ src,
                  __nv_bfloat16* __restrict__ hi, __nv_bfloat16* __restrict__ lo,
                  int n4)
{
    int i = blockIdx.x * 256 + threadIdx.x;
    if (i >= n4) return;
    float4 x = ((const float4*)src)[i];
    __nv_bfloat16 h[4], l[4];
    bf16split(x.x, h[0], l[0]); bf16split(x.y, h[1], l[1]);
    bf16split(x.z, h[2], l[2]); bf16split(x.w, h[3], l[3]);
    ((uint2*)hi)[i] = *(uint2*)h;
    ((uint2*)lo)[i] = *(uint2*)l;
}

// ---------------------------------------------------------------------------
// NT GEMM, bf16x3, cp.async 2-stage (used for proj + outproj).
// MODE 0: fp32 C[m*ldc+n]
// MODE 1: q/k planes scatter (B,H,S,DK)
// MODE 2: v planes transposed scatter (B,H,DK,S)
// ---------------------------------------------------------------------------
template<int BN, int MODE>
__global__ __launch_bounds__(256)
void gemm_bf16x3(const __nv_bfloat16* __restrict__ Ahi, const __nv_bfloat16* __restrict__ Alo,
                 long long aStrZ, int lda,
                 const __nv_bfloat16* __restrict__ Bhi, const __nv_bfloat16* __restrict__ Blo,
                 long long bStrZ, int ldb,
                 float* __restrict__ C, __nv_bfloat16* __restrict__ Chi,
                 __nv_bfloat16* __restrict__ Clo,
                 long long cStrZ, int ldc, int Ktot, float scale)
{
    constexpr int BM = 128, BK = 32;
    constexpr int WARPS_N = BN / 32;
    constexpr int WARPS_M = 8 / WARPS_N;
    constexpr int WM = BM / WARPS_M;
    constexpr int MT = WM / 16;
    constexpr int ROWB = 80;
    constexpr uint32_t OFF_ALO = BM * ROWB;
    constexpr uint32_t OFF_BHI = 2u * BM * ROWB;
    constexpr uint32_t OFF_BLO = 2u * BM * ROWB + BN * ROWB;
    constexpr uint32_t STAGE   = (2u * BM + 2u * BN) * ROWB;

    extern __shared__ __align__(16) uint8_t smem[];
    const uint32_t smBase = smem_u32(smem);

    const int tid  = threadIdx.x;
    const int lane = tid & 31;
    const int wid  = tid >> 5;
    const int warpM = wid / WARPS_N;
    const int warpN = wid % WARPS_N;
    const int mBase = blockIdx.y * BM;
    const int nBase = blockIdx.x * BN;

    const __nv_bfloat16* ahi = Ahi + (size_t)blockIdx.z * aStrZ;
    const __nv_bfloat16* alo = Alo + (size_t)blockIdx.z * aStrZ;
    const __nv_bfloat16* bhi = Bhi + (size_t)blockIdx.z * bStrZ;
    const __nv_bfloat16* blo = Blo + (size_t)blockIdx.z * bStrZ;

    float acc[MT][4][4];
#pragma unroll
    for (int mt = 0; mt < MT; mt++)
#pragma unroll
        for (int nt = 0; nt < 4; nt++)
#pragma unroll
            for (int i = 0; i < 4; i++) acc[mt][nt][i] = 0.0f;

    const int nIter = Ktot / BK;

    auto issue = [&](int it, int s) {
        const int k0 = it * BK;
        const uint32_t sb = smBase + (uint32_t)s * STAGE;
#pragma unroll
        for (int i = 0; i < 2; i++) {
            int idx = tid + i * 256;
            int r = idx >> 2, ce = (idx & 3) * 8;
            size_t g = (size_t)(mBase + r) * lda + k0 + ce;
            uint32_t d = sb + (uint32_t)(r * ROWB + ce * 2);
            cpa16(d, ahi + g);
            cpa16(d + OFF_ALO, alo + g);
        }
#pragma unroll
        for (int i = 0; i < BN / 64; i++) {
            int idx = tid + i * 256;
            int r = idx >> 2, ce = (idx & 3) * 8;
            size_t g = (size_t)(nBase + r) * ldb + k0 + ce;
            uint32_t d = sb + OFF_BHI + (uint32_t)(r * ROWB + ce * 2);
            cpa16(d, bhi + g);
            cpa16(d + (OFF_BLO - OFF_BHI), blo + g);
        }
        cpa_commit();
    };

    const uint32_t aoff = (uint32_t)((warpM * WM + (lane & 15)) * ROWB) + ((lane & 16) ? 16u : 0u);
    const uint32_t boff = (uint32_t)((warpN * 32 + (lane & 15)) * ROWB) + ((lane & 16) ? 16u : 0u);

    issue(0, 0);
    if (nIter > 1) issue(1, 1);

    for (int it = 0; it < nIter; ++it) {
        if (it + 1 < nIter) asm volatile("cp.async.wait_group 1;" ::: "memory");
        else                asm volatile("cp.async.wait_group 0;" ::: "memory");
        __syncthreads();

        const uint32_t sb = smBase + (uint32_t)(it & 1) * STAGE;
        const uint32_t aHiB = sb + aoff;
        const uint32_t aLoB = sb + OFF_ALO + aoff;
        const uint32_t bHiB = sb + OFF_BHI + boff;
        const uint32_t bLoB = sb + OFF_BLO + boff;

#pragma unroll
        for (int ks = 0; ks < 2; ks++) {
            uint32_t fahi[MT][4], falo[MT][4];
            uint32_t fbhi[2][4],  fblo[2][4];
#pragma unroll
            for (int mt = 0; mt < MT; mt++) {
                ldsm4(fahi[mt], aHiB + mt * 16 * ROWB + ks * 32);
                ldsm4(falo[mt], aLoB + mt * 16 * ROWB + ks * 32);
            }
#pragma unroll
            for (int nt2 = 0; nt2 < 2; nt2++) {
                ldsm4(fbhi[nt2], bHiB + nt2 * 16 * ROWB + ks * 32);
                ldsm4(fblo[nt2], bLoB + nt2 * 16 * ROWB + ks * 32);
            }
#pragma unroll
            for (int mt = 0; mt < MT; mt++)
#pragma unroll
                for (int nt = 0; nt < 4; nt++) {
                    const int nt2 = nt >> 1, s = nt & 1;
                    mma16816(acc[mt][nt], fahi[mt], fbhi[nt2][0 + s], fbhi[nt2][2 + s]);
                    mma16816(acc[mt][nt], fahi[mt], fblo[nt2][0 + s], fblo[nt2][2 + s]);
                    mma16816(acc[mt][nt], falo[mt], fbhi[nt2][0 + s], fbhi[nt2][2 + s]);
                }
        }
        __syncthreads();
        if (it + 2 < nIter) issue(it + 2, it & 1);
    }

    float*         c   = C   ? C   + (size_t)blockIdx.z * cStrZ : nullptr;
    __nv_bfloat16* chi = Chi ? Chi + (size_t)blockIdx.z * cStrZ : nullptr;
    __nv_bfloat16* clo = Clo ? Clo + (size_t)blockIdx.z * cStrZ : nullptr;

    const int lr  = lane >> 2;
    const int lc2 = (lane & 3) * 2;
#pragma unroll
    for (int mt = 0; mt < MT; mt++) {
#pragma unroll
        for (int nt = 0; nt < 4; nt++) {
            const int n0 = nBase + warpN * 32 + nt * 8 + lc2;
#pragma unroll
            for (int half = 0; half < 2; half++) {
                const int m = mBase + warpM * WM + mt * 16 + lr + half * 8;
                const float v0 = acc[mt][nt][half * 2 + 0] * scale;
                const float v1 = acc[mt][nt][half * 2 + 1] * scale;
                if (MODE == 0) {
                    *(float2*)&c[(size_t)m * ldc + n0] = make_float2(v0, v1);
                } else if (MODE == 1) {
                    const int bb = m >> 11, ss = m & 2047, h = n0 >> 6, dd = n0 & 63;
                    const size_t idx = (((size_t)(bb * 16 + h)) * 2048 + ss) * 64 + dd;
                    __nv_bfloat162 h2, l2;
                    bf16split(v0, h2.x, l2.x);
                    bf16split(v1, h2.y, l2.y);
                    *(__nv_bfloat162*)&chi[idx] = h2;
                    *(__nv_bfloat162*)&clo[idx] = l2;
                } else { // MODE 2
                    const int bb = m >> 11, ss = m & 2047, h = n0 >> 6, dd = n0 & 63;
                    const size_t i0 = (((size_t)(bb * 16 + h)) * 64 + dd) * 2048 + ss;
                    const size_t i1 = (((size_t)(bb * 16 + h)) * 64 + dd + 1) * 2048 + ss;
                    __nv_bfloat16 h0, l0, h1, l1;
                    bf16split(v0, h0, l0);
                    bf16split(v1, h1, l1);
                    chi[i0] = h0; clo[i0] = l0;
                    chi[i1] = h1; clo[i1] = l1;
                }
            }
        }
    }
}

// ---------------------------------------------------------------------------
// Flash attention: per (q-tile 128, bh).  Loops 16 key-tiles of 128.
// S = QK^T (bf16x3), online softmax, O += P·V (bf16x3, P split in regs).
// Writes ctx planes + per-row m, l.
// ---------------------------------------------------------------------------
__global__ __launch_bounds__(256)
void flash_kernel()
{
    constexpr int QROWB = 144;                 // 64 bf16 = 128B + 16 pad
    constexpr int VROWB = 272;                 // 128 bf16 = 256B + 16 pad
    constexpr uint32_t OFF_QLO   = 128u * QROWB;              // 18432
    constexpr uint32_t OFF_ST0   = 2u * 128u * QROWB;         // 36864
    constexpr uint32_t KLO_OFF   = 128u * QROWB;              // within stage
    constexpr uint32_t VHI_OFF   = 2u * 128u * QROWB;         // 36864 within stage
    constexpr uint32_t VLO_OFF   = VHI_OFF + 64u * VROWB;     // 54272
    constexpr uint32_t STAGE     = VLO_OFF + 64u * VROWB;     // 71680

    extern __shared__ __align__(16) uint8_t smem[];
    const uint32_t sm = smem_u32(smem);

    const int tid = threadIdx.x, lane = tid & 31, warp = tid >> 5;
    const int qt = blockIdx.x, bh = blockIdx.y;
    const int qBase = qt * 128;
    const int b = bh >> 4, h = bh & 15;
    const int lr = lane >> 2;

    const __nv_bfloat16* qhi = g_qhi + (size_t)bh * cS * cDK;
    const __nv_bfloat16* qlo = g_qlo + (size_t)bh * cS * cDK;
    const __nv_bfloat16* khi = g_khi + (size_t)bh * cS * cDK;
    const __nv_bfloat16* klo = g_klo + (size_t)bh * cS * cDK;
    const __nv_bfloat16* vhi = g_vhi + (size_t)bh * cDK * cS;
    const __nv_bfloat16* vlo = g_vlo + (size_t)bh * cDK * cS;

    // ---- issue Q (group 0) ----
    {
#pragma unroll
        for (int i = 0; i < 4; i++) {
            int idx = tid + i * 256;
            int r = idx >> 3, ch = idx & 7;
            size_t g = (size_t)(qBase + r) * 64 + ch * 8;
            uint32_t d = sm + (uint32_t)(r * QROWB + ch * 16);
            cpa16(d, qhi + g);
            cpa16(d + OFF_QLO, qlo + g);
        }
        cpa_commit();
    }
    auto issueKV = [&](int kt, int st) {
        const uint32_t sb = sm + OFF_ST0 + (uint32_t)st * STAGE;
        const int kB = kt * 128;
#pragma unroll
        for (int i = 0; i < 4; i++) {
            int idx = tid + i * 256;
            int r = idx >> 3, ch = idx & 7;
            size_t g = (size_t)(kB + r) * 64 + ch * 8;
            uint32_t d = sb + (uint32_t)(r * QROWB + ch * 16);
            cpa16(d, khi + g);
            cpa16(d + KLO_OFF, klo + g);
        }
#pragma unroll
        for (int i = 0; i < 4; i++) {
            int idx = tid + i * 256;
            int dd = idx >> 4, ch = idx & 15;
            size_t g = (size_t)dd * cS + kB + ch * 8;
            uint32_t d = sb + VHI_OFF + (uint32_t)(dd * VROWB + ch * 16);
            cpa16(d, vhi + g);
            cpa16(d + (VLO_OFF - VHI_OFF), vlo + g);
        }
        cpa_commit();
    };

    issueKV(0, 0);
    issueKV(1, 1);

    float o[8][4];
#pragma unroll
    for (int dt = 0; dt < 8; dt++)
#pragma unroll
        for (int i = 0; i < 4; i++) o[dt][i] = 0.0f;
    float m0 = -1e30f, m1 = -1e30f, l0 = 0.0f, l1 = 0.0f;

    uint32_t qfh[4][4], qfl[4][4];
    const uint32_t qaddr = sm + (uint32_t)((warp * 16 + (lane & 15)) * QROWB) + ((lane & 16) ? 16u : 0u);

    for (int kt = 0; kt < 16; ++kt) {
        if (kt < 15) asm volatile("cp.async.wait_group 1;" ::: "memory");
        else         asm volatile("cp.async.wait_group 0;" ::: "memory");
        __syncthreads();

        if (kt == 0) {
#pragma unroll
            for (int ks = 0; ks < 4; ks++) {
                ldsm4(qfh[ks], qaddr + ks * 32);
                ldsm4(qfl[ks], qaddr + OFF_QLO + ks * 32);
            }
        }

        const uint32_t sb = sm + OFF_ST0 + (uint32_t)(kt & 1) * STAGE;
        const uint32_t kbo = sb + (uint32_t)((lane & 15) * QROWB) + ((lane & 16) ? 16u : 0u);
        const uint32_t vbo = sb + VHI_OFF + (uint32_t)((lane & 15) * VROWB) + ((lane & 16) ? 16u : 0u);

        // ---- S = Q K^T ----
        float s[16][4];
#pragma unroll
        for (int nt = 0; nt < 16; nt++)
#pragma unroll
            for (int i = 0; i < 4; i++) s[nt][i] = 0.0f;

#pragma unroll
        for (int g = 0; g < 8; g++) {
#pragma unroll
            for (int ks = 0; ks < 4; ks++) {
                uint32_t kh[4], kl[4];
                const uint32_t ka = kbo + (uint32_t)(g * 16 * QROWB) + ks * 32;
                ldsm4(kh, ka);
                ldsm4(kl, ka + KLO_OFF);
#pragma unroll
                for (int st2 = 0; st2 < 2; st2++) {
                    mma16816(s[2 * g + st2], qfh[ks], kh[0 + st2], kh[2 + st2]);
                    mma16816(s[2 * g + st2], qfh[ks], kl[0 + st2], kl[2 + st2]);
                    mma16816(s[2 * g + st2], qfl[ks], kh[0 + st2], kh[2 + st2]);
                }
            }
        }

        // ---- online softmax ----
        float rm0 = -1e30f, rm1 = -1e30f;
#pragma unroll
        for (int nt = 0; nt < 16; nt++) {
            rm0 = fmaxf(rm0, fmaxf(s[nt][0], s[nt][1]));
            rm1 = fmaxf(rm1, fmaxf(s[nt][2], s[nt][3]));
        }
        rm0 = fmaxf(rm0, __shfl_xor_sync(0xffffffffu, rm0, 1));
        rm0 = fmaxf(rm0, __shfl_xor_sync(0xffffffffu, rm0, 2));
        rm1 = fmaxf(rm1, __shfl_xor_sync(0xffffffffu, rm1, 1));
        rm1 = fmaxf(rm1, __shfl_xor_sync(0xffffffffu, rm1, 2));

        const float mn0 = fmaxf(m0, rm0), mn1 = fmaxf(m1, rm1);
        const float sc0 = __expf(m0 - mn0), sc1 = __expf(m1 - mn1);
        m0 = mn0; m1 = mn1;

        float rs0 = 0.0f, rs1 = 0.0f;
#pragma unroll
        for (int nt = 0; nt < 16; nt++) {
            s[nt][0] = __expf(s[nt][0] - m0);
            s[nt][1] = __expf(s[nt][1] - m0);
            s[nt][2] = __expf(s[nt][2] - m1);
            s[nt][3] = __expf(s[nt][3] - m1);
            rs0 += s[nt][0] + s[nt][1];
            rs1 += s[nt][2] + s[nt][3];
        }
        rs0 += __shfl_xor_sync(0xffffffffu, rs0, 1);
        rs0 += __shfl_xor_sync(0xffffffffu, rs0, 2);
        rs1 += __shfl_xor_sync(0xffffffffu, rs1, 1);
        rs1 += __shfl_xor_sync(0xffffffffu, rs1, 2);
        l0 = l0 * sc0 + rs0;
        l1 = l1 * sc1 + rs1;

#pragma unroll
        for (int dt = 0; dt < 8; dt++) {
            o[dt][0] *= sc0; o[dt][1] *= sc0;
            o[dt][2] *= sc1; o[dt][3] *= sc1;
        }

        // ---- O += P V  (P repacked in registers as A-frags) ----
#pragma unroll
        for (int ks2 = 0; ks2 < 8; ks2++) {
            uint32_t pah[4], pal[4];
            pah[0] = pack_hilo(s[2 * ks2][0],     s[2 * ks2][1],     pal[0]);
            pah[1] = pack_hilo(s[2 * ks2][2],     s[2 * ks2][3],     pal[1]);
            pah[2] = pack_hilo(s[2 * ks2 + 1][0], s[2 * ks2 + 1][1], pal[2]);
            pah[3] = pack_hilo(s[2 * ks2 + 1][2], s[2 * ks2 + 1][3], pal[3]);
#pragma unroll
            for (int g = 0; g < 4; g++) {
                uint32_t vh[4], vl[4];
                const uint32_t va = vbo + (uint32_t)(g * 16 * VROWB) + ks2 * 32;
                ldsm4(vh, va);
                ldsm4(vl, va + (VLO_OFF - VHI_OFF));
#pragma unroll
                for (int st2 = 0; st2 < 2; st2++) {
                    mma16816(o[2 * g + st2], pah, vh[0 + st2], vh[2 + st2]);
                    mma16816(o[2 * g + st2], pah, vl[0 + st2], vl[2 + st2]);
                    mma16816(o[2 * g + st2], pal, vh[0 + st2], vh[2 + st2]);
                }
            }
        }

        __syncthreads();
        if (kt + 2 < 16) issueKV(kt + 2, kt & 1);
    }

    // ---- epilogue ----
    const float inv0 = 1.0f / l0, inv1 = 1.0f / l1;
    const int row0 = qBase + warp * 16 + lr;
    const int row1 = row0 + 8;
    const int lc2 = (lane & 3) * 2;

    if ((lane & 3) == 0) {
        g_m[(size_t)bh * cS + row0] = m0;
        g_m[(size_t)bh * cS + row1] = m1;
        g_l[(size_t)bh * cS + row0] = l0;
        g_l[(size_t)bh * cS + row1] = l1;
    }

#pragma unroll
    for (int dt = 0; dt < 8; dt++) {
        const int d0 = dt * 8 + lc2;
        const size_t i0 = (((size_t)(b * cS + row0)) * cH + h) * cDK + d0;
        const size_t i1 = (((size_t)(b * cS + row1)) * cH + h) * cDK + d0;
        __nv_bfloat162 h2, l2;
        bf16split(o[dt][0] * inv0, h2.x, l2.x);
        bf16split(o[dt][1] * inv0, h2.y, l2.y);
        *(__nv_bfloat162*)&g_chi[i0] = h2;
        *(__nv_bfloat162*)&g_clo[i0] = l2;
        bf16split(o[dt][2] * inv1, h2.x, l2.x);
        bf16split(o[dt][3] * inv1, h2.y, l2.y);
        *(__nv_bfloat162*)&g_chi[i1] = h2;
        *(__nv_bfloat162*)&g_clo[i1] = l2;
    }
}

// ---------------------------------------------------------------------------
// Sim: per (k-tile, q-tile, b) recompute S for all 16 heads and accumulate
// mean prob.  grid (16, 16, 4).
// ---------------------------------------------------------------------------
__global__ __launch_bounds__(256)
void sim_kernel(float* __restrict__ sim)
{
    constexpr int QROWB = 144;
    constexpr uint32_t QLO_OFF = 128u * QROWB;       // 18432
    constexpr uint32_t KHI_OFF = 2u * 128u * QROWB;  // 36864
    constexpr uint32_t KLO_OFF = KHI_OFF + 128u * QROWB;
    constexpr uint32_t STAGE   = 4u * 128u * QROWB;  // 73728

    extern __shared__ __align__(16) uint8_t smem[];
    const uint32_t sm = smem_u32(smem);

    const int tid = threadIdx.x, lane = tid & 31, warp = tid >> 5;
    const int kt = blockIdx.x, qt = blockIdx.y, b = blockIdx.z;
    const int qBase = qt * 128, kBase = kt * 128;
    const int lr = lane >> 2;

    auto issue = [&](int h, int st) {
        const int bh = b * cH + h;
        const __nv_bfloat16* qhi = g_qhi + (size_t)bh * cS * cDK;
        const __nv_bfloat16* qlo = g_qlo + (size_t)bh * cS * cDK;
        const __nv_bfloat16* khi = g_khi + (size_t)bh * cS * cDK;
        const __nv_bfloat16* klo = g_klo + (size_t)bh * cS * cDK;
        const uint32_t sb = sm + (uint32_t)st * STAGE;
#pragma unroll
        for (int i = 0; i < 4; i++) {
            int idx = tid + i * 256;
            int r = idx >> 3, ch = idx & 7;
            size_t gq = (size_t)(qBase + r) * 64 + ch * 8;
            size_t gk = (size_t)(kBase + r) * 64 + ch * 8;
            uint32_t d = sb + (uint32_t)(r * QROWB + ch * 16);
            cpa16(d, qhi + gq);
            cpa16(d + QLO_OFF, qlo + gq);
            cpa16(d + KHI_OFF, khi + gk);
            cpa16(d + KLO_OFF, klo + gk);
        }
        cpa_commit();
    };

    issue(0, 0);
    issue(1, 1);

    float acc[16][4];
#pragma unroll
    for (int nt = 0; nt < 16; nt++)
#pragma unroll
        for (int i = 0; i < 4; i++) acc[nt][i] = 0.0f;

    const uint32_t frow = (uint32_t)((lane & 15) * QROWB) + ((lane & 16) ? 16u : 0u);

    for (int h = 0; h < 16; ++h) {
        if (h < 15) asm volatile("cp.async.wait_group 1;" ::: "memory");
        else        asm volatile("cp.async.wait_group 0;" ::: "memory");
        __syncthreads();

        const uint32_t sb = sm + (uint32_t)(h & 1) * STAGE;
        const uint32_t qaddr = sb + (uint32_t)(warp * 16 * QROWB) + frow;
        const uint32_t kaddr = sb + KHI_OFF + frow;

        uint32_t qfh[4][4], qfl[4][4];
#pragma unroll
        for (int ks = 0; ks < 4; ks++) {
            ldsm4(qfh[ks], qaddr + ks * 32);
            ldsm4(qfl[ks], qaddr + QLO_OFF + ks * 32);
        }

        const int bh = b * cH + h;
        const float mv0 = __ldg(&g_m[(size_t)bh * cS + qBase + warp * 16 + lr]);
        const float mv1 = __ldg(&g_m[(size_t)bh * cS + qBase + warp * 16 + lr + 8]);
        const float w0  = 0.0625f / __ldg(&g_l[(size_t)bh * cS + qBase + warp * 16 + lr]);
        const float w1  = 0.0625f / __ldg(&g_l[(size_t)bh * cS + qBase + warp * 16 + lr + 8]);

#pragma unroll
        for (int g = 0; g < 8; g++) {
            float s2[2][4];
#pragma unroll
            for (int st2 = 0; st2 < 2; st2++)
#pragma unroll
                for (int i = 0; i < 4; i++) s2[st2][i] = 0.0f;
#pragma unroll
            for (int ks = 0; ks < 4; ks++) {
                uint32_t kh[4], kl[4];
                const uint32_t ka = kaddr + (uint32_t)(g * 16 * QROWB) + ks * 32;
                ldsm4(kh, ka);
                ldsm4(kl, ka + (KLO_OFF - KHI_OFF));
#pragma unroll
                for (int st2 = 0; st2 < 2; st2++) {
                    mma16816(s2[st2], qfh[ks], kh[0 + st2], kh[2 + st2]);
                    mma16816(s2[st2], qfh[ks], kl[0 + st2], kl[2 + st2]);
                    mma16816(s2[st2], qfl[ks], kh[0 + st2], kh[2 + st2]);
                }
            }
#pragma unroll
            for (int st2 = 0; st2 < 2; st2++) {
                const int nt = 2 * g + st2;
                acc[nt][0] += __expf(s2[st2][0] - mv0) * w0;
                acc[nt][1] += __expf(s2[st2][1] - mv0) * w0;
                acc[nt][2] += __expf(s2[st2][2] - mv1) * w1;
                acc[nt][3] += __expf(s2[st2][3] - mv1) * w1;
            }
        }
        __syncthreads();
        if (h + 2 < 16) issue(h + 2, h & 1);
    }

    const int row0 = qBase + warp * 16 + lr;
    const int lc2 = (lane & 3) * 2;
#pragma unroll
    for (int nt = 0; nt < 16; nt++) {
        const int col = kBase + nt * 8 + lc2;
        *(float2*)&sim[((size_t)b * cS + row0) * cS + col]     = make_float2(acc[nt][0], acc[nt][1]);
        *(float2*)&sim[((size_t)b * cS + row0 + 8) * cS + col] = make_float2(acc[nt][2], acc[nt][3]);
    }
}

// ---------------------------------------------------------------------------
// Launch
// ---------------------------------------------------------------------------
extern "C" void kernel_launch(void* const* d_in, const int* in_sizes, int n_in,
                              void* d_out, int out_size)
{
    const float* q_in  = (const float*)d_in[0];
    const float* k_in  = (const float*)d_in[1];
    const float* v_in  = (const float*)d_in[2];
    const float* w_in  = (const float*)d_in[3];
    const float* w_out = (const float*)d_in[4];

    float* out = (float*)d_out;
    float* sim = out + (size_t)cB * cS * cD;

    void *pxh, *pxl, *pwh, *pwl, *pqh, *pql, *pkh, *pkl, *pvh, *pvl, *pch, *pcl;
    cudaGetSymbolAddress(&pxh, g_xhi); cudaGetSymbolAddress(&pxl, g_xlo);
    cudaGetSymbolAddress(&pwh, g_whi); cudaGetSymbolAddress(&pwl, g_wlo);
    cudaGetSymbolAddress(&pqh, g_qhi); cudaGetSymbolAddress(&pql, g_qlo);
    cudaGetSymbolAddress(&pkh, g_khi); cudaGetSymbolAddress(&pkl, g_klo);
    cudaGetSymbolAddress(&pvh, g_vhi); cudaGetSymbolAddress(&pvl, g_vlo);
    cudaGetSymbolAddress(&pch, g_chi); cudaGetSymbolAddress(&pcl, g_clo);

    __nv_bfloat16 *xh = (__nv_bfloat16*)pxh, *xl = (__nv_bfloat16*)pxl;
    __nv_bfloat16 *wh = (__nv_bfloat16*)pwh, *wl = (__nv_bfloat16*)pwl;

    const int SM128 = (2 * 128 + 2 * 128) * 80 * 2;   // 81920
    const int SMF   = 36864 + 2 * 71680;              // 180224 flash
    const int SMS   = 2 * 73728;                      // 147456 sim
    cudaFuncSetAttribute((const void*)gemm_bf16x3<128, 0>, cudaFuncAttributeMaxDynamicSharedMemorySize, SM128);
    cudaFuncSetAttribute((const void*)gemm_bf16x3<128, 1>, cudaFuncAttributeMaxDynamicSharedMemorySize, SM128);
    cudaFuncSetAttribute((const void*)gemm_bf16x3<128, 2>, cudaFuncAttributeMaxDynamicSharedMemorySize, SM128);
    cudaFuncSetAttribute((const void*)flash_kernel, cudaFuncAttributeMaxDynamicSharedMemorySize, SMF);
    cudaFuncSetAttribute((const void*)sim_kernel,   cudaFuncAttributeMaxDynamicSharedMemorySize, SMS);

    // 0. Split inputs
    const size_t nX1 = (size_t)cB * cS * cD;
    split_kernel<<<(int)(nX1 / 4 / 256), 256>>>(q_in, xh,           xl,           (int)(nX1 / 4));
    split_kernel<<<(int)(nX1 / 4 / 256), 256>>>(k_in, xh + nX1,     xl + nX1,     (int)(nX1 / 4));
    split_kernel<<<(int)(nX1 / 4 / 256), 256>>>(v_in, xh + 2 * nX1, xl + 2 * nX1, (int)(nX1 / 4));
    const size_t nW3 = (size_t)3 * cD * cD;
    split_kernel<<<(int)(nW3 / 4 / 256), 256>>>(w_in,  wh,        wl,        (int)(nW3 / 4));
    split_kernel<<<(int)(cD * cD / 4 / 256), 256>>>(w_out, wh + nW3, wl + nW3, (int)(cD * cD / 4));

    // 1. Projections
    dim3 gProj(cD / 128, (cB * cS) / 128, 1);
    gemm_bf16x3<128, 1><<<gProj, 256, SM128>>>(
        xh, xl, 0, cD, wh, wl, 0, cD,
        nullptr, (__nv_bfloat16*)pqh, (__nv_bfloat16*)pql, 0, cD, cD, 0.125f);
    gemm_bf16x3<128, 1><<<gProj, 256, SM128>>>(
        xh + nX1, xl + nX1, 0, cD, wh + (size_t)cD * cD, wl + (size_t)cD * cD, 0, cD,
        nullptr, (__nv_bfloat16*)pkh, (__nv_bfloat16*)pkl, 0, cD, cD, 1.0f);
    gemm_bf16x3<128, 2><<<gProj, 256, SM128>>>(
        xh + 2 * nX1, xl + 2 * nX1, 0, cD, wh + (size_t)2 * cD * cD, wl + (size_t)2 * cD * cD, 0, cD,
        nullptr, (__nv_bfloat16*)pvh, (__nv_bfloat16*)pvl, 0, cD, cD, 1.0f);

    // 2. Flash attention -> ctx planes + m,l
    flash_kernel<<<dim3(cS / 128, cBH), 256, SMF>>>();

    // 3. Sim (recompute scores, mean over heads)
    sim_kernel<<<dim3(cS / 128, cS / 128, cB), 256, SMS>>>(sim);

    // 4. Output projection
    dim3 gOut(cD / 128, (cB * cS) / 128, 1);
    gemm_bf16x3<128, 0><<<gOut, 256, SM128>>>(
        (const __nv_bfloat16*)pch, (const __nv_bfloat16*)pcl, 0, cD,
        wh + nW3, wl + nW3, 0, cD,
        out, nullptr, nullptr, 0, cD, cD, 1.0f);
}

// round 12
// speedup vs baseline: 1.1984x; 1.1984x over previous
#include <cuda_runtime.h>
#include <cuda_bf16.h>
#include <cuda_fp16.h>
#include <stdint.h>
#include <math.h>

// Problem constants
constexpr int cB  = 4;
constexpr int cS  = 2048;
constexpr int cD  = 1024;
constexpr int cH  = 16;
constexpr int cDK = 64;
constexpr int cBH = cB * cH;   // 64

constexpr size_t N_X   = (size_t)3 * cB * cS * cD;
constexpr size_t N_W   = (size_t)4 * cD * cD;
constexpr size_t N_QK  = (size_t)cBH * cS * cDK;
constexpr size_t N_CTX = (size_t)cB * cS * cD;
constexpr size_t N_P   = (size_t)cBH * cS * cS;

// bf16 hi/lo planes + flash stats + fp16 unnormalized P
__device__ __nv_bfloat16 g_xhi[N_X],  g_xlo[N_X];
__device__ __nv_bfloat16 g_whi[N_W],  g_wlo[N_W];
__device__ __nv_bfloat16 g_qhi[N_QK], g_qlo[N_QK];      // (B,H,S,DK) q pre-scaled 0.125
__device__ __nv_bfloat16 g_khi[N_QK], g_klo[N_QK];      // (B,H,S,DK)
__device__ __nv_bfloat16 g_vhi[N_QK], g_vlo[N_QK];      // (B,H,DK,S) transposed
__device__ __nv_bfloat16 g_chi[N_CTX], g_clo[N_CTX];    // ctx planes (B,S,H*DK)
__device__ float g_m[(size_t)cBH * cS];                 // final row max
__device__ float g_l[(size_t)cBH * cS];                 // final row sum
__device__ float g_mrun[(size_t)cBH * 16 * cS];         // running max at key-tile kt
__device__ __half g_ph[N_P];                            // exp(s - m_run) fp16

// ---------------------------------------------------------------------------
// helpers
// ---------------------------------------------------------------------------
__device__ __forceinline__ uint32_t smem_u32(const void* p) {
    uint32_t a;
    asm("{ .reg .u64 t; cvta.to.shared.u64 t, %1; cvt.u32.u64 %0, t; }" : "=r"(a) : "l"(p));
    return a;
}
__device__ __forceinline__ void cpa16(uint32_t dst, const void* src) {
    asm volatile("cp.async.cg.shared.global [%0], [%1], 16;" :: "r"(dst), "l"(src));
}
__device__ __forceinline__ void cpa_commit() {
    asm volatile("cp.async.commit_group;" ::: "memory");
}
__device__ __forceinline__ void ldsm4(uint32_t (&r)[4], uint32_t addr) {
    asm volatile("ldmatrix.sync.aligned.m8n8.x4.shared.b16 {%0,%1,%2,%3}, [%4];"
        : "=r"(r[0]), "=r"(r[1]), "=r"(r[2]), "=r"(r[3]) : "r"(addr));
}
__device__ __forceinline__ void mma16816(float (&d)[4], const uint32_t (&a)[4],
                                         uint32_t b0, uint32_t b1) {
    asm volatile("mma.sync.aligned.m16n8k16.row.col.f32.bf16.bf16.f32 "
        "{%0,%1,%2,%3},{%4,%5,%6,%7},{%8,%9},{%0,%1,%2,%3};"
        : "+f"(d[0]), "+f"(d[1]), "+f"(d[2]), "+f"(d[3])
        : "r"(a[0]), "r"(a[1]), "r"(a[2]), "r"(a[3]), "r"(b0), "r"(b1));
}
__device__ __forceinline__ void bf16split(float x, __nv_bfloat16& h, __nv_bfloat16& l) {
    h = __float2bfloat16_rn(x);
    l = __float2bfloat16_rn(x - __bfloat162float(h));
}
__device__ __forceinline__ uint32_t pack_hilo(float a, float b, uint32_t& lo) {
    __nv_bfloat16 ha, la, hb, lb;
    bf16split(a, ha, la);
    bf16split(b, hb, lb);
    lo = (uint32_t)__bfloat16_as_ushort(la) | ((uint32_t)__bfloat16_as_ushort(lb) << 16);
    return (uint32_t)__bfloat16_as_ushort(ha) | ((uint32_t)__bfloat16_as_ushort(hb) << 16);
}

// ---------------------------------------------------------------------------
// Elementwise fp32 -> (hi, lo) bf16 planes
// ---------------------------------------------------------------------------
__global__ __launch_bounds__(256)
void split_kernel(const float* __restrict__ src,
                  __nv_bfloat16* __restrict__ hi, __nv_bfloat16* __restrict__ lo,
                  int n4)
{
    int i = blockIdx.x * 256 + threadIdx.x;
    if (i >= n4) return;
    float4 x = ((const float4*)src)[i];
    __nv_bfloat16 h[4], l[4];
    bf16split(x.x, h[0], l[0]); bf16split(x.y, h[1], l[1]);
    bf16split(x.z, h[2], l[2]); bf16split(x.w, h[3], l[3]);
    ((uint2*)hi)[i] = *(uint2*)h;
    ((uint2*)lo)[i] = *(uint2*)l;
}

// ---------------------------------------------------------------------------
// NT GEMM, bf16x3, cp.async 2-stage (proj + outproj).
// MODE 0: fp32 C; MODE 1: q/k planes (B,H,S,DK); MODE 2: v planesT (B,H,DK,S)
// ---------------------------------------------------------------------------
template<int BN, int MODE>
__global__ __launch_bounds__(256)
void gemm_bf16x3(const __nv_bfloat16* __restrict__ Ahi, const __nv_bfloat16* __restrict__ Alo,
                 long long aStrZ, int lda,
                 const __nv_bfloat16* __restrict__ Bhi, const __nv_bfloat16* __restrict__ Blo,
                 long long bStrZ, int ldb,
                 float* __restrict__ C, __nv_bfloat16* __restrict__ Chi,
                 __nv_bfloat16* __restrict__ Clo,
                 long long cStrZ, int ldc, int Ktot, float scale)
{
    constexpr int BM = 128, BK = 32;
    constexpr int WARPS_N = BN / 32;
    constexpr int WARPS_M = 8 / WARPS_N;
    constexpr int WM = BM / WARPS_M;
    constexpr int MT = WM / 16;
    constexpr int ROWB = 80;
    constexpr uint32_t OFF_ALO = BM * ROWB;
    constexpr uint32_t OFF_BHI = 2u * BM * ROWB;
    constexpr uint32_t OFF_BLO = 2u * BM * ROWB + BN * ROWB;
    constexpr uint32_t STAGE   = (2u * BM + 2u * BN) * ROWB;

    extern __shared__ __align__(16) uint8_t smem[];
    const uint32_t smBase = smem_u32(smem);

    const int tid  = threadIdx.x;
    const int lane = tid & 31;
    const int wid  = tid >> 5;
    const int warpM = wid / WARPS_N;
    const int warpN = wid % WARPS_N;
    const int mBase = blockIdx.y * BM;
    const int nBase = blockIdx.x * BN;

    const __nv_bfloat16* ahi = Ahi + (size_t)blockIdx.z * aStrZ;
    const __nv_bfloat16* alo = Alo + (size_t)blockIdx.z * aStrZ;
    const __nv_bfloat16* bhi = Bhi + (size_t)blockIdx.z * bStrZ;
    const __nv_bfloat16* blo = Blo + (size_t)blockIdx.z * bStrZ;

    float acc[MT][4][4];
#pragma unroll
    for (int mt = 0; mt < MT; mt++)
#pragma unroll
        for (int nt = 0; nt < 4; nt++)
#pragma unroll
            for (int i = 0; i < 4; i++) acc[mt][nt][i] = 0.0f;

    const int nIter = Ktot / BK;

    auto issue = [&](int it, int s) {
        const int k0 = it * BK;
        const uint32_t sb = smBase + (uint32_t)s * STAGE;
#pragma unroll
        for (int i = 0; i < 2; i++) {
            int idx = tid + i * 256;
            int r = idx >> 2, ce = (idx & 3) * 8;
            size_t g = (size_t)(mBase + r) * lda + k0 + ce;
            uint32_t d = sb + (uint32_t)(r * ROWB + ce * 2);
            cpa16(d, ahi + g);
            cpa16(d + OFF_ALO, alo + g);
        }
#pragma unroll
        for (int i = 0; i < BN / 64; i++) {
            int idx = tid + i * 256;
            int r = idx >> 2, ce = (idx & 3) * 8;
            size_t g = (size_t)(nBase + r) * ldb + k0 + ce;
            uint32_t d = sb + OFF_BHI + (uint32_t)(r * ROWB + ce * 2);
            cpa16(d, bhi + g);
            cpa16(d + (OFF_BLO - OFF_BHI), blo + g);
        }
        cpa_commit();
    };

    const uint32_t aoff = (uint32_t)((warpM * WM + (lane & 15)) * ROWB) + ((lane & 16) ? 16u : 0u);
    const uint32_t boff = (uint32_t)((warpN * 32 + (lane & 15)) * ROWB) + ((lane & 16) ? 16u : 0u);

    issue(0, 0);
    if (nIter > 1) issue(1, 1);

    for (int it = 0; it < nIter; ++it) {
        if (it + 1 < nIter) asm volatile("cp.async.wait_group 1;" ::: "memory");
        else                asm volatile("cp.async.wait_group 0;" ::: "memory");
        __syncthreads();

        const uint32_t sb = smBase + (uint32_t)(it & 1) * STAGE;
        const uint32_t aHiB = sb + aoff;
        const uint32_t aLoB = sb + OFF_ALO + aoff;
        const uint32_t bHiB = sb + OFF_BHI + boff;
        const uint32_t bLoB = sb + OFF_BLO + boff;

#pragma unroll
        for (int ks = 0; ks < 2; ks++) {
            uint32_t fahi[MT][4], falo[MT][4];
            uint32_t fbhi[2][4],  fblo[2][4];
#pragma unroll
            for (int mt = 0; mt < MT; mt++) {
                ldsm4(fahi[mt], aHiB + mt * 16 * ROWB + ks * 32);
                ldsm4(falo[mt], aLoB + mt * 16 * ROWB + ks * 32);
            }
#pragma unroll
            for (int nt2 = 0; nt2 < 2; nt2++) {
                ldsm4(fbhi[nt2], bHiB + nt2 * 16 * ROWB + ks * 32);
                ldsm4(fblo[nt2], bLoB + nt2 * 16 * ROWB + ks * 32);
            }
#pragma unroll
            for (int mt = 0; mt < MT; mt++)
#pragma unroll
                for (int nt = 0; nt < 4; nt++) {
                    const int nt2 = nt >> 1, s = nt & 1;
                    mma16816(acc[mt][nt], fahi[mt], fbhi[nt2][0 + s], fbhi[nt2][2 + s]);
                    mma16816(acc[mt][nt], fahi[mt], fblo[nt2][0 + s], fblo[nt2][2 + s]);
                    mma16816(acc[mt][nt], falo[mt], fbhi[nt2][0 + s], fbhi[nt2][2 + s]);
                }
        }
        __syncthreads();
        if (it + 2 < nIter) issue(it + 2, it & 1);
    }

    float*         c   = C   ? C   + (size_t)blockIdx.z * cStrZ : nullptr;
    __nv_bfloat16* chi = Chi ? Chi + (size_t)blockIdx.z * cStrZ : nullptr;
    __nv_bfloat16* clo = Clo ? Clo + (size_t)blockIdx.z * cStrZ : nullptr;

    const int lr  = lane >> 2;
    const int lc2 = (lane & 3) * 2;
#pragma unroll
    for (int mt = 0; mt < MT; mt++) {
#pragma unroll
        for (int nt = 0; nt < 4; nt++) {
            const int n0 = nBase + warpN * 32 + nt * 8 + lc2;
#pragma unroll
            for (int half = 0; half < 2; half++) {
                const int m = mBase + warpM * WM + mt * 16 + lr + half * 8;
                const float v0 = acc[mt][nt][half * 2 + 0] * scale;
                const float v1 = acc[mt][nt][half * 2 + 1] * scale;
                if (MODE == 0) {
                    *(float2*)&c[(size_t)m * ldc + n0] = make_float2(v0, v1);
                } else if (MODE == 1) {
                    const int bb = m >> 11, ss = m & 2047, h = n0 >> 6, dd = n0 & 63;
                    const size_t idx = (((size_t)(bb * 16 + h)) * 2048 + ss) * 64 + dd;
                    __nv_bfloat162 h2, l2;
                    bf16split(v0, h2.x, l2.x);
                    bf16split(v1, h2.y, l2.y);
                    *(__nv_bfloat162*)&chi[idx] = h2;
                    *(__nv_bfloat162*)&clo[idx] = l2;
                } else { // MODE 2
                    const int bb = m >> 11, ss = m & 2047, h = n0 >> 6, dd = n0 & 63;
                    const size_t i0 = (((size_t)(bb * 16 + h)) * 64 + dd) * 2048 + ss;
                    const size_t i1 = (((size_t)(bb * 16 + h)) * 64 + dd + 1) * 2048 + ss;
                    __nv_bfloat16 h0, l0, h1, l1;
                    bf16split(v0, h0, l0);
                    bf16split(v1, h1, l1);
                    chi[i0] = h0; clo[i0] = l0;
                    chi[i1] = h1; clo[i1] = l1;
                }
            }
        }
    }
}

// ---------------------------------------------------------------------------
// Flash attention: per (q-tile 128, bh).  Also stores exp(s - m_run) as fp16
// (g_ph) and the running max per key-tile (g_mrun) so sim is a cheap pass.
// ---------------------------------------------------------------------------
__global__ __launch_bounds__(256)
void flash_kernel()
{
    constexpr int QROWB = 144;
    constexpr int VROWB = 272;
    constexpr uint32_t OFF_QLO   = 128u * QROWB;
    constexpr uint32_t OFF_ST0   = 2u * 128u * QROWB;
    constexpr uint32_t KLO_OFF   = 128u * QROWB;
    constexpr uint32_t VHI_OFF   = 2u * 128u * QROWB;
    constexpr uint32_t VLO_OFF   = VHI_OFF + 64u * VROWB;
    constexpr uint32_t STAGE     = VLO_OFF + 64u * VROWB;

    extern __shared__ __align__(16) uint8_t smem[];
    const uint32_t sm = smem_u32(smem);

    const int tid = threadIdx.x, lane = tid & 31, warp = tid >> 5;
    const int qt = blockIdx.x, bh = blockIdx.y;
    const int qBase = qt * 128;
    const int b = bh >> 4, h = bh & 15;
    const int lr = lane >> 2;
    const int lc2 = (lane & 3) * 2;
    const int row0 = qBase + warp * 16 + lr;
    const int row1 = row0 + 8;

    const __nv_bfloat16* qhi = g_qhi + (size_t)bh * cS * cDK;
    const __nv_bfloat16* qlo = g_qlo + (size_t)bh * cS * cDK;
    const __nv_bfloat16* khi = g_khi + (size_t)bh * cS * cDK;
    const __nv_bfloat16* klo = g_klo + (size_t)bh * cS * cDK;
    const __nv_bfloat16* vhi = g_vhi + (size_t)bh * cDK * cS;
    const __nv_bfloat16* vlo = g_vlo + (size_t)bh * cDK * cS;

    {
#pragma unroll
        for (int i = 0; i < 4; i++) {
            int idx = tid + i * 256;
            int r = idx >> 3, ch = idx & 7;
            size_t g = (size_t)(qBase + r) * 64 + ch * 8;
            uint32_t d = sm + (uint32_t)(r * QROWB + ch * 16);
            cpa16(d, qhi + g);
            cpa16(d + OFF_QLO, qlo + g);
        }
        cpa_commit();
    }
    auto issueKV = [&](int kt, int st) {
        const uint32_t sb = sm + OFF_ST0 + (uint32_t)st * STAGE;
        const int kB = kt * 128;
#pragma unroll
        for (int i = 0; i < 4; i++) {
            int idx = tid + i * 256;
            int r = idx >> 3, ch = idx & 7;
            size_t g = (size_t)(kB + r) * 64 + ch * 8;
            uint32_t d = sb + (uint32_t)(r * QROWB + ch * 16);
            cpa16(d, khi + g);
            cpa16(d + KLO_OFF, klo + g);
        }
#pragma unroll
        for (int i = 0; i < 4; i++) {
            int idx = tid + i * 256;
            int dd = idx >> 4, ch = idx & 15;
            size_t g = (size_t)dd * cS + kB + ch * 8;
            uint32_t d = sb + VHI_OFF + (uint32_t)(dd * VROWB + ch * 16);
            cpa16(d, vhi + g);
            cpa16(d + (VLO_OFF - VHI_OFF), vlo + g);
        }
        cpa_commit();
    };

    issueKV(0, 0);
    issueKV(1, 1);

    float o[8][4];
#pragma unroll
    for (int dt = 0; dt < 8; dt++)
#pragma unroll
        for (int i = 0; i < 4; i++) o[dt][i] = 0.0f;
    float m0 = -1e30f, m1 = -1e30f, l0 = 0.0f, l1 = 0.0f;

    uint32_t qfh[4][4], qfl[4][4];
    const uint32_t qaddr = sm + (uint32_t)((warp * 16 + (lane & 15)) * QROWB) + ((lane & 16) ? 16u : 0u);

    for (int kt = 0; kt < 16; ++kt) {
        if (kt < 15) asm volatile("cp.async.wait_group 1;" ::: "memory");
        else         asm volatile("cp.async.wait_group 0;" ::: "memory");
        __syncthreads();

        if (kt == 0) {
#pragma unroll
            for (int ks = 0; ks < 4; ks++) {
                ldsm4(qfh[ks], qaddr + ks * 32);
                ldsm4(qfl[ks], qaddr + OFF_QLO + ks * 32);
            }
        }

        const uint32_t sb = sm + OFF_ST0 + (uint32_t)(kt & 1) * STAGE;
        const uint32_t kbo = sb + (uint32_t)((lane & 15) * QROWB) + ((lane & 16) ? 16u : 0u);
        const uint32_t vbo = sb + VHI_OFF + (uint32_t)((lane & 15) * VROWB) + ((lane & 16) ? 16u : 0u);

        // ---- S = Q K^T ----
        float s[16][4];
#pragma unroll
        for (int nt = 0; nt < 16; nt++)
#pragma unroll
            for (int i = 0; i < 4; i++) s[nt][i] = 0.0f;

#pragma unroll
        for (int g = 0; g < 8; g++) {
#pragma unroll
            for (int ks = 0; ks < 4; ks++) {
                uint32_t kh[4], kl[4];
                const uint32_t ka = kbo + (uint32_t)(g * 16 * QROWB) + ks * 32;
                ldsm4(kh, ka);
                ldsm4(kl, ka + KLO_OFF);
#pragma unroll
                for (int st2 = 0; st2 < 2; st2++) {
                    mma16816(s[2 * g + st2], qfh[ks], kh[0 + st2], kh[2 + st2]);
                    mma16816(s[2 * g + st2], qfh[ks], kl[0 + st2], kl[2 + st2]);
                    mma16816(s[2 * g + st2], qfl[ks], kh[0 + st2], kh[2 + st2]);
                }
            }
        }

        // ---- online softmax ----
        float rm0 = -1e30f, rm1 = -1e30f;
#pragma unroll
        for (int nt = 0; nt < 16; nt++) {
            rm0 = fmaxf(rm0, fmaxf(s[nt][0], s[nt][1]));
            rm1 = fmaxf(rm1, fmaxf(s[nt][2], s[nt][3]));
        }
        rm0 = fmaxf(rm0, __shfl_xor_sync(0xffffffffu, rm0, 1));
        rm0 = fmaxf(rm0, __shfl_xor_sync(0xffffffffu, rm0, 2));
        rm1 = fmaxf(rm1, __shfl_xor_sync(0xffffffffu, rm1, 1));
        rm1 = fmaxf(rm1, __shfl_xor_sync(0xffffffffu, rm1, 2));

        const float mn0 = fmaxf(m0, rm0), mn1 = fmaxf(m1, rm1);
        const float sc0 = __expf(m0 - mn0), sc1 = __expf(m1 - mn1);
        m0 = mn0; m1 = mn1;

        float rs0 = 0.0f, rs1 = 0.0f;
#pragma unroll
        for (int nt = 0; nt < 16; nt++) {
            s[nt][0] = __expf(s[nt][0] - m0);
            s[nt][1] = __expf(s[nt][1] - m0);
            s[nt][2] = __expf(s[nt][2] - m1);
            s[nt][3] = __expf(s[nt][3] - m1);
            rs0 += s[nt][0] + s[nt][1];
            rs1 += s[nt][2] + s[nt][3];
        }
        rs0 += __shfl_xor_sync(0xffffffffu, rs0, 1);
        rs0 += __shfl_xor_sync(0xffffffffu, rs0, 2);
        rs1 += __shfl_xor_sync(0xffffffffu, rs1, 1);
        rs1 += __shfl_xor_sync(0xffffffffu, rs1, 2);
        l0 = l0 * sc0 + rs0;
        l1 = l1 * sc1 + rs1;

        // ---- store running max + unnormalized P (fp16) for sim ----
        if ((lane & 3) == 0) {
            g_mrun[((size_t)bh * 16 + kt) * cS + row0] = m0;
            g_mrun[((size_t)bh * 16 + kt) * cS + row1] = m1;
        }
        {
            const int kB = kt * 128;
#pragma unroll
            for (int nt = 0; nt < 16; nt++) {
                const int col = kB + nt * 8 + lc2;
                *(__half2*)&g_ph[((size_t)bh * cS + row0) * cS + col] =
                    __floats2half2_rn(s[nt][0], s[nt][1]);
                *(__half2*)&g_ph[((size_t)bh * cS + row1) * cS + col] =
                    __floats2half2_rn(s[nt][2], s[nt][3]);
            }
        }

#pragma unroll
        for (int dt = 0; dt < 8; dt++) {
            o[dt][0] *= sc0; o[dt][1] *= sc0;
            o[dt][2] *= sc1; o[dt][3] *= sc1;
        }

        // ---- O += P V ----
#pragma unroll
        for (int ks2 = 0; ks2 < 8; ks2++) {
            uint32_t pah[4], pal[4];
            pah[0] = pack_hilo(s[2 * ks2][0],     s[2 * ks2][1],     pal[0]);
            pah[1] = pack_hilo(s[2 * ks2][2],     s[2 * ks2][3],     pal[1]);
            pah[2] = pack_hilo(s[2 * ks2 + 1][0], s[2 * ks2 + 1][1], pal[2]);
            pah[3] = pack_hilo(s[2 * ks2 + 1][2], s[2 * ks2 + 1][3], pal[3]);
#pragma unroll
            for (int g = 0; g < 4; g++) {
                uint32_t vh[4], vl[4];
                const uint32_t va = vbo + (uint32_t)(g * 16 * VROWB) + ks2 * 32;
                ldsm4(vh, va);
                ldsm4(vl, va + (VLO_OFF - VHI_OFF));
#pragma unroll
                for (int st2 = 0; st2 < 2; st2++) {
                    mma16816(o[2 * g + st2], pah, vh[0 + st2], vh[2 + st2]);
                    mma16816(o[2 * g + st2], pah, vl[0 + st2], vl[2 + st2]);
                    mma16816(o[2 * g + st2], pal, vh[0 + st2], vh[2 + st2]);
                }
            }
        }

        __syncthreads();
        if (kt + 2 < 16) issueKV(kt + 2, kt & 1);
    }

    // ---- epilogue ----
    const float inv0 = 1.0f / l0, inv1 = 1.0f / l1;

    if ((lane & 3) == 0) {
        g_m[(size_t)bh * cS + row0] = m0;
        g_m[(size_t)bh * cS + row1] = m1;
        g_l[(size_t)bh * cS + row0] = l0;
        g_l[(size_t)bh * cS + row1] = l1;
    }

#pragma unroll
    for (int dt = 0; dt < 8; dt++) {
        const int d0 = dt * 8 + lc2;
        const size_t i0 = (((size_t)(b * cS + row0)) * cH + h) * cDK + d0;
        const size_t i1 = (((size_t)(b * cS + row1)) * cH + h) * cDK + d0;
        __nv_bfloat162 h2, l2;
        bf16split(o[dt][0] * inv0, h2.x, l2.x);
        bf16split(o[dt][1] * inv0, h2.y, l2.y);
        *(__nv_bfloat162*)&g_chi[i0] = h2;
        *(__nv_bfloat162*)&g_clo[i0] = l2;
        bf16split(o[dt][2] * inv1, h2.x, l2.x);
        bf16split(o[dt][3] * inv1, h2.y, l2.y);
        *(__nv_bfloat162*)&g_chi[i1] = h2;
        *(__nv_bfloat162*)&g_clo[i1] = l2;
    }
}

// ---------------------------------------------------------------------------
// Sim (cheap): sim[b,q,:] = sum_h g_ph[bh,q,:] * exp(m_run - m_final)/(16 l).
// One block per (q, b), 256 threads x 8 cols each.  Thread's 8 cols live in
// one key-tile kt = tid>>4, so one correction factor per head.
// ---------------------------------------------------------------------------
__global__ __launch_bounds__(256)
void simfast_kernel(float* __restrict__ sim)
{
    const int q = blockIdx.x;
    const int b = blockIdx.y;
    const int tid = threadIdx.x;
    const int kt  = tid >> 4;          // 8 cols/thread, 128 cols per kt

    float acc[8] = {};

#pragma unroll 1
    for (int h = 0; h < cH; h++) {
        const int bh = b * cH + h;
        const float mf = __ldg(&g_m[(size_t)bh * cS + q]);
        const float mr = __ldg(&g_mrun[((size_t)bh * 16 + kt) * cS + q]);
        const float f  = __expf(mr - mf) / __ldg(&g_l[(size_t)bh * cS + q]) * 0.0625f;

        const uint4 raw = *(const uint4*)&g_ph[((size_t)bh * cS + q) * cS + tid * 8];
        const __half2* hp = (const __half2*)&raw;
#pragma unroll
        for (int i = 0; i < 4; i++) {
            float2 v = __half22float2(hp[i]);
            acc[2 * i + 0] += f * v.x;
            acc[2 * i + 1] += f * v.y;
        }
    }

    float* s = sim + ((size_t)b * cS + q) * cS + tid * 8;
    *(float4*)&s[0] = make_float4(acc[0], acc[1], acc[2], acc[3]);
    *(float4*)&s[4] = make_float4(acc[4], acc[5], acc[6], acc[7]);
}

// ---------------------------------------------------------------------------
// Launch
// ---------------------------------------------------------------------------
extern "C" void kernel_launch(void* const* d_in, const int* in_sizes, int n_in,
                              void* d_out, int out_size)
{
    const float* q_in  = (const float*)d_in[0];
    const float* k_in  = (const float*)d_in[1];
    const float* v_in  = (const float*)d_in[2];
    const float* w_in  = (const float*)d_in[3];
    const float* w_out = (const float*)d_in[4];

    float* out = (float*)d_out;
    float* sim = out + (size_t)cB * cS * cD;

    void *pxh, *pxl, *pwh, *pwl, *pqh, *pql, *pkh, *pkl, *pvh, *pvl, *pch, *pcl;
    cudaGetSymbolAddress(&pxh, g_xhi); cudaGetSymbolAddress(&pxl, g_xlo);
    cudaGetSymbolAddress(&pwh, g_whi); cudaGetSymbolAddress(&pwl, g_wlo);
    cudaGetSymbolAddress(&pqh, g_qhi); cudaGetSymbolAddress(&pql, g_qlo);
    cudaGetSymbolAddress(&pkh, g_khi); cudaGetSymbolAddress(&pkl, g_klo);
    cudaGetSymbolAddress(&pvh, g_vhi); cudaGetSymbolAddress(&pvl, g_vlo);
    cudaGetSymbolAddress(&pch, g_chi); cudaGetSymbolAddress(&pcl, g_clo);

    __nv_bfloat16 *xh = (__nv_bfloat16*)pxh, *xl = (__nv_bfloat16*)pxl;
    __nv_bfloat16 *wh = (__nv_bfloat16*)pwh, *wl = (__nv_bfloat16*)pwl;

    const int SM128 = (2 * 128 + 2 * 128) * 80 * 2;   // 81920
    const int SMF   = 36864 + 2 * 71680;              // 180224 flash
    cudaFuncSetAttribute((const void*)gemm_bf16x3<128, 0>, cudaFuncAttributeMaxDynamicSharedMemorySize, SM128);
    cudaFuncSetAttribute((const void*)gemm_bf16x3<128, 1>, cudaFuncAttributeMaxDynamicSharedMemorySize, SM128);
    cudaFuncSetAttribute((const void*)gemm_bf16x3<128, 2>, cudaFuncAttributeMaxDynamicSharedMemorySize, SM128);
    cudaFuncSetAttribute((const void*)flash_kernel, cudaFuncAttributeMaxDynamicSharedMemorySize, SMF);

    // 0. Split inputs
    const size_t nX1 = (size_t)cB * cS * cD;
    split_kernel<<<(int)(nX1 / 4 / 256), 256>>>(q_in, xh,           xl,           (int)(nX1 / 4));
    split_kernel<<<(int)(nX1 / 4 / 256), 256>>>(k_in, xh + nX1,     xl + nX1,     (int)(nX1 / 4));
    split_kernel<<<(int)(nX1 / 4 / 256), 256>>>(v_in, xh + 2 * nX1, xl + 2 * nX1, (int)(nX1 / 4));
    const size_t nW3 = (size_t)3 * cD * cD;
    split_kernel<<<(int)(nW3 / 4 / 256), 256>>>(w_in,  wh,        wl,        (int)(nW3 / 4));
    split_kernel<<<(int)(cD * cD / 4 / 256), 256>>>(w_out, wh + nW3, wl + nW3, (int)(cD * cD / 4));

    // 1. Projections
    dim3 gProj(cD / 128, (cB * cS) / 128, 1);
    gemm_bf16x3<128, 1><<<gProj, 256, SM128>>>(
        xh, xl, 0, cD, wh, wl, 0, cD,
        nullptr, (__nv_bfloat16*)pqh, (__nv_bfloat16*)pql, 0, cD, cD, 0.125f);
    gemm_bf16x3<128, 1><<<gProj, 256, SM128>>>(
        xh + nX1, xl + nX1, 0, cD, wh + (size_t)cD * cD, wl + (size_t)cD * cD, 0, cD,
        nullptr, (__nv_bfloat16*)pkh, (__nv_bfloat16*)pkl, 0, cD, cD, 1.0f);
    gemm_bf16x3<128, 2><<<gProj, 256, SM128>>>(
        xh + 2 * nX1, xl + 2 * nX1, 0, cD, wh + (size_t)2 * cD * cD, wl + (size_t)2 * cD * cD, 0, cD,
        nullptr, (__nv_bfloat16*)pvh, (__nv_bfloat16*)pvl, 0, cD, cD, 1.0f);

    // 2. Flash attention -> ctx planes + m,l + fp16 P + m_run
    flash_kernel<<<dim3(cS / 128, cBH), 256, SMF>>>();

    // 3. Sim: cheap weighted-sum pass over stored P
    simfast_kernel<<<dim3(cS, cB), 256>>>(sim);

    // 4. Output projection
    dim3 gOut(cD / 128, (cB * cS) / 128, 1);
    gemm_bf16x3<128, 0><<<gOut, 256, SM128>>>(
        (const __nv_bfloat16*)pch, (const __nv_bfloat16*)pcl, 0, cD,
        wh + nW3, wl + nW3, 0, cD,
        out, nullptr, nullptr, 0, cD, cD, 1.0f);
}

// round 13
// speedup vs baseline: 1.5649x; 1.3058x over previous
#include <cuda_runtime.h>
#include <cuda_bf16.h>
#include <cuda_fp16.h>
#include <stdint.h>
#include <math.h>

// Problem constants
constexpr int cB  = 4;
constexpr int cS  = 2048;
constexpr int cD  = 1024;
constexpr int cH  = 16;
constexpr int cDK = 64;
constexpr int cBH = cB * cH;   // 64

constexpr size_t N_X   = (size_t)3 * cB * cS * cD;
constexpr size_t N_W   = (size_t)4 * cD * cD;
constexpr size_t N_QK  = (size_t)cBH * cS * cDK;
constexpr size_t N_CTX = (size_t)cB * cS * cD;
constexpr size_t N_P   = (size_t)cBH * cS * cS;

// fp16 operand storage
__device__ __half g_x16[N_X];                      // inputs, single fp16
__device__ __half g_whi[N_W], g_wlo[N_W];          // weights, fp16 hi/lo (exact-ish)
__device__ __half g_q16[N_QK];                     // Q single (pre-scaled 0.125), (B,H,S,DK)
__device__ __half g_khi[N_QK], g_klo[N_QK];        // K hi/lo, (B,H,S,DK)
__device__ __half g_v16[N_QK];                     // V single, (B,H,DK,S) transposed
__device__ __half g_c16[N_CTX];                    // ctx single, (B,S,H*DK)
__device__ float g_m[(size_t)cBH * cS];            // final row max
__device__ float g_l[(size_t)cBH * cS];            // final row sum
__device__ float g_mrun[(size_t)cBH * 16 * cS];    // running max per key-tile
__device__ __half g_ph[N_P];                       // exp(s - m_run) fp16

// ---------------------------------------------------------------------------
// helpers
// ---------------------------------------------------------------------------
__device__ __forceinline__ uint32_t smem_u32(const void* p) {
    uint32_t a;
    asm("{ .reg .u64 t; cvta.to.shared.u64 t, %1; cvt.u32.u64 %0, t; }" : "=r"(a) : "l"(p));
    return a;
}
__device__ __forceinline__ void cpa16(uint32_t dst, const void* src) {
    asm volatile("cp.async.cg.shared.global [%0], [%1], 16;" :: "r"(dst), "l"(src));
}
__device__ __forceinline__ void cpa_commit() {
    asm volatile("cp.async.commit_group;" ::: "memory");
}
__device__ __forceinline__ void ldsm4(uint32_t (&r)[4], uint32_t addr) {
    asm volatile("ldmatrix.sync.aligned.m8n8.x4.shared.b16 {%0,%1,%2,%3}, [%4];"
        : "=r"(r[0]), "=r"(r[1]), "=r"(r[2]), "=r"(r[3]) : "r"(addr));
}
__device__ __forceinline__ void mma16816(float (&d)[4], const uint32_t (&a)[4],
                                         uint32_t b0, uint32_t b1) {
    asm volatile("mma.sync.aligned.m16n8k16.row.col.f32.f16.f16.f32 "
        "{%0,%1,%2,%3},{%4,%5,%6,%7},{%8,%9},{%0,%1,%2,%3};"
        : "+f"(d[0]), "+f"(d[1]), "+f"(d[2]), "+f"(d[3])
        : "r"(a[0]), "r"(a[1]), "r"(a[2]), "r"(a[3]), "r"(b0), "r"(b1));
}
__device__ __forceinline__ void h16split(float x, __half& h, __half& l) {
    h = __float2half_rn(x);
    l = __float2half_rn(x - __half2float(h));
}
// pack two fp32 -> fp16x2 hi word + fp16x2 lo word (exact split)
__device__ __forceinline__ uint32_t pack_hilo(float a, float b, uint32_t& lo) {
    __half ha, la, hb, lb;
    h16split(a, ha, la);
    h16split(b, hb, lb);
    lo = (uint32_t)__half_as_ushort(la) | ((uint32_t)__half_as_ushort(lb) << 16);
    return (uint32_t)__half_as_ushort(ha) | ((uint32_t)__half_as_ushort(hb) << 16);
}

// ---------------------------------------------------------------------------
// fp32 -> single fp16 plane
// ---------------------------------------------------------------------------
__global__ __launch_bounds__(256)
void tofp16_kernel(const float* __restrict__ src, __half* __restrict__ dst, int n4)
{
    int i = blockIdx.x * 256 + threadIdx.x;
    if (i >= n4) return;
    float4 x = ((const float4*)src)[i];
    __half2 a = __floats2half2_rn(x.x, x.y);
    __half2 b = __floats2half2_rn(x.z, x.w);
    ((uint2*)dst)[i] = make_uint2(*(uint32_t*)&a, *(uint32_t*)&b);
}

// fp32 -> fp16 hi/lo planes
__global__ __launch_bounds__(256)
void split16_kernel(const float* __restrict__ src,
                    __half* __restrict__ hi, __half* __restrict__ lo, int n4)
{
    int i = blockIdx.x * 256 + threadIdx.x;
    if (i >= n4) return;
    float4 x = ((const float4*)src)[i];
    __half h[4], l[4];
    h16split(x.x, h[0], l[0]); h16split(x.y, h[1], l[1]);
    h16split(x.z, h[2], l[2]); h16split(x.w, h[3], l[3]);
    ((uint2*)hi)[i] = *(uint2*)h;
    ((uint2*)lo)[i] = *(uint2*)l;
}

// ---------------------------------------------------------------------------
// NT GEMM, asymmetric fp16x2:  D[m,n] = sum_k A16[m,k]*(Bhi+Blo)[n,k]
// BM=128, BN=128, BK=32, 256 threads, cp.async 2-stage.
// MODE 0: fp32 C[m*ldc+n] = v*scale
// MODE 1: single fp16 scatter C16a[((bb*16+h)*2048+ss)*64+dd]      (Q)
// MODE 2: hi/lo fp16 scatter  C16a/C16b[same idx]                  (K)
// MODE 3: single fp16 transposed C16a[((bb*16+h)*64+dd)*2048+ss]   (V)
// ---------------------------------------------------------------------------
template<int BN, int MODE>
__global__ __launch_bounds__(256)
void gemm_fp16x2(const __half* __restrict__ A, long long aStrZ, int lda,
                 const __half* __restrict__ Bhi, const __half* __restrict__ Blo,
                 long long bStrZ, int ldb,
                 float* __restrict__ C, __half* __restrict__ C16a,
                 __half* __restrict__ C16b,
                 long long cStrZ, int ldc, int Ktot, float scale)
{
    constexpr int BM = 128, BK = 32;
    constexpr int WARPS_N = BN / 32;          // 4
    constexpr int WARPS_M = 8 / WARPS_N;      // 2
    constexpr int WM = BM / WARPS_M;          // 64
    constexpr int MT = WM / 16;               // 4
    constexpr int ROWB = 80;
    constexpr uint32_t OFF_BHI = BM * ROWB;
    constexpr uint32_t OFF_BLO = BM * ROWB + BN * ROWB;
    constexpr uint32_t STAGE   = (BM + 2u * BN) * ROWB;

    extern __shared__ __align__(16) uint8_t smem[];
    const uint32_t smBase = smem_u32(smem);

    const int tid  = threadIdx.x;
    const int lane = tid & 31;
    const int wid  = tid >> 5;
    const int warpM = wid / WARPS_N;
    const int warpN = wid % WARPS_N;
    const int mBase = blockIdx.y * BM;
    const int nBase = blockIdx.x * BN;

    const __half* a   = A   + (size_t)blockIdx.z * aStrZ;
    const __half* bhi = Bhi + (size_t)blockIdx.z * bStrZ;
    const __half* blo = Blo + (size_t)blockIdx.z * bStrZ;

    float acc[MT][4][4];
#pragma unroll
    for (int mt = 0; mt < MT; mt++)
#pragma unroll
        for (int nt = 0; nt < 4; nt++)
#pragma unroll
            for (int i = 0; i < 4; i++) acc[mt][nt][i] = 0.0f;

    const int nIter = Ktot / BK;

    auto issue = [&](int it, int s) {
        const int k0 = it * BK;
        const uint32_t sb = smBase + (uint32_t)s * STAGE;
#pragma unroll
        for (int i = 0; i < 2; i++) {                 // A single: 128 rows x 4 chunks
            int idx = tid + i * 256;
            int r = idx >> 2, ce = (idx & 3) * 8;
            cpa16(sb + (uint32_t)(r * ROWB + ce * 2),
                  a + (size_t)(mBase + r) * lda + k0 + ce);
        }
#pragma unroll
        for (int i = 0; i < BN / 64; i++) {           // B hi/lo
            int idx = tid + i * 256;
            int r = idx >> 2, ce = (idx & 3) * 8;
            size_t g = (size_t)(nBase + r) * ldb + k0 + ce;
            uint32_t d = sb + OFF_BHI + (uint32_t)(r * ROWB + ce * 2);
            cpa16(d, bhi + g);
            cpa16(d + (OFF_BLO - OFF_BHI), blo + g);
        }
        cpa_commit();
    };

    const uint32_t aoff = (uint32_t)((warpM * WM + (lane & 15)) * ROWB) + ((lane & 16) ? 16u : 0u);
    const uint32_t boff = (uint32_t)((warpN * 32 + (lane & 15)) * ROWB) + ((lane & 16) ? 16u : 0u);

    issue(0, 0);
    if (nIter > 1) issue(1, 1);

    for (int it = 0; it < nIter; ++it) {
        if (it + 1 < nIter) asm volatile("cp.async.wait_group 1;" ::: "memory");
        else                asm volatile("cp.async.wait_group 0;" ::: "memory");
        __syncthreads();

        const uint32_t sb = smBase + (uint32_t)(it & 1) * STAGE;
        const uint32_t aB  = sb + aoff;
        const uint32_t bHiB = sb + OFF_BHI + boff;
        const uint32_t bLoB = sb + OFF_BLO + boff;

#pragma unroll
        for (int ks = 0; ks < 2; ks++) {
            uint32_t fa[MT][4];
            uint32_t fbh[2][4], fbl[2][4];
#pragma unroll
            for (int mt = 0; mt < MT; mt++)
                ldsm4(fa[mt], aB + mt * 16 * ROWB + ks * 32);
#pragma unroll
            for (int nt2 = 0; nt2 < 2; nt2++) {
                ldsm4(fbh[nt2], bHiB + nt2 * 16 * ROWB + ks * 32);
                ldsm4(fbl[nt2], bLoB + nt2 * 16 * ROWB + ks * 32);
            }
#pragma unroll
            for (int mt = 0; mt < MT; mt++)
#pragma unroll
                for (int nt = 0; nt < 4; nt++) {
                    const int nt2 = nt >> 1, s = nt & 1;
                    mma16816(acc[mt][nt], fa[mt], fbh[nt2][0 + s], fbh[nt2][2 + s]);
                    mma16816(acc[mt][nt], fa[mt], fbl[nt2][0 + s], fbl[nt2][2 + s]);
                }
        }
        __syncthreads();
        if (it + 2 < nIter) issue(it + 2, it & 1);
    }

    float*  c   = C    ? C    + (size_t)blockIdx.z * cStrZ : nullptr;
    __half* c1  = C16a ? C16a + (size_t)blockIdx.z * cStrZ : nullptr;
    __half* c2  = C16b ? C16b + (size_t)blockIdx.z * cStrZ : nullptr;

    const int lr  = lane >> 2;
    const int lc2 = (lane & 3) * 2;
#pragma unroll
    for (int mt = 0; mt < MT; mt++) {
#pragma unroll
        for (int nt = 0; nt < 4; nt++) {
            const int n0 = nBase + warpN * 32 + nt * 8 + lc2;
#pragma unroll
            for (int half = 0; half < 2; half++) {
                const int m = mBase + warpM * WM + mt * 16 + lr + half * 8;
                const float v0 = acc[mt][nt][half * 2 + 0] * scale;
                const float v1 = acc[mt][nt][half * 2 + 1] * scale;
                if (MODE == 0) {
                    *(float2*)&c[(size_t)m * ldc + n0] = make_float2(v0, v1);
                } else if (MODE == 1) {
                    const int bb = m >> 11, ss = m & 2047, hh = n0 >> 6, dd = n0 & 63;
                    const size_t idx = (((size_t)(bb * 16 + hh)) * 2048 + ss) * 64 + dd;
                    *(__half2*)&c1[idx] = __floats2half2_rn(v0, v1);
                } else if (MODE == 2) {
                    const int bb = m >> 11, ss = m & 2047, hh = n0 >> 6, dd = n0 & 63;
                    const size_t idx = (((size_t)(bb * 16 + hh)) * 2048 + ss) * 64 + dd;
                    __half h0, l0, h1, l1;
                    h16split(v0, h0, l0);
                    h16split(v1, h1, l1);
                    __half hh2[2] = {h0, h1}, ll2[2] = {l0, l1};
                    *(__half2*)&c1[idx] = *(__half2*)hh2;
                    *(__half2*)&c2[idx] = *(__half2*)ll2;
                } else { // MODE 3
                    const int bb = m >> 11, ss = m & 2047, hh = n0 >> 6, dd = n0 & 63;
                    c1[(((size_t)(bb * 16 + hh)) * 64 + dd)     * 2048 + ss] = __float2half_rn(v0);
                    c1[(((size_t)(bb * 16 + hh)) * 64 + dd + 1) * 2048 + ss] = __float2half_rn(v1);
                }
            }
        }
    }
}

// ---------------------------------------------------------------------------
// Flash attention: per (q-tile 128, bh).  Q single fp16, K hi/lo, V single.
// S = Q·(Khi+Klo), online softmax, O += (Phi+Plo)·V.  Stores fp16 P + m_run.
// ---------------------------------------------------------------------------
__global__ __launch_bounds__(256)
void flash_kernel()
{
    constexpr int QROWB = 144;                 // 64 fp16 = 128B + 16 pad
    constexpr int VROWB = 272;                 // 128 fp16 = 256B + 16 pad
    constexpr uint32_t OFF_ST0 = 128u * QROWB;              // 18432 (Q single)
    constexpr uint32_t KLO_OFF = 128u * QROWB;              // within stage
    constexpr uint32_t V_OFF   = 2u * 128u * QROWB;         // 36864 within stage
    constexpr uint32_t STAGE   = V_OFF + 64u * VROWB;       // 54272

    extern __shared__ __align__(16) uint8_t smem[];
    const uint32_t sm = smem_u32(smem);

    const int tid = threadIdx.x, lane = tid & 31, warp = tid >> 5;
    const int qt = blockIdx.x, bh = blockIdx.y;
    const int qBase = qt * 128;
    const int b = bh >> 4, h = bh & 15;
    const int lr = lane >> 2;
    const int lc2 = (lane & 3) * 2;
    const int row0 = qBase + warp * 16 + lr;
    const int row1 = row0 + 8;

    const __half* q16 = g_q16 + (size_t)bh * cS * cDK;
    const __half* khi = g_khi + (size_t)bh * cS * cDK;
    const __half* klo = g_klo + (size_t)bh * cS * cDK;
    const __half* v16 = g_v16 + (size_t)bh * cDK * cS;

    {
#pragma unroll
        for (int i = 0; i < 4; i++) {
            int idx = tid + i * 256;
            int r = idx >> 3, ch = idx & 7;
            cpa16(sm + (uint32_t)(r * QROWB + ch * 16),
                  q16 + (size_t)(qBase + r) * 64 + ch * 8);
        }
        cpa_commit();
    }
    auto issueKV = [&](int kt, int st) {
        const uint32_t sb = sm + OFF_ST0 + (uint32_t)st * STAGE;
        const int kB = kt * 128;
#pragma unroll
        for (int i = 0; i < 4; i++) {
            int idx = tid + i * 256;
            int r = idx >> 3, ch = idx & 7;
            size_t g = (size_t)(kB + r) * 64 + ch * 8;
            uint32_t d = sb + (uint32_t)(r * QROWB + ch * 16);
            cpa16(d, khi + g);
            cpa16(d + KLO_OFF, klo + g);
        }
#pragma unroll
        for (int i = 0; i < 4; i++) {
            int idx = tid + i * 256;
            int dd = idx >> 4, ch = idx & 15;
            cpa16(sb + V_OFF + (uint32_t)(dd * VROWB + ch * 16),
                  v16 + (size_t)dd * cS + kB + ch * 8);
        }
        cpa_commit();
    };

    issueKV(0, 0);
    issueKV(1, 1);

    float o[8][4];
#pragma unroll
    for (int dt = 0; dt < 8; dt++)
#pragma unroll
        for (int i = 0; i < 4; i++) o[dt][i] = 0.0f;
    float m0 = -1e30f, m1 = -1e30f, l0 = 0.0f, l1 = 0.0f;

    uint32_t qf[4][4];
    const uint32_t qaddr = sm + (uint32_t)((warp * 16 + (lane & 15)) * QROWB) + ((lane & 16) ? 16u : 0u);

    for (int kt = 0; kt < 16; ++kt) {
        if (kt < 15) asm volatile("cp.async.wait_group 1;" ::: "memory");
        else         asm volatile("cp.async.wait_group 0;" ::: "memory");
        __syncthreads();

        if (kt == 0) {
#pragma unroll
            for (int ks = 0; ks < 4; ks++)
                ldsm4(qf[ks], qaddr + ks * 32);
        }

        const uint32_t sb = sm + OFF_ST0 + (uint32_t)(kt & 1) * STAGE;
        const uint32_t kbo = sb + (uint32_t)((lane & 15) * QROWB) + ((lane & 16) ? 16u : 0u);
        const uint32_t vbo = sb + V_OFF + (uint32_t)((lane & 15) * VROWB) + ((lane & 16) ? 16u : 0u);

        // ---- S = Q (Khi + Klo)^T ----
        float s[16][4];
#pragma unroll
        for (int nt = 0; nt < 16; nt++)
#pragma unroll
            for (int i = 0; i < 4; i++) s[nt][i] = 0.0f;

#pragma unroll
        for (int g = 0; g < 8; g++) {
#pragma unroll
            for (int ks = 0; ks < 4; ks++) {
                uint32_t kh[4], kl[4];
                const uint32_t ka = kbo + (uint32_t)(g * 16 * QROWB) + ks * 32;
                ldsm4(kh, ka);
                ldsm4(kl, ka + KLO_OFF);
#pragma unroll
                for (int st2 = 0; st2 < 2; st2++) {
                    mma16816(s[2 * g + st2], qf[ks], kh[0 + st2], kh[2 + st2]);
                    mma16816(s[2 * g + st2], qf[ks], kl[0 + st2], kl[2 + st2]);
                }
            }
        }

        // ---- online softmax ----
        float rm0 = -1e30f, rm1 = -1e30f;
#pragma unroll
        for (int nt = 0; nt < 16; nt++) {
            rm0 = fmaxf(rm0, fmaxf(s[nt][0], s[nt][1]));
            rm1 = fmaxf(rm1, fmaxf(s[nt][2], s[nt][3]));
        }
        rm0 = fmaxf(rm0, __shfl_xor_sync(0xffffffffu, rm0, 1));
        rm0 = fmaxf(rm0, __shfl_xor_sync(0xffffffffu, rm0, 2));
        rm1 = fmaxf(rm1, __shfl_xor_sync(0xffffffffu, rm1, 1));
        rm1 = fmaxf(rm1, __shfl_xor_sync(0xffffffffu, rm1, 2));

        const float mn0 = fmaxf(m0, rm0), mn1 = fmaxf(m1, rm1);
        const float sc0 = __expf(m0 - mn0), sc1 = __expf(m1 - mn1);
        m0 = mn0; m1 = mn1;

        float rs0 = 0.0f, rs1 = 0.0f;
#pragma unroll
        for (int nt = 0; nt < 16; nt++) {
            s[nt][0] = __expf(s[nt][0] - m0);
            s[nt][1] = __expf(s[nt][1] - m0);
            s[nt][2] = __expf(s[nt][2] - m1);
            s[nt][3] = __expf(s[nt][3] - m1);
            rs0 += s[nt][0] + s[nt][1];
            rs1 += s[nt][2] + s[nt][3];
        }
        rs0 += __shfl_xor_sync(0xffffffffu, rs0, 1);
        rs0 += __shfl_xor_sync(0xffffffffu, rs0, 2);
        rs1 += __shfl_xor_sync(0xffffffffu, rs1, 1);
        rs1 += __shfl_xor_sync(0xffffffffu, rs1, 2);
        l0 = l0 * sc0 + rs0;
        l1 = l1 * sc1 + rs1;

        // ---- store running max + unnormalized P (fp16) for sim ----
        if ((lane & 3) == 0) {
            g_mrun[((size_t)bh * 16 + kt) * cS + row0] = m0;
            g_mrun[((size_t)bh * 16 + kt) * cS + row1] = m1;
        }
        {
            const int kB = kt * 128;
#pragma unroll
            for (int nt = 0; nt < 16; nt++) {
                const int col = kB + nt * 8 + lc2;
                *(__half2*)&g_ph[((size_t)bh * cS + row0) * cS + col] =
                    __floats2half2_rn(s[nt][0], s[nt][1]);
                *(__half2*)&g_ph[((size_t)bh * cS + row1) * cS + col] =
                    __floats2half2_rn(s[nt][2], s[nt][3]);
            }
        }

#pragma unroll
        for (int dt = 0; dt < 8; dt++) {
            o[dt][0] *= sc0; o[dt][1] *= sc0;
            o[dt][2] *= sc1; o[dt][3] *= sc1;
        }

        // ---- O += (Phi + Plo) V ----
#pragma unroll
        for (int ks2 = 0; ks2 < 8; ks2++) {
            uint32_t pah[4], pal[4];
            pah[0] = pack_hilo(s[2 * ks2][0],     s[2 * ks2][1],     pal[0]);
            pah[1] = pack_hilo(s[2 * ks2][2],     s[2 * ks2][3],     pal[1]);
            pah[2] = pack_hilo(s[2 * ks2 + 1][0], s[2 * ks2 + 1][1], pal[2]);
            pah[3] = pack_hilo(s[2 * ks2 + 1][2], s[2 * ks2 + 1][3], pal[3]);
#pragma unroll
            for (int g = 0; g < 4; g++) {
                uint32_t vh[4];
                ldsm4(vh, vbo + (uint32_t)(g * 16 * VROWB) + ks2 * 32);
#pragma unroll
                for (int st2 = 0; st2 < 2; st2++) {
                    mma16816(o[2 * g + st2], pah, vh[0 + st2], vh[2 + st2]);
                    mma16816(o[2 * g + st2], pal, vh[0 + st2], vh[2 + st2]);
                }
            }
        }

        __syncthreads();
        if (kt + 2 < 16) issueKV(kt + 2, kt & 1);
    }

    // ---- epilogue: ctx single fp16 + m, l ----
    const float inv0 = 1.0f / l0, inv1 = 1.0f / l1;

    if ((lane & 3) == 0) {
        g_m[(size_t)bh * cS + row0] = m0;
        g_m[(size_t)bh * cS + row1] = m1;
        g_l[(size_t)bh * cS + row0] = l0;
        g_l[(size_t)bh * cS + row1] = l1;
    }

#pragma unroll
    for (int dt = 0; dt < 8; dt++) {
        const int d0 = dt * 8 + lc2;
        const size_t i0 = (((size_t)(b * cS + row0)) * cH + h) * cDK + d0;
        const size_t i1 = (((size_t)(b * cS + row1)) * cH + h) * cDK + d0;
        *(__half2*)&g_c16[i0] = __floats2half2_rn(o[dt][0] * inv0, o[dt][1] * inv0);
        *(__half2*)&g_c16[i1] = __floats2half2_rn(o[dt][2] * inv1, o[dt][3] * inv1);
    }
}

// ---------------------------------------------------------------------------
// Sim: sim[b,q,:] = sum_h g_ph[bh,q,:] * exp(m_run - m_final)/(16 l)
// ---------------------------------------------------------------------------
__global__ __launch_bounds__(256)
void simfast_kernel(float* __restrict__ sim)
{
    const int q = blockIdx.x;
    const int b = blockIdx.y;
    const int tid = threadIdx.x;
    const int kt  = tid >> 4;

    float acc[8] = {};

#pragma unroll 1
    for (int h = 0; h < cH; h++) {
        const int bh = b * cH + h;
        const float mf = __ldg(&g_m[(size_t)bh * cS + q]);
        const float mr = __ldg(&g_mrun[((size_t)bh * 16 + kt) * cS + q]);
        const float f  = __expf(mr - mf) / __ldg(&g_l[(size_t)bh * cS + q]) * 0.0625f;

        const uint4 raw = *(const uint4*)&g_ph[((size_t)bh * cS + q) * cS + tid * 8];
        const __half2* hp = (const __half2*)&raw;
#pragma unroll
        for (int i = 0; i < 4; i++) {
            float2 v = __half22float2(hp[i]);
            acc[2 * i + 0] += f * v.x;
            acc[2 * i + 1] += f * v.y;
        }
    }

    float* s = sim + ((size_t)b * cS + q) * cS + tid * 8;
    *(float4*)&s[0] = make_float4(acc[0], acc[1], acc[2], acc[3]);
    *(float4*)&s[4] = make_float4(acc[4], acc[5], acc[6], acc[7]);
}

// ---------------------------------------------------------------------------
// Launch
// ---------------------------------------------------------------------------
extern "C" void kernel_launch(void* const* d_in, const int* in_sizes, int n_in,
                              void* d_out, int out_size)
{
    const float* q_in  = (const float*)d_in[0];
    const float* k_in  = (const float*)d_in[1];
    const float* v_in  = (const float*)d_in[2];
    const float* w_in  = (const float*)d_in[3];
    const float* w_out = (const float*)d_in[4];

    float* out = (float*)d_out;
    float* sim = out + (size_t)cB * cS * cD;

    void *px, *pwh, *pwl, *pq, *pkh, *pkl, *pv, *pc;
    cudaGetSymbolAddress(&px,  g_x16);
    cudaGetSymbolAddress(&pwh, g_whi); cudaGetSymbolAddress(&pwl, g_wlo);
    cudaGetSymbolAddress(&pq,  g_q16);
    cudaGetSymbolAddress(&pkh, g_khi); cudaGetSymbolAddress(&pkl, g_klo);
    cudaGetSymbolAddress(&pv,  g_v16);
    cudaGetSymbolAddress(&pc,  g_c16);

    __half *x16 = (__half*)px;
    __half *wh = (__half*)pwh, *wl = (__half*)pwl;

    const int SMG = (128 + 2 * 128) * 80 * 2;    // 61440 gemm (2 stages)
    const int SMF = 18432 + 2 * 54272;           // 126976 flash
    cudaFuncSetAttribute((const void*)gemm_fp16x2<128, 0>, cudaFuncAttributeMaxDynamicSharedMemorySize, SMG);
    cudaFuncSetAttribute((const void*)gemm_fp16x2<128, 1>, cudaFuncAttributeMaxDynamicSharedMemorySize, SMG);
    cudaFuncSetAttribute((const void*)gemm_fp16x2<128, 2>, cudaFuncAttributeMaxDynamicSharedMemorySize, SMG);
    cudaFuncSetAttribute((const void*)gemm_fp16x2<128, 3>, cudaFuncAttributeMaxDynamicSharedMemorySize, SMG);
    cudaFuncSetAttribute((const void*)flash_kernel, cudaFuncAttributeMaxDynamicSharedMemorySize, SMF);

    // 0. Convert inputs (single fp16) and weights (fp16 hi/lo)
    const size_t nX1 = (size_t)cB * cS * cD;
    tofp16_kernel<<<(int)(nX1 / 4 / 256), 256>>>(q_in, x16,           (int)(nX1 / 4));
    tofp16_kernel<<<(int)(nX1 / 4 / 256), 256>>>(k_in, x16 + nX1,     (int)(nX1 / 4));
    tofp16_kernel<<<(int)(nX1 / 4 / 256), 256>>>(v_in, x16 + 2 * nX1, (int)(nX1 / 4));
    const size_t nW3 = (size_t)3 * cD * cD;
    split16_kernel<<<(int)(nW3 / 4 / 256), 256>>>(w_in,  wh,        wl,        (int)(nW3 / 4));
    split16_kernel<<<(int)(cD * cD / 4 / 256), 256>>>(w_out, wh + nW3, wl + nW3, (int)(cD * cD / 4));

    // 1. Projections: M=8192, N=1024, K=1024
    dim3 gProj(cD / 128, (cB * cS) / 128, 1);
    gemm_fp16x2<128, 1><<<gProj, 256, SMG>>>(
        x16, 0, cD, wh, wl, 0, cD,
        nullptr, (__half*)pq, nullptr, 0, cD, cD, 0.125f);
    gemm_fp16x2<128, 2><<<gProj, 256, SMG>>>(
        x16 + nX1, 0, cD, wh + (size_t)cD * cD, wl + (size_t)cD * cD, 0, cD,
        nullptr, (__half*)pkh, (__half*)pkl, 0, cD, cD, 1.0f);
    gemm_fp16x2<128, 3><<<gProj, 256, SMG>>>(
        x16 + 2 * nX1, 0, cD, wh + (size_t)2 * cD * cD, wl + (size_t)2 * cD * cD, 0, cD,
        nullptr, (__half*)pv, nullptr, 0, cD, cD, 1.0f);

    // 2. Flash attention -> ctx fp16 + m,l + fp16 P + m_run
    flash_kernel<<<dim3(cS / 128, cBH), 256, SMF>>>();

    // 3. Sim: cheap weighted-sum pass
    simfast_kernel<<<dim3(cS, cB), 256>>>(sim);

    // 4. Output projection: M=8192, N=1024, K=1024 -> out fp32
    dim3 gOut(cD / 128, (cB * cS) / 128, 1);
    gemm_fp16x2<128, 0><<<gOut, 256, SMG>>>(
        (const __half*)pc, 0, cD, wh + nW3, wl + nW3, 0, cD,
        out, nullptr, nullptr, 0, cD, cD, 1.0f);
}

// round 14
// speedup vs baseline: 1.5650x; 1.0000x over previous
#include <cuda_runtime.h>
#include <cuda_bf16.h>
#include <cuda_fp16.h>
#include <stdint.h>
#include <math.h>

// Problem constants
constexpr int cB  = 4;
constexpr int cS  = 2048;
constexpr int cD  = 1024;
constexpr int cH  = 16;
constexpr int cDK = 64;
constexpr int cBH = cB * cH;   // 64

constexpr size_t N_X   = (size_t)3 * cB * cS * cD;
constexpr size_t N_W   = (size_t)4 * cD * cD;
constexpr size_t N_QK  = (size_t)cBH * cS * cDK;
constexpr size_t N_CTX = (size_t)cB * cS * cD;
constexpr size_t N_P   = (size_t)cBH * cS * cS;

// fp16 operand storage
__device__ __half g_x16[N_X];                      // inputs, single fp16
__device__ __half g_whi[N_W], g_wlo[N_W];          // weights, fp16 hi/lo
__device__ __half g_q16[N_QK];                     // Q single (pre-scaled), (B,H,S,DK)
__device__ __half g_khi[N_QK], g_klo[N_QK];        // K hi/lo, (B,H,S,DK)
__device__ __half g_v16[N_QK];                     // V single, (B,H,DK,S) transposed
__device__ __half g_c16[N_CTX];                    // ctx single, (B,S,H*DK)
__device__ float g_m[(size_t)cBH * cS];
__device__ float g_l[(size_t)cBH * cS];
__device__ float g_mrun[(size_t)cBH * 16 * cS];
__device__ __half g_ph[N_P];                       // exp(s - m_run) fp16

// ---------------------------------------------------------------------------
// helpers
// ---------------------------------------------------------------------------
__device__ __forceinline__ uint32_t smem_u32(const void* p) {
    uint32_t a;
    asm("{ .reg .u64 t; cvta.to.shared.u64 t, %1; cvt.u32.u64 %0, t; }" : "=r"(a) : "l"(p));
    return a;
}
__device__ __forceinline__ void cpa16(uint32_t dst, const void* src) {
    asm volatile("cp.async.cg.shared.global [%0], [%1], 16;" :: "r"(dst), "l"(src));
}
__device__ __forceinline__ void cpa_commit() {
    asm volatile("cp.async.commit_group;" ::: "memory");
}
__device__ __forceinline__ void cpa_wait(int rem) {
    if (rem >= 2)      asm volatile("cp.async.wait_group 2;" ::: "memory");
    else if (rem == 1) asm volatile("cp.async.wait_group 1;" ::: "memory");
    else               asm volatile("cp.async.wait_group 0;" ::: "memory");
}
__device__ __forceinline__ void ldsm4(uint32_t (&r)[4], uint32_t addr) {
    asm volatile("ldmatrix.sync.aligned.m8n8.x4.shared.b16 {%0,%1,%2,%3}, [%4];"
        : "=r"(r[0]), "=r"(r[1]), "=r"(r[2]), "=r"(r[3]) : "r"(addr));
}
__device__ __forceinline__ void mma16816(float (&d)[4], const uint32_t (&a)[4],
                                         uint32_t b0, uint32_t b1) {
    asm volatile("mma.sync.aligned.m16n8k16.row.col.f32.f16.f16.f32 "
        "{%0,%1,%2,%3},{%4,%5,%6,%7},{%8,%9},{%0,%1,%2,%3};"
        : "+f"(d[0]), "+f"(d[1]), "+f"(d[2]), "+f"(d[3])
        : "r"(a[0]), "r"(a[1]), "r"(a[2]), "r"(a[3]), "r"(b0), "r"(b1));
}
__device__ __forceinline__ void h16split(float x, __half& h, __half& l) {
    h = __float2half_rn(x);
    l = __float2half_rn(x - __half2float(h));
}
__device__ __forceinline__ uint32_t pack_hilo(float a, float b, uint32_t& lo) {
    __half ha, la, hb, lb;
    h16split(a, ha, la);
    h16split(b, hb, lb);
    lo = (uint32_t)__half_as_ushort(la) | ((uint32_t)__half_as_ushort(lb) << 16);
    return (uint32_t)__half_as_ushort(ha) | ((uint32_t)__half_as_ushort(hb) << 16);
}

// ---------------------------------------------------------------------------
// fp32 -> single fp16 / hi+lo fp16 planes
// ---------------------------------------------------------------------------
__global__ __launch_bounds__(256)
void tofp16_kernel(const float* __restrict__ src, __half* __restrict__ dst, int n4)
{
    int i = blockIdx.x * 256 + threadIdx.x;
    if (i >= n4) return;
    float4 x = ((const float4*)src)[i];
    __half2 a = __floats2half2_rn(x.x, x.y);
    __half2 b = __floats2half2_rn(x.z, x.w);
    ((uint2*)dst)[i] = make_uint2(*(uint32_t*)&a, *(uint32_t*)&b);
}

__global__ __launch_bounds__(256)
void split16_kernel(const float* __restrict__ src,
                    __half* __restrict__ hi, __half* __restrict__ lo, int n4)
{
    int i = blockIdx.x * 256 + threadIdx.x;
    if (i >= n4) return;
    float4 x = ((const float4*)src)[i];
    __half h[4], l[4];
    h16split(x.x, h[0], l[0]); h16split(x.y, h[1], l[1]);
    h16split(x.z, h[2], l[2]); h16split(x.w, h[3], l[3]);
    ((uint2*)hi)[i] = *(uint2*)h;
    ((uint2*)lo)[i] = *(uint2*)l;
}

// ---------------------------------------------------------------------------
// NT GEMM, asymmetric fp16x2, cp.async 3-stage.
// D[m,n] = sum_k A16[m,k]*(Bhi+Blo)[n,k]
// MODE 0: fp32 C; MODE 1: Q single scatter; MODE 2: K hi/lo scatter;
// MODE 3: V single transposed scatter
// ---------------------------------------------------------------------------
template<int BN, int MODE>
__global__ __launch_bounds__(256)
void gemm_fp16x2(const __half* __restrict__ A, long long aStrZ, int lda,
                 const __half* __restrict__ Bhi, const __half* __restrict__ Blo,
                 long long bStrZ, int ldb,
                 float* __restrict__ C, __half* __restrict__ C16a,
                 __half* __restrict__ C16b,
                 long long cStrZ, int ldc, int Ktot, float scale)
{
    constexpr int BM = 128, BK = 32;
    constexpr int WARPS_N = BN / 32;          // 4
    constexpr int WARPS_M = 8 / WARPS_N;      // 2
    constexpr int WM = BM / WARPS_M;          // 64
    constexpr int MT = WM / 16;               // 4
    constexpr int ROWB = 80;
    constexpr uint32_t OFF_BHI = BM * ROWB;
    constexpr uint32_t OFF_BLO = BM * ROWB + BN * ROWB;
    constexpr uint32_t STAGE   = (BM + 2u * BN) * ROWB;   // 30720

    extern __shared__ __align__(16) uint8_t smem[];
    const uint32_t smBase = smem_u32(smem);

    const int tid  = threadIdx.x;
    const int lane = tid & 31;
    const int wid  = tid >> 5;
    const int warpM = wid / WARPS_N;
    const int warpN = wid % WARPS_N;
    const int mBase = blockIdx.y * BM;
    const int nBase = blockIdx.x * BN;

    const __half* a   = A   + (size_t)blockIdx.z * aStrZ;
    const __half* bhi = Bhi + (size_t)blockIdx.z * bStrZ;
    const __half* blo = Blo + (size_t)blockIdx.z * bStrZ;

    float acc[MT][4][4];
#pragma unroll
    for (int mt = 0; mt < MT; mt++)
#pragma unroll
        for (int nt = 0; nt < 4; nt++)
#pragma unroll
            for (int i = 0; i < 4; i++) acc[mt][nt][i] = 0.0f;

    const int nIter = Ktot / BK;

    auto issue = [&](int it) {
        const int k0 = it * BK;
        const uint32_t sb = smBase + (uint32_t)(it % 3) * STAGE;
#pragma unroll
        for (int i = 0; i < 2; i++) {
            int idx = tid + i * 256;
            int r = idx >> 2, ce = (idx & 3) * 8;
            cpa16(sb + (uint32_t)(r * ROWB + ce * 2),
                  a + (size_t)(mBase + r) * lda + k0 + ce);
        }
#pragma unroll
        for (int i = 0; i < BN / 64; i++) {
            int idx = tid + i * 256;
            int r = idx >> 2, ce = (idx & 3) * 8;
            size_t g = (size_t)(nBase + r) * ldb + k0 + ce;
            uint32_t d = sb + OFF_BHI + (uint32_t)(r * ROWB + ce * 2);
            cpa16(d, bhi + g);
            cpa16(d + (OFF_BLO - OFF_BHI), blo + g);
        }
        cpa_commit();
    };

    const uint32_t aoff = (uint32_t)((warpM * WM + (lane & 15)) * ROWB) + ((lane & 16) ? 16u : 0u);
    const uint32_t boff = (uint32_t)((warpN * 32 + (lane & 15)) * ROWB) + ((lane & 16) ? 16u : 0u);

    int issued = 0;
    issue(0); issued = 1;
    if (nIter > 1) { issue(1); issued = 2; }
    if (nIter > 2) { issue(2); issued = 3; }

    for (int it = 0; it < nIter; ++it) {
        cpa_wait(issued - it - 1);
        __syncthreads();

        const uint32_t sb = smBase + (uint32_t)(it % 3) * STAGE;
        const uint32_t aB   = sb + aoff;
        const uint32_t bHiB = sb + OFF_BHI + boff;
        const uint32_t bLoB = sb + OFF_BLO + boff;

#pragma unroll
        for (int ks = 0; ks < 2; ks++) {
            uint32_t fa[MT][4];
            uint32_t fbh[2][4], fbl[2][4];
#pragma unroll
            for (int mt = 0; mt < MT; mt++)
                ldsm4(fa[mt], aB + mt * 16 * ROWB + ks * 32);
#pragma unroll
            for (int nt2 = 0; nt2 < 2; nt2++) {
                ldsm4(fbh[nt2], bHiB + nt2 * 16 * ROWB + ks * 32);
                ldsm4(fbl[nt2], bLoB + nt2 * 16 * ROWB + ks * 32);
            }
#pragma unroll
            for (int mt = 0; mt < MT; mt++)
#pragma unroll
                for (int nt = 0; nt < 4; nt++) {
                    const int nt2 = nt >> 1, s = nt & 1;
                    mma16816(acc[mt][nt], fa[mt], fbh[nt2][0 + s], fbh[nt2][2 + s]);
                    mma16816(acc[mt][nt], fa[mt], fbl[nt2][0 + s], fbl[nt2][2 + s]);
                }
        }
        __syncthreads();
        if (issued < nIter) { issue(issued); issued++; }
    }

    float*  c  = C    ? C    + (size_t)blockIdx.z * cStrZ : nullptr;
    __half* c1 = C16a ? C16a + (size_t)blockIdx.z * cStrZ : nullptr;
    __half* c2 = C16b ? C16b + (size_t)blockIdx.z * cStrZ : nullptr;

    const int lr  = lane >> 2;
    const int lc2 = (lane & 3) * 2;
#pragma unroll
    for (int mt = 0; mt < MT; mt++) {
#pragma unroll
        for (int nt = 0; nt < 4; nt++) {
            const int n0 = nBase + warpN * 32 + nt * 8 + lc2;
#pragma unroll
            for (int half = 0; half < 2; half++) {
                const int m = mBase + warpM * WM + mt * 16 + lr + half * 8;
                const float v0 = acc[mt][nt][half * 2 + 0] * scale;
                const float v1 = acc[mt][nt][half * 2 + 1] * scale;
                if (MODE == 0) {
                    *(float2*)&c[(size_t)m * ldc + n0] = make_float2(v0, v1);
                } else if (MODE == 1) {
                    const int bb = m >> 11, ss = m & 2047, hh = n0 >> 6, dd = n0 & 63;
                    const size_t idx = (((size_t)(bb * 16 + hh)) * 2048 + ss) * 64 + dd;
                    *(__half2*)&c1[idx] = __floats2half2_rn(v0, v1);
                } else if (MODE == 2) {
                    const int bb = m >> 11, ss = m & 2047, hh = n0 >> 6, dd = n0 & 63;
                    const size_t idx = (((size_t)(bb * 16 + hh)) * 2048 + ss) * 64 + dd;
                    __half h0, l0, h1, l1;
                    h16split(v0, h0, l0);
                    h16split(v1, h1, l1);
                    __half hh2[2] = {h0, h1}, ll2[2] = {l0, l1};
                    *(__half2*)&c1[idx] = *(__half2*)hh2;
                    *(__half2*)&c2[idx] = *(__half2*)ll2;
                } else { // MODE 3
                    const int bb = m >> 11, ss = m & 2047, hh = n0 >> 6, dd = n0 & 63;
                    c1[(((size_t)(bb * 16 + hh)) * 64 + dd)     * 2048 + ss] = __float2half_rn(v0);
                    c1[(((size_t)(bb * 16 + hh)) * 64 + dd + 1) * 2048 + ss] = __float2half_rn(v1);
                }
            }
        }
    }
}

// ---------------------------------------------------------------------------
// Flash attention: per (q-tile 128, bh).  Q single fp16, K hi/lo, V single.
// 3-stage K/V cp.async pipeline (Q folded into group 0).
// ---------------------------------------------------------------------------
__global__ __launch_bounds__(256)
void flash_kernel()
{
    constexpr int QROWB = 144;
    constexpr int VROWB = 272;
    constexpr uint32_t OFF_ST0 = 128u * QROWB;          // 18432 (Q region size)
    constexpr uint32_t KLO_OFF = 128u * QROWB;
    constexpr uint32_t V_OFF   = 2u * 128u * QROWB;
    constexpr uint32_t STAGE   = V_OFF + 64u * VROWB;   // 54272

    extern __shared__ __align__(16) uint8_t smem[];
    const uint32_t sm = smem_u32(smem);

    const int tid = threadIdx.x, lane = tid & 31, warp = tid >> 5;
    const int qt = blockIdx.x, bh = blockIdx.y;
    const int qBase = qt * 128;
    const int b = bh >> 4, h = bh & 15;
    const int lr = lane >> 2;
    const int lc2 = (lane & 3) * 2;
    const int row0 = qBase + warp * 16 + lr;
    const int row1 = row0 + 8;

    const __half* q16 = g_q16 + (size_t)bh * cS * cDK;
    const __half* khi = g_khi + (size_t)bh * cS * cDK;
    const __half* klo = g_klo + (size_t)bh * cS * cDK;
    const __half* v16 = g_v16 + (size_t)bh * cDK * cS;

    auto issueKV = [&](int kt) {
        const uint32_t sb = sm + OFF_ST0 + (uint32_t)(kt % 3) * STAGE;
        const int kB = kt * 128;
#pragma unroll
        for (int i = 0; i < 4; i++) {
            int idx = tid + i * 256;
            int r = idx >> 3, ch = idx & 7;
            size_t g = (size_t)(kB + r) * 64 + ch * 8;
            uint32_t d = sb + (uint32_t)(r * QROWB + ch * 16);
            cpa16(d, khi + g);
            cpa16(d + KLO_OFF, klo + g);
        }
#pragma unroll
        for (int i = 0; i < 4; i++) {
            int idx = tid + i * 256;
            int dd = idx >> 4, ch = idx & 15;
            cpa16(sb + V_OFF + (uint32_t)(dd * VROWB + ch * 16),
                  v16 + (size_t)dd * cS + kB + ch * 8);
        }
        cpa_commit();
    };

    // group 0: Q + KV(0)
    {
#pragma unroll
        for (int i = 0; i < 4; i++) {
            int idx = tid + i * 256;
            int r = idx >> 3, ch = idx & 7;
            cpa16(sm + (uint32_t)(r * QROWB + ch * 16),
                  q16 + (size_t)(qBase + r) * 64 + ch * 8);
        }
        // KV(0) into stage 0 (same commit group)
        const uint32_t sb = sm + OFF_ST0;
#pragma unroll
        for (int i = 0; i < 4; i++) {
            int idx = tid + i * 256;
            int r = idx >> 3, ch = idx & 7;
            size_t g = (size_t)r * 64 + ch * 8;
            uint32_t d = sb + (uint32_t)(r * QROWB + ch * 16);
            cpa16(d, khi + g);
            cpa16(d + KLO_OFF, klo + g);
        }
#pragma unroll
        for (int i = 0; i < 4; i++) {
            int idx = tid + i * 256;
            int dd = idx >> 4, ch = idx & 15;
            cpa16(sb + V_OFF + (uint32_t)(dd * VROWB + ch * 16),
                  v16 + (size_t)dd * cS + ch * 8);
        }
        cpa_commit();
    }
    int issued = 1;
    issueKV(1); issued = 2;
    issueKV(2); issued = 3;

    float o[8][4];
#pragma unroll
    for (int dt = 0; dt < 8; dt++)
#pragma unroll
        for (int i = 0; i < 4; i++) o[dt][i] = 0.0f;
    float m0 = -1e30f, m1 = -1e30f, l0 = 0.0f, l1 = 0.0f;

    uint32_t qf[4][4];
    const uint32_t qaddr = sm + (uint32_t)((warp * 16 + (lane & 15)) * QROWB) + ((lane & 16) ? 16u : 0u);

    for (int kt = 0; kt < 16; ++kt) {
        cpa_wait(issued - kt - 1);
        __syncthreads();

        if (kt == 0) {
#pragma unroll
            for (int ks = 0; ks < 4; ks++)
                ldsm4(qf[ks], qaddr + ks * 32);
        }

        const uint32_t sb = sm + OFF_ST0 + (uint32_t)(kt % 3) * STAGE;
        const uint32_t kbo = sb + (uint32_t)((lane & 15) * QROWB) + ((lane & 16) ? 16u : 0u);
        const uint32_t vbo = sb + V_OFF + (uint32_t)((lane & 15) * VROWB) + ((lane & 16) ? 16u : 0u);

        // ---- S = Q (Khi + Klo)^T ----
        float s[16][4];
#pragma unroll
        for (int nt = 0; nt < 16; nt++)
#pragma unroll
            for (int i = 0; i < 4; i++) s[nt][i] = 0.0f;

#pragma unroll
        for (int g = 0; g < 8; g++) {
#pragma unroll
            for (int ks = 0; ks < 4; ks++) {
                uint32_t kh[4], kl[4];
                const uint32_t ka = kbo + (uint32_t)(g * 16 * QROWB) + ks * 32;
                ldsm4(kh, ka);
                ldsm4(kl, ka + KLO_OFF);
#pragma unroll
                for (int st2 = 0; st2 < 2; st2++) {
                    mma16816(s[2 * g + st2], qf[ks], kh[0 + st2], kh[2 + st2]);
                    mma16816(s[2 * g + st2], qf[ks], kl[0 + st2], kl[2 + st2]);
                }
            }
        }

        // ---- online softmax ----
        float rm0 = -1e30f, rm1 = -1e30f;
#pragma unroll
        for (int nt = 0; nt < 16; nt++) {
            rm0 = fmaxf(rm0, fmaxf(s[nt][0], s[nt][1]));
            rm1 = fmaxf(rm1, fmaxf(s[nt][2], s[nt][3]));
        }
        rm0 = fmaxf(rm0, __shfl_xor_sync(0xffffffffu, rm0, 1));
        rm0 = fmaxf(rm0, __shfl_xor_sync(0xffffffffu, rm0, 2));
        rm1 = fmaxf(rm1, __shfl_xor_sync(0xffffffffu, rm1, 1));
        rm1 = fmaxf(rm1, __shfl_xor_sync(0xffffffffu, rm1, 2));

        const float mn0 = fmaxf(m0, rm0), mn1 = fmaxf(m1, rm1);
        const float sc0 = __expf(m0 - mn0), sc1 = __expf(m1 - mn1);
        m0 = mn0; m1 = mn1;

        float rs0 = 0.0f, rs1 = 0.0f;
#pragma unroll
        for (int nt = 0; nt < 16; nt++) {
            s[nt][0] = __expf(s[nt][0] - m0);
            s[nt][1] = __expf(s[nt][1] - m0);
            s[nt][2] = __expf(s[nt][2] - m1);
            s[nt][3] = __expf(s[nt][3] - m1);
            rs0 += s[nt][0] + s[nt][1];
            rs1 += s[nt][2] + s[nt][3];
        }
        rs0 += __shfl_xor_sync(0xffffffffu, rs0, 1);
        rs0 += __shfl_xor_sync(0xffffffffu, rs0, 2);
        rs1 += __shfl_xor_sync(0xffffffffu, rs1, 1);
        rs1 += __shfl_xor_sync(0xffffffffu, rs1, 2);
        l0 = l0 * sc0 + rs0;
        l1 = l1 * sc1 + rs1;

        // ---- store running max + unnormalized P (fp16) for sim ----
        if ((lane & 3) == 0) {
            g_mrun[((size_t)bh * 16 + kt) * cS + row0] = m0;
            g_mrun[((size_t)bh * 16 + kt) * cS + row1] = m1;
        }
        {
            const int kB = kt * 128;
#pragma unroll
            for (int nt = 0; nt < 16; nt++) {
                const int col = kB + nt * 8 + lc2;
                *(__half2*)&g_ph[((size_t)bh * cS + row0) * cS + col] =
                    __floats2half2_rn(s[nt][0], s[nt][1]);
                *(__half2*)&g_ph[((size_t)bh * cS + row1) * cS + col] =
                    __floats2half2_rn(s[nt][2], s[nt][3]);
            }
        }

#pragma unroll
        for (int dt = 0; dt < 8; dt++) {
            o[dt][0] *= sc0; o[dt][1] *= sc0;
            o[dt][2] *= sc1; o[dt][3] *= sc1;
        }

        // ---- O += (Phi + Plo) V ----
#pragma unroll
        for (int ks2 = 0; ks2 < 8; ks2++) {
            uint32_t pah[4], pal[4];
            pah[0] = pack_hilo(s[2 * ks2][0],     s[2 * ks2][1],     pal[0]);
            pah[1] = pack_hilo(s[2 * ks2][2],     s[2 * ks2][3],     pal[1]);
            pah[2] = pack_hilo(s[2 * ks2 + 1][0], s[2 * ks2 + 1][1], pal[2]);
            pah[3] = pack_hilo(s[2 * ks2 + 1][2], s[2 * ks2 + 1][3], pal[3]);
#pragma unroll
            for (int g = 0; g < 4; g++) {
                uint32_t vh[4];
                ldsm4(vh, vbo + (uint32_t)(g * 16 * VROWB) + ks2 * 32);
#pragma unroll
                for (int st2 = 0; st2 < 2; st2++) {
                    mma16816(o[2 * g + st2], pah, vh[0 + st2], vh[2 + st2]);
                    mma16816(o[2 * g + st2], pal, vh[0 + st2], vh[2 + st2]);
                }
            }
        }

        __syncthreads();
        if (issued < 16) { issueKV(issued); issued++; }
    }

    // ---- epilogue ----
    const float inv0 = 1.0f / l0, inv1 = 1.0f / l1;

    if ((lane & 3) == 0) {
        g_m[(size_t)bh * cS + row0] = m0;
        g_m[(size_t)bh * cS + row1] = m1;
        g_l[(size_t)bh * cS + row0] = l0;
        g_l[(size_t)bh * cS + row1] = l1;
    }

#pragma unroll
    for (int dt = 0; dt < 8; dt++) {
        const int d0 = dt * 8 + lc2;
        const size_t i0 = (((size_t)(b * cS + row0)) * cH + h) * cDK + d0;
        const size_t i1 = (((size_t)(b * cS + row1)) * cH + h) * cDK + d0;
        *(__half2*)&g_c16[i0] = __floats2half2_rn(o[dt][0] * inv0, o[dt][1] * inv0);
        *(__half2*)&g_c16[i1] = __floats2half2_rn(o[dt][2] * inv1, o[dt][3] * inv1);
    }
}

// ---------------------------------------------------------------------------
// Sim: sim[b,q,:] = sum_h g_ph[bh,q,:] * exp(m_run - m_final)/(16 l)
// ---------------------------------------------------------------------------
__global__ __launch_bounds__(256)
void simfast_kernel(float* __restrict__ sim)
{
    const int q = blockIdx.x;
    const int b = blockIdx.y;
    const int tid = threadIdx.x;
    const int kt  = tid >> 4;

    float acc[8] = {};

#pragma unroll 1
    for (int h = 0; h < cH; h++) {
        const int bh = b * cH + h;
        const float mf = __ldg(&g_m[(size_t)bh * cS + q]);
        const float mr = __ldg(&g_mrun[((size_t)bh * 16 + kt) * cS + q]);
        const float f  = __expf(mr - mf) / __ldg(&g_l[(size_t)bh * cS + q]) * 0.0625f;

        const uint4 raw = *(const uint4*)&g_ph[((size_t)bh * cS + q) * cS + tid * 8];
        const __half2* hp = (const __half2*)&raw;
#pragma unroll
        for (int i = 0; i < 4; i++) {
            float2 v = __half22float2(hp[i]);
            acc[2 * i + 0] += f * v.x;
            acc[2 * i + 1] += f * v.y;
        }
    }

    float* s = sim + ((size_t)b * cS + q) * cS + tid * 8;
    *(float4*)&s[0] = make_float4(acc[0], acc[1], acc[2], acc[3]);
    *(float4*)&s[4] = make_float4(acc[4], acc[5], acc[6], acc[7]);
}

// ---------------------------------------------------------------------------
// Launch
// ---------------------------------------------------------------------------
extern "C" void kernel_launch(void* const* d_in, const int* in_sizes, int n_in,
                              void* d_out, int out_size)
{
    const float* q_in  = (const float*)d_in[0];
    const float* k_in  = (const float*)d_in[1];
    const float* v_in  = (const float*)d_in[2];
    const float* w_in  = (const float*)d_in[3];
    const float* w_out = (const float*)d_in[4];

    float* out = (float*)d_out;
    float* sim = out + (size_t)cB * cS * cD;

    void *px, *pwh, *pwl, *pq, *pkh, *pkl, *pv, *pc;
    cudaGetSymbolAddress(&px,  g_x16);
    cudaGetSymbolAddress(&pwh, g_whi); cudaGetSymbolAddress(&pwl, g_wlo);
    cudaGetSymbolAddress(&pq,  g_q16);
    cudaGetSymbolAddress(&pkh, g_khi); cudaGetSymbolAddress(&pkl, g_klo);
    cudaGetSymbolAddress(&pv,  g_v16);
    cudaGetSymbolAddress(&pc,  g_c16);

    __half *x16 = (__half*)px;
    __half *wh = (__half*)pwh, *wl = (__half*)pwl;

    const int SMG = (128 + 2 * 128) * 80 * 3;    // 92160, 3 stages
    const int SMF = 18432 + 3 * 54272;           // 181248 flash, 3 stages
    cudaFuncSetAttribute((const void*)gemm_fp16x2<128, 0>, cudaFuncAttributeMaxDynamicSharedMemorySize, SMG);
    cudaFuncSetAttribute((const void*)gemm_fp16x2<128, 1>, cudaFuncAttributeMaxDynamicSharedMemorySize, SMG);
    cudaFuncSetAttribute((const void*)gemm_fp16x2<128, 2>, cudaFuncAttributeMaxDynamicSharedMemorySize, SMG);
    cudaFuncSetAttribute((const void*)gemm_fp16x2<128, 3>, cudaFuncAttributeMaxDynamicSharedMemorySize, SMG);
    cudaFuncSetAttribute((const void*)flash_kernel, cudaFuncAttributeMaxDynamicSharedMemorySize, SMF);

    // 0. Converts
    const size_t nX1 = (size_t)cB * cS * cD;
    tofp16_kernel<<<(int)(nX1 / 4 / 256), 256>>>(q_in, x16,           (int)(nX1 / 4));
    tofp16_kernel<<<(int)(nX1 / 4 / 256), 256>>>(k_in, x16 + nX1,     (int)(nX1 / 4));
    tofp16_kernel<<<(int)(nX1 / 4 / 256), 256>>>(v_in, x16 + 2 * nX1, (int)(nX1 / 4));
    const size_t nW3 = (size_t)3 * cD * cD;
    split16_kernel<<<(int)(nW3 / 4 / 256), 256>>>(w_in,  wh,        wl,        (int)(nW3 / 4));
    split16_kernel<<<(int)(cD * cD / 4 / 256), 256>>>(w_out, wh + nW3, wl + nW3, (int)(cD * cD / 4));

    // 1. Projections
    dim3 gProj(cD / 128, (cB * cS) / 128, 1);
    gemm_fp16x2<128, 1><<<gProj, 256, SMG>>>(
        x16, 0, cD, wh, wl, 0, cD,
        nullptr, (__half*)pq, nullptr, 0, cD, cD, 0.125f);
    gemm_fp16x2<128, 2><<<gProj, 256, SMG>>>(
        x16 + nX1, 0, cD, wh + (size_t)cD * cD, wl + (size_t)cD * cD, 0, cD,
        nullptr, (__half*)pkh, (__half*)pkl, 0, cD, cD, 1.0f);
    gemm_fp16x2<128, 3><<<gProj, 256, SMG>>>(
        x16 + 2 * nX1, 0, cD, wh + (size_t)2 * cD * cD, wl + (size_t)2 * cD * cD, 0, cD,
        nullptr, (__half*)pv, nullptr, 0, cD, cD, 1.0f);

    // 2. Flash attention
    flash_kernel<<<dim3(cS / 128, cBH), 256, SMF>>>();

    // 3. Sim
    simfast_kernel<<<dim3(cS, cB), 256>>>(sim);

    // 4. Output projection
    dim3 gOut(cD / 128, (cB * cS) / 128, 1);
    gemm_fp16x2<128, 0><<<gOut, 256, SMG>>>(
        (const __half*)pc, 0, cD, wh + nW3, wl + nW3, 0, cD,
        out, nullptr, nullptr, 0, cD, cD, 1.0f);
}

// round 15
// speedup vs baseline: 1.7756x; 1.1346x over previous
#include <cuda_runtime.h>
#include <cuda_bf16.h>
#include <cuda_fp16.h>
#include <stdint.h>
#include <math.h>

// Problem constants
constexpr int cB  = 4;
constexpr int cS  = 2048;
constexpr int cD  = 1024;
constexpr int cH  = 16;
constexpr int cDK = 64;
constexpr int cBH = cB * cH;   // 64

constexpr size_t N_X   = (size_t)3 * cB * cS * cD;
constexpr size_t N_W   = (size_t)4 * cD * cD;
constexpr size_t N_QK  = (size_t)cBH * cS * cDK;
constexpr size_t N_CTX = (size_t)cB * cS * cD;
constexpr size_t N_P   = (size_t)cBH * cS * cS;
constexpr size_t N_X1  = (size_t)cB * cS * cD;

// fp16 operand storage
__device__ __half g_x16[N_X];                      // inputs, single fp16
__device__ __half g_whi[N_W], g_wlo[N_W];          // weights, fp16 hi/lo
__device__ __half g_q16[N_QK];                     // Q single (pre-scaled), (B,H,S,DK)
__device__ __half g_khi[N_QK], g_klo[N_QK];        // K hi/lo, (B,H,S,DK)
__device__ __half g_v16[N_QK];                     // V single, (B,H,DK,S) transposed
__device__ __half g_c16[N_CTX];                    // ctx single, (B,S,H*DK)
__device__ float g_m[(size_t)cBH * cS];
__device__ float g_l[(size_t)cBH * cS];
__device__ float g_mrun[(size_t)cBH * 16 * cS];
__device__ __half g_ph[N_P];                       // exp(s - m_run) fp16

// ---------------------------------------------------------------------------
// helpers
// ---------------------------------------------------------------------------
__device__ __forceinline__ uint32_t smem_u32(const void* p) {
    uint32_t a;
    asm("{ .reg .u64 t; cvta.to.shared.u64 t, %1; cvt.u32.u64 %0, t; }" : "=r"(a) : "l"(p));
    return a;
}
__device__ __forceinline__ void cpa16(uint32_t dst, const void* src) {
    asm volatile("cp.async.cg.shared.global [%0], [%1], 16;" :: "r"(dst), "l"(src));
}
__device__ __forceinline__ void cpa_commit() {
    asm volatile("cp.async.commit_group;" ::: "memory");
}
__device__ __forceinline__ void cpa_wait(int rem) {
    if (rem >= 2)      asm volatile("cp.async.wait_group 2;" ::: "memory");
    else if (rem == 1) asm volatile("cp.async.wait_group 1;" ::: "memory");
    else               asm volatile("cp.async.wait_group 0;" ::: "memory");
}
__device__ __forceinline__ void ldsm4(uint32_t (&r)[4], uint32_t addr) {
    asm volatile("ldmatrix.sync.aligned.m8n8.x4.shared.b16 {%0,%1,%2,%3}, [%4];"
        : "=r"(r[0]), "=r"(r[1]), "=r"(r[2]), "=r"(r[3]) : "r"(addr));
}
__device__ __forceinline__ void mma16816(float (&d)[4], const uint32_t (&a)[4],
                                         uint32_t b0, uint32_t b1) {
    asm volatile("mma.sync.aligned.m16n8k16.row.col.f32.f16.f16.f32 "
        "{%0,%1,%2,%3},{%4,%5,%6,%7},{%8,%9},{%0,%1,%2,%3};"
        : "+f"(d[0]), "+f"(d[1]), "+f"(d[2]), "+f"(d[3])
        : "r"(a[0]), "r"(a[1]), "r"(a[2]), "r"(a[3]), "r"(b0), "r"(b1));
}
__device__ __forceinline__ void h16split(float x, __half& h, __half& l) {
    h = __float2half_rn(x);
    l = __float2half_rn(x - __half2float(h));
}
__device__ __forceinline__ uint32_t pack2(float a, float b) {
    __half2 h = __floats2half2_rn(a, b);
    return *(uint32_t*)&h;
}

// ---------------------------------------------------------------------------
// fp32 -> single fp16 / hi+lo fp16 planes
// ---------------------------------------------------------------------------
__global__ __launch_bounds__(256)
void tofp16_kernel(const float* __restrict__ src, __half* __restrict__ dst, int n4)
{
    int i = blockIdx.x * 256 + threadIdx.x;
    if (i >= n4) return;
    float4 x = ((const float4*)src)[i];
    __half2 a = __floats2half2_rn(x.x, x.y);
    __half2 b = __floats2half2_rn(x.z, x.w);
    ((uint2*)dst)[i] = make_uint2(*(uint32_t*)&a, *(uint32_t*)&b);
}

__global__ __launch_bounds__(256)
void split16_kernel(const float* __restrict__ src,
                    __half* __restrict__ hi, __half* __restrict__ lo, int n4)
{
    int i = blockIdx.x * 256 + threadIdx.x;
    if (i >= n4) return;
    float4 x = ((const float4*)src)[i];
    __half h[4], l[4];
    h16split(x.x, h[0], l[0]); h16split(x.y, h[1], l[1]);
    h16split(x.z, h[2], l[2]); h16split(x.w, h[3], l[3]);
    ((uint2*)hi)[i] = *(uint2*)h;
    ((uint2*)lo)[i] = *(uint2*)l;
}

// ===========================================================================
// Shared GEMM mainloop body (macro-free: inline template over epilogue)
// BM=128, BN=128, BK=32, 256 threads, 2-stage cp.async, 2 CTAs/SM.
// Computes acc[4][4][4] = A16 * (Bhi + Blo)^T tile.
// ===========================================================================
struct GemmCore {
    template<typename EpiFn>
    static __device__ __forceinline__ void run(
        const __half* __restrict__ a,   int lda,
        const __half* __restrict__ bhi, const __half* __restrict__ blo, int ldb,
        int mBase, int nBase, int Ktot, uint8_t* smem, EpiFn epi)
    {
        constexpr int BM = 128, BN = 128;
        constexpr int ROWB = 80;
        constexpr uint32_t OFF_BHI = BM * ROWB;
        constexpr uint32_t OFF_BLO = BM * ROWB + BN * ROWB;
        constexpr uint32_t STAGE   = (BM + 2u * BN) * ROWB;   // 30720

        const uint32_t smBase = smem_u32(smem);
        const int tid  = threadIdx.x;
        const int lane = tid & 31;
        const int wid  = tid >> 5;
        const int warpM = wid >> 2;          // 2 warps in M
        const int warpN = wid & 3;           // 4 warps in N

        float acc[4][4][4];
#pragma unroll
        for (int mt = 0; mt < 4; mt++)
#pragma unroll
            for (int nt = 0; nt < 4; nt++)
#pragma unroll
                for (int i = 0; i < 4; i++) acc[mt][nt][i] = 0.0f;

        const int nIter = Ktot >> 5;

        auto issue = [&](int it) {
            const int k0 = it << 5;
            const uint32_t sb = smBase + (uint32_t)(it & 1) * STAGE;
#pragma unroll
            for (int i = 0; i < 2; i++) {
                int idx = tid + i * 256;
                int r = idx >> 2, ce = (idx & 3) * 8;
                cpa16(sb + (uint32_t)(r * ROWB + ce * 2),
                      a + (size_t)(mBase + r) * lda + k0 + ce);
            }
#pragma unroll
            for (int i = 0; i < 2; i++) {
                int idx = tid + i * 256;
                int r = idx >> 2, ce = (idx & 3) * 8;
                size_t g = (size_t)(nBase + r) * ldb + k0 + ce;
                uint32_t d = sb + OFF_BHI + (uint32_t)(r * ROWB + ce * 2);
                cpa16(d, bhi + g);
                cpa16(d + (OFF_BLO - OFF_BHI), blo + g);
            }
            cpa_commit();
        };

        const uint32_t aoff = (uint32_t)((warpM * 64 + (lane & 15)) * ROWB) + ((lane & 16) ? 16u : 0u);
        const uint32_t boff = (uint32_t)((warpN * 32 + (lane & 15)) * ROWB) + ((lane & 16) ? 16u : 0u);

        issue(0);
        if (nIter > 1) issue(1);

        for (int it = 0; it < nIter; ++it) {
            if (it + 1 < nIter) asm volatile("cp.async.wait_group 1;" ::: "memory");
            else                asm volatile("cp.async.wait_group 0;" ::: "memory");
            __syncthreads();

            const uint32_t sb = smBase + (uint32_t)(it & 1) * STAGE;
            const uint32_t aB   = sb + aoff;
            const uint32_t bHiB = sb + OFF_BHI + boff;
            const uint32_t bLoB = sb + OFF_BLO + boff;

#pragma unroll
            for (int ks = 0; ks < 2; ks++) {
                uint32_t fa[4][4];
                uint32_t fbh[2][4], fbl[2][4];
#pragma unroll
                for (int mt = 0; mt < 4; mt++)
                    ldsm4(fa[mt], aB + mt * 16 * ROWB + ks * 32);
#pragma unroll
                for (int nt2 = 0; nt2 < 2; nt2++) {
                    ldsm4(fbh[nt2], bHiB + nt2 * 16 * ROWB + ks * 32);
                    ldsm4(fbl[nt2], bLoB + nt2 * 16 * ROWB + ks * 32);
                }
#pragma unroll
                for (int mt = 0; mt < 4; mt++)
#pragma unroll
                    for (int nt = 0; nt < 4; nt++) {
                        const int nt2 = nt >> 1, s = nt & 1;
                        mma16816(acc[mt][nt], fa[mt], fbh[nt2][0 + s], fbh[nt2][2 + s]);
                        mma16816(acc[mt][nt], fa[mt], fbl[nt2][0 + s], fbl[nt2][2 + s]);
                    }
            }
            __syncthreads();
            if (it + 2 < nIter) issue(it + 2);
        }

        // epilogue: hand each accumulator pair to the functor
        const int lr  = lane >> 2;
        const int lc2 = (lane & 3) * 2;
#pragma unroll
        for (int mt = 0; mt < 4; mt++)
#pragma unroll
            for (int nt = 0; nt < 4; nt++) {
                const int n0 = nBase + warpN * 32 + nt * 8 + lc2;
#pragma unroll
                for (int half = 0; half < 2; half++) {
                    const int m = mBase + warpM * 64 + mt * 16 + lr + half * 8;
                    epi(m, n0, acc[mt][nt][half * 2 + 0], acc[mt][nt][half * 2 + 1]);
                }
            }
    }
};

// ---------------------------------------------------------------------------
// Combined projection kernel: grid (8, 64, 3).  z=0:Q z=1:K z=2:V.
// ---------------------------------------------------------------------------
__global__ __launch_bounds__(256, 2)
void proj_kernel()
{
    extern __shared__ __align__(16) uint8_t smem[];
    const int z = blockIdx.z;
    const __half* a   = g_x16 + (size_t)z * N_X1;
    const __half* bhi = g_whi + (size_t)z * cD * cD;
    const __half* blo = g_wlo + (size_t)z * cD * cD;
    const int mBase = blockIdx.y * 128;
    const int nBase = blockIdx.x * 128;

    if (z == 0) {
        GemmCore::run(a, cD, bhi, blo, cD, mBase, nBase, cD, smem,
            [](int m, int n0, float v0, float v1) {
                const int bb = m >> 11, ss = m & 2047, hh = n0 >> 6, dd = n0 & 63;
                const size_t idx = (((size_t)(bb * 16 + hh)) * 2048 + ss) * 64 + dd;
                *(__half2*)&g_q16[idx] = __floats2half2_rn(v0 * 0.125f, v1 * 0.125f);
            });
    } else if (z == 1) {
        GemmCore::run(a, cD, bhi, blo, cD, mBase, nBase, cD, smem,
            [](int m, int n0, float v0, float v1) {
                const int bb = m >> 11, ss = m & 2047, hh = n0 >> 6, dd = n0 & 63;
                const size_t idx = (((size_t)(bb * 16 + hh)) * 2048 + ss) * 64 + dd;
                __half h0, l0, h1, l1;
                h16split(v0, h0, l0);
                h16split(v1, h1, l1);
                __half hh2[2] = {h0, h1}, ll2[2] = {l0, l1};
                *(__half2*)&g_khi[idx] = *(__half2*)hh2;
                *(__half2*)&g_klo[idx] = *(__half2*)ll2;
            });
    } else {
        GemmCore::run(a, cD, bhi, blo, cD, mBase, nBase, cD, smem,
            [](int m, int n0, float v0, float v1) {
                const int bb = m >> 11, ss = m & 2047, hh = n0 >> 6, dd = n0 & 63;
                g_v16[(((size_t)(bb * 16 + hh)) * 64 + dd)     * 2048 + ss] = __float2half_rn(v0);
                g_v16[(((size_t)(bb * 16 + hh)) * 64 + dd + 1) * 2048 + ss] = __float2half_rn(v1);
            });
    }
}

// ---------------------------------------------------------------------------
// Output projection: C fp32 = ctx16 * (Whi+Wlo)^T
// ---------------------------------------------------------------------------
__global__ __launch_bounds__(256, 2)
void outproj_kernel(float* __restrict__ out)
{
    extern __shared__ __align__(16) uint8_t smem[];
    const int mBase = blockIdx.y * 128;
    const int nBase = blockIdx.x * 128;
    const __half* bhi = g_whi + (size_t)3 * cD * cD;
    const __half* blo = g_wlo + (size_t)3 * cD * cD;

    GemmCore::run(g_c16, cD, bhi, blo, cD, mBase, nBase, cD, smem,
        [out](int m, int n0, float v0, float v1) {
            *(float2*)&out[(size_t)m * cD + n0] = make_float2(v0, v1);
        });
}

// ---------------------------------------------------------------------------
// Flash attention: per (q-tile 128, bh).  Q single fp16, K hi/lo, V single,
// PV uses single-fp16 P (same rounding as the stored g_ph).  3-stage K/V.
// ---------------------------------------------------------------------------
__global__ __launch_bounds__(256)
void flash_kernel()
{
    constexpr int QROWB = 144;
    constexpr int VROWB = 272;
    constexpr uint32_t OFF_ST0 = 128u * QROWB;          // 18432
    constexpr uint32_t KLO_OFF = 128u * QROWB;
    constexpr uint32_t V_OFF   = 2u * 128u * QROWB;
    constexpr uint32_t STAGE   = V_OFF + 64u * VROWB;   // 54272

    extern __shared__ __align__(16) uint8_t smem[];
    const uint32_t sm = smem_u32(smem);

    const int tid = threadIdx.x, lane = tid & 31, warp = tid >> 5;
    const int qt = blockIdx.x, bh = blockIdx.y;
    const int qBase = qt * 128;
    const int b = bh >> 4, h = bh & 15;
    const int lr = lane >> 2;
    const int lc2 = (lane & 3) * 2;
    const int row0 = qBase + warp * 16 + lr;
    const int row1 = row0 + 8;

    const __half* q16 = g_q16 + (size_t)bh * cS * cDK;
    const __half* khi = g_khi + (size_t)bh * cS * cDK;
    const __half* klo = g_klo + (size_t)bh * cS * cDK;
    const __half* v16 = g_v16 + (size_t)bh * cDK * cS;

    auto issueKV = [&](int kt) {
        const uint32_t sb = sm + OFF_ST0 + (uint32_t)(kt % 3) * STAGE;
        const int kB = kt * 128;
#pragma unroll
        for (int i = 0; i < 4; i++) {
            int idx = tid + i * 256;
            int r = idx >> 3, ch = idx & 7;
            size_t g = (size_t)(kB + r) * 64 + ch * 8;
            uint32_t d = sb + (uint32_t)(r * QROWB + ch * 16);
            cpa16(d, khi + g);
            cpa16(d + KLO_OFF, klo + g);
        }
#pragma unroll
        for (int i = 0; i < 4; i++) {
            int idx = tid + i * 256;
            int dd = idx >> 4, ch = idx & 15;
            cpa16(sb + V_OFF + (uint32_t)(dd * VROWB + ch * 16),
                  v16 + (size_t)dd * cS + kB + ch * 8);
        }
        cpa_commit();
    };

    // group 0: Q + KV(0)
    {
#pragma unroll
        for (int i = 0; i < 4; i++) {
            int idx = tid + i * 256;
            int r = idx >> 3, ch = idx & 7;
            cpa16(sm + (uint32_t)(r * QROWB + ch * 16),
                  q16 + (size_t)(qBase + r) * 64 + ch * 8);
        }
        const uint32_t sb = sm + OFF_ST0;
#pragma unroll
        for (int i = 0; i < 4; i++) {
            int idx = tid + i * 256;
            int r = idx >> 3, ch = idx & 7;
            size_t g = (size_t)r * 64 + ch * 8;
            uint32_t d = sb + (uint32_t)(r * QROWB + ch * 16);
            cpa16(d, khi + g);
            cpa16(d + KLO_OFF, klo + g);
        }
#pragma unroll
        for (int i = 0; i < 4; i++) {
            int idx = tid + i * 256;
            int dd = idx >> 4, ch = idx & 15;
            cpa16(sb + V_OFF + (uint32_t)(dd * VROWB + ch * 16),
                  v16 + (size_t)dd * cS + ch * 8);
        }
        cpa_commit();
    }
    int issued = 1;
    issueKV(1); issued = 2;
    issueKV(2); issued = 3;

    float o[8][4];
#pragma unroll
    for (int dt = 0; dt < 8; dt++)
#pragma unroll
        for (int i = 0; i < 4; i++) o[dt][i] = 0.0f;
    float m0 = -1e30f, m1 = -1e30f, l0 = 0.0f, l1 = 0.0f;

    uint32_t qf[4][4];
    const uint32_t qaddr = sm + (uint32_t)((warp * 16 + (lane & 15)) * QROWB) + ((lane & 16) ? 16u : 0u);

    for (int kt = 0; kt < 16; ++kt) {
        cpa_wait(issued - kt - 1);
        __syncthreads();

        if (kt == 0) {
#pragma unroll
            for (int ks = 0; ks < 4; ks++)
                ldsm4(qf[ks], qaddr + ks * 32);
        }

        const uint32_t sb = sm + OFF_ST0 + (uint32_t)(kt % 3) * STAGE;
        const uint32_t kbo = sb + (uint32_t)((lane & 15) * QROWB) + ((lane & 16) ? 16u : 0u);
        const uint32_t vbo = sb + V_OFF + (uint32_t)((lane & 15) * VROWB) + ((lane & 16) ? 16u : 0u);

        // ---- S = Q (Khi + Klo)^T ----
        float s[16][4];
#pragma unroll
        for (int nt = 0; nt < 16; nt++)
#pragma unroll
            for (int i = 0; i < 4; i++) s[nt][i] = 0.0f;

#pragma unroll
        for (int g = 0; g < 8; g++) {
#pragma unroll
            for (int ks = 0; ks < 4; ks++) {
                uint32_t kh[4], kl[4];
                const uint32_t ka = kbo + (uint32_t)(g * 16 * QROWB) + ks * 32;
                ldsm4(kh, ka);
                ldsm4(kl, ka + KLO_OFF);
#pragma unroll
                for (int st2 = 0; st2 < 2; st2++) {
                    mma16816(s[2 * g + st2], qf[ks], kh[0 + st2], kh[2 + st2]);
                    mma16816(s[2 * g + st2], qf[ks], kl[0 + st2], kl[2 + st2]);
                }
            }
        }

        // ---- online softmax ----
        float rm0 = -1e30f, rm1 = -1e30f;
#pragma unroll
        for (int nt = 0; nt < 16; nt++) {
            rm0 = fmaxf(rm0, fmaxf(s[nt][0], s[nt][1]));
            rm1 = fmaxf(rm1, fmaxf(s[nt][2], s[nt][3]));
        }
        rm0 = fmaxf(rm0, __shfl_xor_sync(0xffffffffu, rm0, 1));
        rm0 = fmaxf(rm0, __shfl_xor_sync(0xffffffffu, rm0, 2));
        rm1 = fmaxf(rm1, __shfl_xor_sync(0xffffffffu, rm1, 1));
        rm1 = fmaxf(rm1, __shfl_xor_sync(0xffffffffu, rm1, 2));

        const float mn0 = fmaxf(m0, rm0), mn1 = fmaxf(m1, rm1);
        const float sc0 = __expf(m0 - mn0), sc1 = __expf(m1 - mn1);
        m0 = mn0; m1 = mn1;

        float rs0 = 0.0f, rs1 = 0.0f;
#pragma unroll
        for (int nt = 0; nt < 16; nt++) {
            s[nt][0] = __expf(s[nt][0] - m0);
            s[nt][1] = __expf(s[nt][1] - m0);
            s[nt][2] = __expf(s[nt][2] - m1);
            s[nt][3] = __expf(s[nt][3] - m1);
            rs0 += s[nt][0] + s[nt][1];
            rs1 += s[nt][2] + s[nt][3];
        }
        rs0 += __shfl_xor_sync(0xffffffffu, rs0, 1);
        rs0 += __shfl_xor_sync(0xffffffffu, rs0, 2);
        rs1 += __shfl_xor_sync(0xffffffffu, rs1, 1);
        rs1 += __shfl_xor_sync(0xffffffffu, rs1, 2);
        l0 = l0 * sc0 + rs0;
        l1 = l1 * sc1 + rs1;

        // ---- store running max + unnormalized P (fp16) ----
        if ((lane & 3) == 0) {
            g_mrun[((size_t)bh * 16 + kt) * cS + row0] = m0;
            g_mrun[((size_t)bh * 16 + kt) * cS + row1] = m1;
        }
        {
            const int kB = kt * 128;
#pragma unroll
            for (int nt = 0; nt < 16; nt++) {
                const int col = kB + nt * 8 + lc2;
                *(__half2*)&g_ph[((size_t)bh * cS + row0) * cS + col] =
                    __floats2half2_rn(s[nt][0], s[nt][1]);
                *(__half2*)&g_ph[((size_t)bh * cS + row1) * cS + col] =
                    __floats2half2_rn(s[nt][2], s[nt][3]);
            }
        }

#pragma unroll
        for (int dt = 0; dt < 8; dt++) {
            o[dt][0] *= sc0; o[dt][1] *= sc0;
            o[dt][2] *= sc1; o[dt][3] *= sc1;
        }

        // ---- O += P16 V  (single-fp16 P, same rounding as g_ph) ----
#pragma unroll
        for (int ks2 = 0; ks2 < 8; ks2++) {
            uint32_t pa[4];
            pa[0] = pack2(s[2 * ks2][0],     s[2 * ks2][1]);
            pa[1] = pack2(s[2 * ks2][2],     s[2 * ks2][3]);
            pa[2] = pack2(s[2 * ks2 + 1][0], s[2 * ks2 + 1][1]);
            pa[3] = pack2(s[2 * ks2 + 1][2], s[2 * ks2 + 1][3]);
#pragma unroll
            for (int g = 0; g < 4; g++) {
                uint32_t vh[4];
                ldsm4(vh, vbo + (uint32_t)(g * 16 * VROWB) + ks2 * 32);
#pragma unroll
                for (int st2 = 0; st2 < 2; st2++)
                    mma16816(o[2 * g + st2], pa, vh[0 + st2], vh[2 + st2]);
            }
        }

        __syncthreads();
        if (issued < 16) { issueKV(issued); issued++; }
    }

    // ---- epilogue ----
    const float inv0 = 1.0f / l0, inv1 = 1.0f / l1;

    if ((lane & 3) == 0) {
        g_m[(size_t)bh * cS + row0] = m0;
        g_m[(size_t)bh * cS + row1] = m1;
        g_l[(size_t)bh * cS + row0] = l0;
        g_l[(size_t)bh * cS + row1] = l1;
    }

#pragma unroll
    for (int dt = 0; dt < 8; dt++) {
        const int d0 = dt * 8 + lc2;
        const size_t i0 = (((size_t)(b * cS + row0)) * cH + h) * cDK + d0;
        const size_t i1 = (((size_t)(b * cS + row1)) * cH + h) * cDK + d0;
        *(__half2*)&g_c16[i0] = __floats2half2_rn(o[dt][0] * inv0, o[dt][1] * inv0);
        *(__half2*)&g_c16[i1] = __floats2half2_rn(o[dt][2] * inv1, o[dt][3] * inv1);
    }
}

// ---------------------------------------------------------------------------
// Sim: sim[b,q,:] = sum_h g_ph[bh,q,:] * exp(m_run - m_final)/(16 l)
// ---------------------------------------------------------------------------
__global__ __launch_bounds__(256)
void simfast_kernel(float* __restrict__ sim)
{
    const int q = blockIdx.x;
    const int b = blockIdx.y;
    const int tid = threadIdx.x;
    const int kt  = tid >> 4;

    float acc[8] = {};

#pragma unroll 1
    for (int h = 0; h < cH; h++) {
        const int bh = b * cH + h;
        const float mf = __ldg(&g_m[(size_t)bh * cS + q]);
        const float mr = __ldg(&g_mrun[((size_t)bh * 16 + kt) * cS + q]);
        const float f  = __expf(mr - mf) / __ldg(&g_l[(size_t)bh * cS + q]) * 0.0625f;

        const uint4 raw = *(const uint4*)&g_ph[((size_t)bh * cS + q) * cS + tid * 8];
        const __half2* hp = (const __half2*)&raw;
#pragma unroll
        for (int i = 0; i < 4; i++) {
            float2 v = __half22float2(hp[i]);
            acc[2 * i + 0] += f * v.x;
            acc[2 * i + 1] += f * v.y;
        }
    }

    float* s = sim + ((size_t)b * cS + q) * cS + tid * 8;
    *(float4*)&s[0] = make_float4(acc[0], acc[1], acc[2], acc[3]);
    *(float4*)&s[4] = make_float4(acc[4], acc[5], acc[6], acc[7]);
}

// ---------------------------------------------------------------------------
// Launch
// ---------------------------------------------------------------------------
extern "C" void kernel_launch(void* const* d_in, const int* in_sizes, int n_in,
                              void* d_out, int out_size)
{
    const float* q_in  = (const float*)d_in[0];
    const float* k_in  = (const float*)d_in[1];
    const float* v_in  = (const float*)d_in[2];
    const float* w_in  = (const float*)d_in[3];
    const float* w_out = (const float*)d_in[4];

    float* out = (float*)d_out;
    float* sim = out + (size_t)cB * cS * cD;

    void *px, *pwh, *pwl;
    cudaGetSymbolAddress(&px,  g_x16);
    cudaGetSymbolAddress(&pwh, g_whi);
    cudaGetSymbolAddress(&pwl, g_wlo);
    __half *x16 = (__half*)px;
    __half *wh = (__half*)pwh, *wl = (__half*)pwl;

    const int SMG = (128 + 2 * 128) * 80 * 2;    // 61440, 2 stages
    const int SMF = 18432 + 3 * 54272;           // 181248 flash, 3 stages
    cudaFuncSetAttribute((const void*)proj_kernel,    cudaFuncAttributeMaxDynamicSharedMemorySize, SMG);
    cudaFuncSetAttribute((const void*)outproj_kernel, cudaFuncAttributeMaxDynamicSharedMemorySize, SMG);
    cudaFuncSetAttribute((const void*)flash_kernel,   cudaFuncAttributeMaxDynamicSharedMemorySize, SMF);

    // 0. Converts
    tofp16_kernel<<<(int)(N_X1 / 4 / 256), 256>>>(q_in, x16,            (int)(N_X1 / 4));
    tofp16_kernel<<<(int)(N_X1 / 4 / 256), 256>>>(k_in, x16 + N_X1,     (int)(N_X1 / 4));
    tofp16_kernel<<<(int)(N_X1 / 4 / 256), 256>>>(v_in, x16 + 2 * N_X1, (int)(N_X1 / 4));
    const size_t nW3 = (size_t)3 * cD * cD;
    split16_kernel<<<(int)(nW3 / 4 / 256), 256>>>(w_in,  wh,        wl,        (int)(nW3 / 4));
    split16_kernel<<<(int)(cD * cD / 4 / 256), 256>>>(w_out, wh + nW3, wl + nW3, (int)(cD * cD / 4));

    // 1. All three projections in one launch
    proj_kernel<<<dim3(cD / 128, (cB * cS) / 128, 3), 256, SMG>>>();

    // 2. Flash attention
    flash_kernel<<<dim3(cS / 128, cBH), 256, SMF>>>();

    // 3. Sim
    simfast_kernel<<<dim3(cS, cB), 256>>>(sim);

    // 4. Output projection
    outproj_kernel<<<dim3(cD / 128, (cB * cS) / 128), 256, SMG>>>(out);
}

// round 16
// speedup vs baseline: 1.8319x; 1.0317x over previous
#include <cuda_runtime.h>
#include <cuda_bf16.h>
#include <cuda_fp16.h>
#include <stdint.h>
#include <math.h>

// Problem constants
constexpr int cB  = 4;
constexpr int cS  = 2048;
constexpr int cD  = 1024;
constexpr int cH  = 16;
constexpr int cDK = 64;
constexpr int cBH = cB * cH;   // 64

constexpr size_t N_X   = (size_t)3 * cB * cS * cD;
constexpr size_t N_W   = (size_t)4 * cD * cD;
constexpr size_t N_QK  = (size_t)cBH * cS * cDK;
constexpr size_t N_CTX = (size_t)cB * cS * cD;
constexpr size_t N_P   = (size_t)cBH * cS * cS;
constexpr size_t N_X1  = (size_t)cB * cS * cD;

// fp16 operand storage
__device__ __half g_x16[N_X];                      // inputs, single fp16
__device__ __half g_whi[N_W], g_wlo[N_W];          // weights, fp16 hi/lo
__device__ __half g_q16[N_QK];                     // Q single (pre-scaled), (B,H,S,DK)
__device__ __half g_khi[N_QK], g_klo[N_QK];        // K hi/lo, (B,H,S,DK)
__device__ __half g_v16[N_QK];                     // V single, (B,H,DK,S) transposed
__device__ __half g_c16[N_CTX];                    // ctx single, (B,S,H*DK)
__device__ float g_m[(size_t)cBH * cS];
__device__ float g_l[(size_t)cBH * cS];
__device__ float g_mrun[(size_t)cBH * 16 * cS];
__device__ __half g_ph[N_P];                       // exp(s - m_run) fp16

// ---------------------------------------------------------------------------
// helpers
// ---------------------------------------------------------------------------
__device__ __forceinline__ uint32_t smem_u32(const void* p) {
    uint32_t a;
    asm("{ .reg .u64 t; cvta.to.shared.u64 t, %1; cvt.u32.u64 %0, t; }" : "=r"(a) : "l"(p));
    return a;
}
__device__ __forceinline__ void cpa16(uint32_t dst, const void* src) {
    asm volatile("cp.async.cg.shared.global [%0], [%1], 16;" :: "r"(dst), "l"(src));
}
__device__ __forceinline__ void cpa_commit() {
    asm volatile("cp.async.commit_group;" ::: "memory");
}
__device__ __forceinline__ void cpa_wait(int rem) {
    if (rem >= 2)      asm volatile("cp.async.wait_group 2;" ::: "memory");
    else if (rem == 1) asm volatile("cp.async.wait_group 1;" ::: "memory");
    else               asm volatile("cp.async.wait_group 0;" ::: "memory");
}
__device__ __forceinline__ void ldsm4(uint32_t (&r)[4], uint32_t addr) {
    asm volatile("ldmatrix.sync.aligned.m8n8.x4.shared.b16 {%0,%1,%2,%3}, [%4];"
        : "=r"(r[0]), "=r"(r[1]), "=r"(r[2]), "=r"(r[3]) : "r"(addr));
}
__device__ __forceinline__ void mma16816(float (&d)[4], const uint32_t (&a)[4],
                                         uint32_t b0, uint32_t b1) {
    asm volatile("mma.sync.aligned.m16n8k16.row.col.f32.f16.f16.f32 "
        "{%0,%1,%2,%3},{%4,%5,%6,%7},{%8,%9},{%0,%1,%2,%3};"
        : "+f"(d[0]), "+f"(d[1]), "+f"(d[2]), "+f"(d[3])
        : "r"(a[0]), "r"(a[1]), "r"(a[2]), "r"(a[3]), "r"(b0), "r"(b1));
}
__device__ __forceinline__ void h16split(float x, __half& h, __half& l) {
    h = __float2half_rn(x);
    l = __float2half_rn(x - __half2float(h));
}
__device__ __forceinline__ uint32_t pack2(float a, float b) {
    __half2 h = __floats2half2_rn(a, b);
    return *(uint32_t*)&h;
}

// ---------------------------------------------------------------------------
// fp32 -> single fp16 / hi+lo fp16 planes
// ---------------------------------------------------------------------------
__global__ __launch_bounds__(256)
void tofp16_kernel(const float* __restrict__ src, __half* __restrict__ dst, int n4)
{
    int i = blockIdx.x * 256 + threadIdx.x;
    if (i >= n4) return;
    float4 x = ((const float4*)src)[i];
    __half2 a = __floats2half2_rn(x.x, x.y);
    __half2 b = __floats2half2_rn(x.z, x.w);
    ((uint2*)dst)[i] = make_uint2(*(uint32_t*)&a, *(uint32_t*)&b);
}

__global__ __launch_bounds__(256)
void split16_kernel(const float* __restrict__ src,
                    __half* __restrict__ hi, __half* __restrict__ lo, int n4)
{
    int i = blockIdx.x * 256 + threadIdx.x;
    if (i >= n4) return;
    float4 x = ((const float4*)src)[i];
    __half h[4], l[4];
    h16split(x.x, h[0], l[0]); h16split(x.y, h[1], l[1]);
    h16split(x.z, h[2], l[2]); h16split(x.w, h[3], l[3]);
    ((uint2*)hi)[i] = *(uint2*)h;
    ((uint2*)lo)[i] = *(uint2*)l;
}

// ===========================================================================
// Shared GEMM mainloop body.  BM=128, BN=128, BK=32, 256 threads, 2-stage
// cp.async, 2 CTAs/SM.  acc = A16 * (Bhi + Blo)^T tile.
// ===========================================================================
struct GemmCore {
    template<typename EpiFn>
    static __device__ __forceinline__ void run(
        const __half* __restrict__ a,   int lda,
        const __half* __restrict__ bhi, const __half* __restrict__ blo, int ldb,
        int mBase, int nBase, int Ktot, uint8_t* smem, EpiFn epi)
    {
        constexpr int BM = 128, BN = 128;
        constexpr int ROWB = 80;
        constexpr uint32_t OFF_BHI = BM * ROWB;
        constexpr uint32_t OFF_BLO = BM * ROWB + BN * ROWB;
        constexpr uint32_t STAGE   = (BM + 2u * BN) * ROWB;   // 30720

        const uint32_t smBase = smem_u32(smem);
        const int tid  = threadIdx.x;
        const int lane = tid & 31;
        const int wid  = tid >> 5;
        const int warpM = wid >> 2;
        const int warpN = wid & 3;

        float acc[4][4][4];
#pragma unroll
        for (int mt = 0; mt < 4; mt++)
#pragma unroll
            for (int nt = 0; nt < 4; nt++)
#pragma unroll
                for (int i = 0; i < 4; i++) acc[mt][nt][i] = 0.0f;

        const int nIter = Ktot >> 5;

        auto issue = [&](int it) {
            const int k0 = it << 5;
            const uint32_t sb = smBase + (uint32_t)(it & 1) * STAGE;
#pragma unroll
            for (int i = 0; i < 2; i++) {
                int idx = tid + i * 256;
                int r = idx >> 2, ce = (idx & 3) * 8;
                cpa16(sb + (uint32_t)(r * ROWB + ce * 2),
                      a + (size_t)(mBase + r) * lda + k0 + ce);
            }
#pragma unroll
            for (int i = 0; i < 2; i++) {
                int idx = tid + i * 256;
                int r = idx >> 2, ce = (idx & 3) * 8;
                size_t g = (size_t)(nBase + r) * ldb + k0 + ce;
                uint32_t d = sb + OFF_BHI + (uint32_t)(r * ROWB + ce * 2);
                cpa16(d, bhi + g);
                cpa16(d + (OFF_BLO - OFF_BHI), blo + g);
            }
            cpa_commit();
        };

        const uint32_t aoff = (uint32_t)((warpM * 64 + (lane & 15)) * ROWB) + ((lane & 16) ? 16u : 0u);
        const uint32_t boff = (uint32_t)((warpN * 32 + (lane & 15)) * ROWB) + ((lane & 16) ? 16u : 0u);

        issue(0);
        if (nIter > 1) issue(1);

        for (int it = 0; it < nIter; ++it) {
            if (it + 1 < nIter) asm volatile("cp.async.wait_group 1;" ::: "memory");
            else                asm volatile("cp.async.wait_group 0;" ::: "memory");
            __syncthreads();

            const uint32_t sb = smBase + (uint32_t)(it & 1) * STAGE;
            const uint32_t aB   = sb + aoff;
            const uint32_t bHiB = sb + OFF_BHI + boff;
            const uint32_t bLoB = sb + OFF_BLO + boff;

#pragma unroll
            for (int ks = 0; ks < 2; ks++) {
                uint32_t fa[4][4];
                uint32_t fbh[2][4], fbl[2][4];
#pragma unroll
                for (int mt = 0; mt < 4; mt++)
                    ldsm4(fa[mt], aB + mt * 16 * ROWB + ks * 32);
#pragma unroll
                for (int nt2 = 0; nt2 < 2; nt2++) {
                    ldsm4(fbh[nt2], bHiB + nt2 * 16 * ROWB + ks * 32);
                    ldsm4(fbl[nt2], bLoB + nt2 * 16 * ROWB + ks * 32);
                }
#pragma unroll
                for (int mt = 0; mt < 4; mt++)
#pragma unroll
                    for (int nt = 0; nt < 4; nt++) {
                        const int nt2 = nt >> 1, s = nt & 1;
                        mma16816(acc[mt][nt], fa[mt], fbh[nt2][0 + s], fbh[nt2][2 + s]);
                        mma16816(acc[mt][nt], fa[mt], fbl[nt2][0 + s], fbl[nt2][2 + s]);
                    }
            }
            __syncthreads();
            if (it + 2 < nIter) issue(it + 2);
        }

        const int lr  = lane >> 2;
        const int lc2 = (lane & 3) * 2;
#pragma unroll
        for (int mt = 0; mt < 4; mt++)
#pragma unroll
            for (int nt = 0; nt < 4; nt++) {
                const int n0 = nBase + warpN * 32 + nt * 8 + lc2;
#pragma unroll
                for (int half = 0; half < 2; half++) {
                    const int m = mBase + warpM * 64 + mt * 16 + lr + half * 8;
                    epi(m, n0, acc[mt][nt][half * 2 + 0], acc[mt][nt][half * 2 + 1]);
                }
            }
    }
};

// ---------------------------------------------------------------------------
// Combined projection kernel: grid (8, 64, 3).  z=0:Q z=1:K z=2:V.
// ---------------------------------------------------------------------------
__global__ __launch_bounds__(256, 2)
void proj_kernel()
{
    extern __shared__ __align__(16) uint8_t smem[];
    const int z = blockIdx.z;
    const __half* a   = g_x16 + (size_t)z * N_X1;
    const __half* bhi = g_whi + (size_t)z * cD * cD;
    const __half* blo = g_wlo + (size_t)z * cD * cD;
    const int mBase = blockIdx.y * 128;
    const int nBase = blockIdx.x * 128;

    if (z == 0) {
        GemmCore::run(a, cD, bhi, blo, cD, mBase, nBase, cD, smem,
            [](int m, int n0, float v0, float v1) {
                const int bb = m >> 11, ss = m & 2047, hh = n0 >> 6, dd = n0 & 63;
                const size_t idx = (((size_t)(bb * 16 + hh)) * 2048 + ss) * 64 + dd;
                *(__half2*)&g_q16[idx] = __floats2half2_rn(v0 * 0.125f, v1 * 0.125f);
            });
    } else if (z == 1) {
        GemmCore::run(a, cD, bhi, blo, cD, mBase, nBase, cD, smem,
            [](int m, int n0, float v0, float v1) {
                const int bb = m >> 11, ss = m & 2047, hh = n0 >> 6, dd = n0 & 63;
                const size_t idx = (((size_t)(bb * 16 + hh)) * 2048 + ss) * 64 + dd;
                __half h0, l0, h1, l1;
                h16split(v0, h0, l0);
                h16split(v1, h1, l1);
                __half hh2[2] = {h0, h1}, ll2[2] = {l0, l1};
                *(__half2*)&g_khi[idx] = *(__half2*)hh2;
                *(__half2*)&g_klo[idx] = *(__half2*)ll2;
            });
    } else {
        GemmCore::run(a, cD, bhi, blo, cD, mBase, nBase, cD, smem,
            [](int m, int n0, float v0, float v1) {
                const int bb = m >> 11, ss = m & 2047, hh = n0 >> 6, dd = n0 & 63;
                g_v16[(((size_t)(bb * 16 + hh)) * 64 + dd)     * 2048 + ss] = __float2half_rn(v0);
                g_v16[(((size_t)(bb * 16 + hh)) * 64 + dd + 1) * 2048 + ss] = __float2half_rn(v1);
            });
    }
}

// ---------------------------------------------------------------------------
// Output projection: C fp32 = ctx16 * (Whi+Wlo)^T
// ---------------------------------------------------------------------------
__global__ __launch_bounds__(256, 2)
void outproj_kernel(float* __restrict__ out)
{
    extern __shared__ __align__(16) uint8_t smem[];
    const int mBase = blockIdx.y * 128;
    const int nBase = blockIdx.x * 128;
    const __half* bhi = g_whi + (size_t)3 * cD * cD;
    const __half* blo = g_wlo + (size_t)3 * cD * cD;

    GemmCore::run(g_c16, cD, bhi, blo, cD, mBase, nBase, cD, smem,
        [out](int m, int n0, float v0, float v1) {
            *(float2*)&out[(size_t)m * cD + n0] = make_float2(v0, v1);
        });
}

// ---------------------------------------------------------------------------
// Flash attention: per (q-tile 128, bh).  Q single fp16, K hi/lo, V single,
// PV uses single-fp16 P.  3-stage K/V cp.async.
// ---------------------------------------------------------------------------
__global__ __launch_bounds__(256)
void flash_kernel()
{
    constexpr int QROWB = 144;
    constexpr int VROWB = 272;
    constexpr uint32_t OFF_ST0 = 128u * QROWB;          // 18432
    constexpr uint32_t KLO_OFF = 128u * QROWB;
    constexpr uint32_t V_OFF   = 2u * 128u * QROWB;
    constexpr uint32_t STAGE   = V_OFF + 64u * VROWB;   // 54272

    extern __shared__ __align__(16) uint8_t smem[];
    const uint32_t sm = smem_u32(smem);

    const int tid = threadIdx.x, lane = tid & 31, warp = tid >> 5;
    const int qt = blockIdx.x, bh = blockIdx.y;
    const int qBase = qt * 128;
    const int b = bh >> 4, h = bh & 15;
    const int lr = lane >> 2;
    const int lc2 = (lane & 3) * 2;
    const int row0 = qBase + warp * 16 + lr;
    const int row1 = row0 + 8;

    const __half* q16 = g_q16 + (size_t)bh * cS * cDK;
    const __half* khi = g_khi + (size_t)bh * cS * cDK;
    const __half* klo = g_klo + (size_t)bh * cS * cDK;
    const __half* v16 = g_v16 + (size_t)bh * cDK * cS;

    auto issueKV = [&](int kt) {
        const uint32_t sb = sm + OFF_ST0 + (uint32_t)(kt % 3) * STAGE;
        const int kB = kt * 128;
#pragma unroll
        for (int i = 0; i < 4; i++) {
            int idx = tid + i * 256;
            int r = idx >> 3, ch = idx & 7;
            size_t g = (size_t)(kB + r) * 64 + ch * 8;
            uint32_t d = sb + (uint32_t)(r * QROWB + ch * 16);
            cpa16(d, khi + g);
            cpa16(d + KLO_OFF, klo + g);
        }
#pragma unroll
        for (int i = 0; i < 4; i++) {
            int idx = tid + i * 256;
            int dd = idx >> 4, ch = idx & 15;
            cpa16(sb + V_OFF + (uint32_t)(dd * VROWB + ch * 16),
                  v16 + (size_t)dd * cS + kB + ch * 8);
        }
        cpa_commit();
    };

    // group 0: Q + KV(0)
    {
#pragma unroll
        for (int i = 0; i < 4; i++) {
            int idx = tid + i * 256;
            int r = idx >> 3, ch = idx & 7;
            cpa16(sm + (uint32_t)(r * QROWB + ch * 16),
                  q16 + (size_t)(qBase + r) * 64 + ch * 8);
        }
        const uint32_t sb = sm + OFF_ST0;
#pragma unroll
        for (int i = 0; i < 4; i++) {
            int idx = tid + i * 256;
            int r = idx >> 3, ch = idx & 7;
            size_t g = (size_t)r * 64 + ch * 8;
            uint32_t d = sb + (uint32_t)(r * QROWB + ch * 16);
            cpa16(d, khi + g);
            cpa16(d + KLO_OFF, klo + g);
        }
#pragma unroll
        for (int i = 0; i < 4; i++) {
            int idx = tid + i * 256;
            int dd = idx >> 4, ch = idx & 15;
            cpa16(sb + V_OFF + (uint32_t)(dd * VROWB + ch * 16),
                  v16 + (size_t)dd * cS + ch * 8);
        }
        cpa_commit();
    }
    int issued = 1;
    issueKV(1); issued = 2;
    issueKV(2); issued = 3;

    float o[8][4];
#pragma unroll
    for (int dt = 0; dt < 8; dt++)
#pragma unroll
        for (int i = 0; i < 4; i++) o[dt][i] = 0.0f;
    float m0 = -1e30f, m1 = -1e30f, l0 = 0.0f, l1 = 0.0f;

    uint32_t qf[4][4];
    const uint32_t qaddr = sm + (uint32_t)((warp * 16 + (lane & 15)) * QROWB) + ((lane & 16) ? 16u : 0u);

    for (int kt = 0; kt < 16; ++kt) {
        cpa_wait(issued - kt - 1);
        __syncthreads();

        if (kt == 0) {
#pragma unroll
            for (int ks = 0; ks < 4; ks++)
                ldsm4(qf[ks], qaddr + ks * 32);
        }

        const uint32_t sb = sm + OFF_ST0 + (uint32_t)(kt % 3) * STAGE;
        const uint32_t kbo = sb + (uint32_t)((lane & 15) * QROWB) + ((lane & 16) ? 16u : 0u);
        const uint32_t vbo = sb + V_OFF + (uint32_t)((lane & 15) * VROWB) + ((lane & 16) ? 16u : 0u);

        // ---- S = Q (Khi + Klo)^T ----
        float s[16][4];
#pragma unroll
        for (int nt = 0; nt < 16; nt++)
#pragma unroll
            for (int i = 0; i < 4; i++) s[nt][i] = 0.0f;

#pragma unroll
        for (int g = 0; g < 8; g++) {
#pragma unroll
            for (int ks = 0; ks < 4; ks++) {
                uint32_t kh[4], kl[4];
                const uint32_t ka = kbo + (uint32_t)(g * 16 * QROWB) + ks * 32;
                ldsm4(kh, ka);
                ldsm4(kl, ka + KLO_OFF);
#pragma unroll
                for (int st2 = 0; st2 < 2; st2++) {
                    mma16816(s[2 * g + st2], qf[ks], kh[0 + st2], kh[2 + st2]);
                    mma16816(s[2 * g + st2], qf[ks], kl[0 + st2], kl[2 + st2]);
                }
            }
        }

        // ---- online softmax ----
        float rm0 = -1e30f, rm1 = -1e30f;
#pragma unroll
        for (int nt = 0; nt < 16; nt++) {
            rm0 = fmaxf(rm0, fmaxf(s[nt][0], s[nt][1]));
            rm1 = fmaxf(rm1, fmaxf(s[nt][2], s[nt][3]));
        }
        rm0 = fmaxf(rm0, __shfl_xor_sync(0xffffffffu, rm0, 1));
        rm0 = fmaxf(rm0, __shfl_xor_sync(0xffffffffu, rm0, 2));
        rm1 = fmaxf(rm1, __shfl_xor_sync(0xffffffffu, rm1, 1));
        rm1 = fmaxf(rm1, __shfl_xor_sync(0xffffffffu, rm1, 2));

        const float mn0 = fmaxf(m0, rm0), mn1 = fmaxf(m1, rm1);
        const float sc0 = __expf(m0 - mn0), sc1 = __expf(m1 - mn1);
        m0 = mn0; m1 = mn1;

        float rs0 = 0.0f, rs1 = 0.0f;
#pragma unroll
        for (int nt = 0; nt < 16; nt++) {
            s[nt][0] = __expf(s[nt][0] - m0);
            s[nt][1] = __expf(s[nt][1] - m0);
            s[nt][2] = __expf(s[nt][2] - m1);
            s[nt][3] = __expf(s[nt][3] - m1);
            rs0 += s[nt][0] + s[nt][1];
            rs1 += s[nt][2] + s[nt][3];
        }
        rs0 += __shfl_xor_sync(0xffffffffu, rs0, 1);
        rs0 += __shfl_xor_sync(0xffffffffu, rs0, 2);
        rs1 += __shfl_xor_sync(0xffffffffu, rs1, 1);
        rs1 += __shfl_xor_sync(0xffffffffu, rs1, 2);
        l0 = l0 * sc0 + rs0;
        l1 = l1 * sc1 + rs1;

        // ---- store running max + unnormalized P (fp16) ----
        if ((lane & 3) == 0) {
            g_mrun[((size_t)bh * 16 + kt) * cS + row0] = m0;
            g_mrun[((size_t)bh * 16 + kt) * cS + row1] = m1;
        }
        {
            const int kB = kt * 128;
#pragma unroll
            for (int nt = 0; nt < 16; nt++) {
                const int col = kB + nt * 8 + lc2;
                *(__half2*)&g_ph[((size_t)bh * cS + row0) * cS + col] =
                    __floats2half2_rn(s[nt][0], s[nt][1]);
                *(__half2*)&g_ph[((size_t)bh * cS + row1) * cS + col] =
                    __floats2half2_rn(s[nt][2], s[nt][3]);
            }
        }

#pragma unroll
        for (int dt = 0; dt < 8; dt++) {
            o[dt][0] *= sc0; o[dt][1] *= sc0;
            o[dt][2] *= sc1; o[dt][3] *= sc1;
        }

        // ---- O += P16 V ----
#pragma unroll
        for (int ks2 = 0; ks2 < 8; ks2++) {
            uint32_t pa[4];
            pa[0] = pack2(s[2 * ks2][0],     s[2 * ks2][1]);
            pa[1] = pack2(s[2 * ks2][2],     s[2 * ks2][3]);
            pa[2] = pack2(s[2 * ks2 + 1][0], s[2 * ks2 + 1][1]);
            pa[3] = pack2(s[2 * ks2 + 1][2], s[2 * ks2 + 1][3]);
#pragma unroll
            for (int g = 0; g < 4; g++) {
                uint32_t vh[4];
                ldsm4(vh, vbo + (uint32_t)(g * 16 * VROWB) + ks2 * 32);
#pragma unroll
                for (int st2 = 0; st2 < 2; st2++)
                    mma16816(o[2 * g + st2], pa, vh[0 + st2], vh[2 + st2]);
            }
        }

        __syncthreads();
        if (issued < 16) { issueKV(issued); issued++; }
    }

    // ---- epilogue ----
    const float inv0 = 1.0f / l0, inv1 = 1.0f / l1;

    if ((lane & 3) == 0) {
        g_m[(size_t)bh * cS + row0] = m0;
        g_m[(size_t)bh * cS + row1] = m1;
        g_l[(size_t)bh * cS + row0] = l0;
        g_l[(size_t)bh * cS + row1] = l1;
    }

#pragma unroll
    for (int dt = 0; dt < 8; dt++) {
        const int d0 = dt * 8 + lc2;
        const size_t i0 = (((size_t)(b * cS + row0)) * cH + h) * cDK + d0;
        const size_t i1 = (((size_t)(b * cS + row1)) * cH + h) * cDK + d0;
        *(__half2*)&g_c16[i0] = __floats2half2_rn(o[dt][0] * inv0, o[dt][1] * inv0);
        *(__half2*)&g_c16[i1] = __floats2half2_rn(o[dt][2] * inv1, o[dt][3] * inv1);
    }
}

// ---------------------------------------------------------------------------
// Sim: sim[b,q,:] = sum_h g_ph[bh,q,:] * exp(m_run - m_final)/(16 l)
// ---------------------------------------------------------------------------
__global__ __launch_bounds__(256)
void simfast_kernel(float* __restrict__ sim)
{
    const int q = blockIdx.x;
    const int b = blockIdx.y;
    const int tid = threadIdx.x;
    const int kt  = tid >> 4;

    float acc[8] = {};

#pragma unroll 1
    for (int h = 0; h < cH; h++) {
        const int bh = b * cH + h;
        const float mf = __ldg(&g_m[(size_t)bh * cS + q]);
        const float mr = __ldg(&g_mrun[((size_t)bh * 16 + kt) * cS + q]);
        const float f  = __expf(mr - mf) / __ldg(&g_l[(size_t)bh * cS + q]) * 0.0625f;

        const uint4 raw = *(const uint4*)&g_ph[((size_t)bh * cS + q) * cS + tid * 8];
        const __half2* hp = (const __half2*)&raw;
#pragma unroll
        for (int i = 0; i < 4; i++) {
            float2 v = __half22float2(hp[i]);
            acc[2 * i + 0] += f * v.x;
            acc[2 * i + 1] += f * v.y;
        }
    }

    float* s = sim + ((size_t)b * cS + q) * cS + tid * 8;
    *(float4*)&s[0] = make_float4(acc[0], acc[1], acc[2], acc[3]);
    *(float4*)&s[4] = make_float4(acc[4], acc[5], acc[6], acc[7]);
}

// ---------------------------------------------------------------------------
// Launch — fork/join streams inside graph capture:
//   stream0: tofp16 x3 ─┐                ┌─ outproj ──────────┐
//                       ├─ proj ─ flash ─┤                    ├─ (join)
//   s1:     split16 x2 ─┘                └─ simfast ──────────┘
// ---------------------------------------------------------------------------
extern "C" void kernel_launch(void* const* d_in, const int* in_sizes, int n_in,
                              void* d_out, int out_size)
{
    const float* q_in  = (const float*)d_in[0];
    const float* k_in  = (const float*)d_in[1];
    const float* v_in  = (const float*)d_in[2];
    const float* w_in  = (const float*)d_in[3];
    const float* w_out = (const float*)d_in[4];

    float* out = (float*)d_out;
    float* sim = out + (size_t)cB * cS * cD;

    void *px, *pwh, *pwl;
    cudaGetSymbolAddress(&px,  g_x16);
    cudaGetSymbolAddress(&pwh, g_whi);
    cudaGetSymbolAddress(&pwl, g_wlo);
    __half *x16 = (__half*)px;
    __half *wh = (__half*)pwh, *wl = (__half*)pwl;

    const int SMG = (128 + 2 * 128) * 80 * 2;    // 61440, 2 stages
    const int SMF = 18432 + 3 * 54272;           // 181248 flash, 3 stages
    cudaFuncSetAttribute((const void*)proj_kernel,    cudaFuncAttributeMaxDynamicSharedMemorySize, SMG);
    cudaFuncSetAttribute((const void*)outproj_kernel, cudaFuncAttributeMaxDynamicSharedMemorySize, SMG);
    cudaFuncSetAttribute((const void*)flash_kernel,   cudaFuncAttributeMaxDynamicSharedMemorySize, SMF);

    // Lazily-created side stream + events (host objects only; no device mem)
    static cudaStream_t s1 = nullptr;
    static cudaEvent_t evFork = nullptr, evW = nullptr, evFlash = nullptr, evSim = nullptr;
    if (!s1) {
        cudaStreamCreateWithFlags(&s1, cudaStreamNonBlocking);
        cudaEventCreateWithFlags(&evFork,  cudaEventDisableTiming);
        cudaEventCreateWithFlags(&evW,     cudaEventDisableTiming);
        cudaEventCreateWithFlags(&evFlash, cudaEventDisableTiming);
        cudaEventCreateWithFlags(&evSim,   cudaEventDisableTiming);
    }

    // --- fork: weight splits on s1, input converts on stream 0 ---
    cudaEventRecord(evFork, 0);
    cudaStreamWaitEvent(s1, evFork, 0);

    const size_t nW3 = (size_t)3 * cD * cD;
    split16_kernel<<<(int)(nW3 / 4 / 256), 256, 0, s1>>>(w_in, wh, wl, (int)(nW3 / 4));
    split16_kernel<<<(int)(cD * cD / 4 / 256), 256, 0, s1>>>(w_out, wh + nW3, wl + nW3,
                                                             (int)(cD * cD / 4));

    tofp16_kernel<<<(int)(N_X1 / 4 / 256), 256>>>(q_in, x16,            (int)(N_X1 / 4));
    tofp16_kernel<<<(int)(N_X1 / 4 / 256), 256>>>(k_in, x16 + N_X1,     (int)(N_X1 / 4));
    tofp16_kernel<<<(int)(N_X1 / 4 / 256), 256>>>(v_in, x16 + 2 * N_X1, (int)(N_X1 / 4));

    // join weights before proj
    cudaEventRecord(evW, s1);
    cudaStreamWaitEvent(0, evW, 0);

    // --- serial spine: proj -> flash ---
    proj_kernel<<<dim3(cD / 128, (cB * cS) / 128, 3), 256, SMG>>>();
    flash_kernel<<<dim3(cS / 128, cBH), 256, SMF>>>();

    // --- fork: simfast on s1 concurrent with outproj on stream 0 ---
    cudaEventRecord(evFlash, 0);
    cudaStreamWaitEvent(s1, evFlash, 0);

    simfast_kernel<<<dim3(cS, cB), 256, 0, s1>>>(sim);
    outproj_kernel<<<dim3(cD / 128, (cB * cS) / 128), 256, SMG>>>(out);

    // join
    cudaEventRecord(evSim, s1);
    cudaStreamWaitEvent(0, evSim, 0);
}

// round 17
// speedup vs baseline: 2.4121x; 1.3167x over previous
#include <cuda_runtime.h>
#include <cuda_bf16.h>
#include <cuda_fp16.h>
#include <stdint.h>
#include <math.h>

// Problem constants
constexpr int cB  = 4;
constexpr int cS  = 2048;
constexpr int cD  = 1024;
constexpr int cH  = 16;
constexpr int cDK = 64;
constexpr int cBH = cB * cH;   // 64

constexpr size_t N_X   = (size_t)3 * cB * cS * cD;
constexpr size_t N_QK  = (size_t)cBH * cS * cDK;
constexpr size_t N_CTX = (size_t)cB * cS * cD;
constexpr size_t N_P   = (size_t)cBH * cS * cS;
constexpr size_t N_X1  = (size_t)cB * cS * cD;

// fp16 operand storage
__device__ __half g_x16[N_X];                      // inputs, single fp16
__device__ __half g_w16[(size_t)3 * cD * cD];      // input weights, single fp16
__device__ __half g_wohi[(size_t)cD * cD];         // out weight hi
__device__ __half g_wolo[(size_t)cD * cD];         // out weight lo
__device__ __half g_q16[N_QK];                     // Q single (pre-scaled), (B,H,S,DK)
__device__ __half g_k16[N_QK];                     // K single, (B,H,S,DK)
__device__ __half g_v16[N_QK];                     // V single, (B,H,DK,S) transposed
__device__ __half g_c16[N_CTX];                    // ctx single, (B,S,H*DK)
__device__ float g_m[(size_t)cBH * cS];
__device__ float g_l[(size_t)cBH * cS];
__device__ float g_mrun[(size_t)cBH * 16 * cS];
__device__ __half g_ph[N_P];                       // exp(s - m_run) fp16

// ---------------------------------------------------------------------------
// helpers
// ---------------------------------------------------------------------------
__device__ __forceinline__ uint32_t smem_u32(const void* p) {
    uint32_t a;
    asm("{ .reg .u64 t; cvta.to.shared.u64 t, %1; cvt.u32.u64 %0, t; }" : "=r"(a) : "l"(p));
    return a;
}
__device__ __forceinline__ void cpa16(uint32_t dst, const void* src) {
    asm volatile("cp.async.cg.shared.global [%0], [%1], 16;" :: "r"(dst), "l"(src));
}
__device__ __forceinline__ void cpa_commit() {
    asm volatile("cp.async.commit_group;" ::: "memory");
}
__device__ __forceinline__ void cpa_wait(int rem) {
    if (rem >= 2)      asm volatile("cp.async.wait_group 2;" ::: "memory");
    else if (rem == 1) asm volatile("cp.async.wait_group 1;" ::: "memory");
    else               asm volatile("cp.async.wait_group 0;" ::: "memory");
}
__device__ __forceinline__ void ldsm4(uint32_t (&r)[4], uint32_t addr) {
    asm volatile("ldmatrix.sync.aligned.m8n8.x4.shared.b16 {%0,%1,%2,%3}, [%4];"
        : "=r"(r[0]), "=r"(r[1]), "=r"(r[2]), "=r"(r[3]) : "r"(addr));
}
__device__ __forceinline__ void mma16816(float (&d)[4], const uint32_t (&a)[4],
                                         uint32_t b0, uint32_t b1) {
    asm volatile("mma.sync.aligned.m16n8k16.row.col.f32.f16.f16.f32 "
        "{%0,%1,%2,%3},{%4,%5,%6,%7},{%8,%9},{%0,%1,%2,%3};"
        : "+f"(d[0]), "+f"(d[1]), "+f"(d[2]), "+f"(d[3])
        : "r"(a[0]), "r"(a[1]), "r"(a[2]), "r"(a[3]), "r"(b0), "r"(b1));
}
__device__ __forceinline__ void h16split(float x, __half& h, __half& l) {
    h = __float2half_rn(x);
    l = __float2half_rn(x - __half2float(h));
}
__device__ __forceinline__ uint32_t pack2(float a, float b) {
    __half2 h = __floats2half2_rn(a, b);
    return *(uint32_t*)&h;
}

// ---------------------------------------------------------------------------
// fp32 -> single fp16 / hi+lo fp16 planes
// ---------------------------------------------------------------------------
__global__ __launch_bounds__(256)
void tofp16_kernel(const float* __restrict__ src, __half* __restrict__ dst, int n4)
{
    int i = blockIdx.x * 256 + threadIdx.x;
    if (i >= n4) return;
    float4 x = ((const float4*)src)[i];
    __half2 a = __floats2half2_rn(x.x, x.y);
    __half2 b = __floats2half2_rn(x.z, x.w);
    ((uint2*)dst)[i] = make_uint2(*(uint32_t*)&a, *(uint32_t*)&b);
}

__global__ __launch_bounds__(256)
void split16_kernel(const float* __restrict__ src,
                    __half* __restrict__ hi, __half* __restrict__ lo, int n4)
{
    int i = blockIdx.x * 256 + threadIdx.x;
    if (i >= n4) return;
    float4 x = ((const float4*)src)[i];
    __half h[4], l[4];
    h16split(x.x, h[0], l[0]); h16split(x.y, h[1], l[1]);
    h16split(x.z, h[2], l[2]); h16split(x.w, h[3], l[3]);
    ((uint2*)hi)[i] = *(uint2*)h;
    ((uint2*)lo)[i] = *(uint2*)l;
}

// ===========================================================================
// Shared GEMM mainloop.  BM=128, BN=128, BK=32, 256 threads, 2-stage cp.async.
// DUAL=false: D = A16 * B16^T          (1 MMA per frag pair)
// DUAL=true : D = A16 * (Bhi+Blo)^T    (2 MMAs)
// ===========================================================================
template<bool DUAL>
struct GemmCore {
    template<typename EpiFn>
    static __device__ __forceinline__ void run(
        const __half* __restrict__ a,   int lda,
        const __half* __restrict__ bhi, const __half* __restrict__ blo, int ldb,
        int mBase, int nBase, int Ktot, uint8_t* smem, EpiFn epi)
    {
        constexpr int BM = 128, BN = 128;
        constexpr int ROWB = 80;
        constexpr uint32_t OFF_BHI = BM * ROWB;
        constexpr uint32_t OFF_BLO = BM * ROWB + BN * ROWB;
        constexpr uint32_t STAGE   = (DUAL ? 3u : 2u) * 128u * ROWB;

        const uint32_t smBase = smem_u32(smem);
        const int tid  = threadIdx.x;
        const int lane = tid & 31;
        const int wid  = tid >> 5;
        const int warpM = wid >> 2;
        const int warpN = wid & 3;

        float acc[4][4][4];
#pragma unroll
        for (int mt = 0; mt < 4; mt++)
#pragma unroll
            for (int nt = 0; nt < 4; nt++)
#pragma unroll
                for (int i = 0; i < 4; i++) acc[mt][nt][i] = 0.0f;

        const int nIter = Ktot >> 5;

        auto issue = [&](int it) {
            const int k0 = it << 5;
            const uint32_t sb = smBase + (uint32_t)(it & 1) * STAGE;
#pragma unroll
            for (int i = 0; i < 2; i++) {
                int idx = tid + i * 256;
                int r = idx >> 2, ce = (idx & 3) * 8;
                cpa16(sb + (uint32_t)(r * ROWB + ce * 2),
                      a + (size_t)(mBase + r) * lda + k0 + ce);
            }
#pragma unroll
            for (int i = 0; i < 2; i++) {
                int idx = tid + i * 256;
                int r = idx >> 2, ce = (idx & 3) * 8;
                size_t g = (size_t)(nBase + r) * ldb + k0 + ce;
                uint32_t d = sb + OFF_BHI + (uint32_t)(r * ROWB + ce * 2);
                cpa16(d, bhi + g);
                if (DUAL) cpa16(d + (OFF_BLO - OFF_BHI), blo + g);
            }
            cpa_commit();
        };

        const uint32_t aoff = (uint32_t)((warpM * 64 + (lane & 15)) * ROWB) + ((lane & 16) ? 16u : 0u);
        const uint32_t boff = (uint32_t)((warpN * 32 + (lane & 15)) * ROWB) + ((lane & 16) ? 16u : 0u);

        issue(0);
        if (nIter > 1) issue(1);

        for (int it = 0; it < nIter; ++it) {
            if (it + 1 < nIter) asm volatile("cp.async.wait_group 1;" ::: "memory");
            else                asm volatile("cp.async.wait_group 0;" ::: "memory");
            __syncthreads();

            const uint32_t sb = smBase + (uint32_t)(it & 1) * STAGE;
            const uint32_t aB   = sb + aoff;
            const uint32_t bHiB = sb + OFF_BHI + boff;
            const uint32_t bLoB = sb + OFF_BLO + boff;

#pragma unroll
            for (int ks = 0; ks < 2; ks++) {
                uint32_t fa[4][4];
                uint32_t fbh[2][4], fbl[2][4];
#pragma unroll
                for (int mt = 0; mt < 4; mt++)
                    ldsm4(fa[mt], aB + mt * 16 * ROWB + ks * 32);
#pragma unroll
                for (int nt2 = 0; nt2 < 2; nt2++) {
                    ldsm4(fbh[nt2], bHiB + nt2 * 16 * ROWB + ks * 32);
                    if (DUAL) ldsm4(fbl[nt2], bLoB + nt2 * 16 * ROWB + ks * 32);
                }
#pragma unroll
                for (int mt = 0; mt < 4; mt++)
#pragma unroll
                    for (int nt = 0; nt < 4; nt++) {
                        const int nt2 = nt >> 1, s = nt & 1;
                        mma16816(acc[mt][nt], fa[mt], fbh[nt2][0 + s], fbh[nt2][2 + s]);
                        if (DUAL)
                            mma16816(acc[mt][nt], fa[mt], fbl[nt2][0 + s], fbl[nt2][2 + s]);
                    }
            }
            __syncthreads();
            if (it + 2 < nIter) issue(it + 2);
        }

        const int lr  = lane >> 2;
        const int lc2 = (lane & 3) * 2;
#pragma unroll
        for (int mt = 0; mt < 4; mt++)
#pragma unroll
            for (int nt = 0; nt < 4; nt++) {
                const int n0 = nBase + warpN * 32 + nt * 8 + lc2;
#pragma unroll
                for (int half = 0; half < 2; half++) {
                    const int m = mBase + warpM * 64 + mt * 16 + lr + half * 8;
                    epi(m, n0, acc[mt][nt][half * 2 + 0], acc[mt][nt][half * 2 + 1]);
                }
            }
    }
};

// ---------------------------------------------------------------------------
// Combined projection kernel (single x single): grid (8, 64, 3).
// ---------------------------------------------------------------------------
__global__ __launch_bounds__(256, 2)
void proj_kernel()
{
    extern __shared__ __align__(16) uint8_t smem[];
    const int z = blockIdx.z;
    const __half* a = g_x16 + (size_t)z * N_X1;
    const __half* b = g_w16 + (size_t)z * cD * cD;
    const int mBase = blockIdx.y * 128;
    const int nBase = blockIdx.x * 128;

    if (z == 0) {
        GemmCore<false>::run(a, cD, b, nullptr, cD, mBase, nBase, cD, smem,
            [](int m, int n0, float v0, float v1) {
                const int bb = m >> 11, ss = m & 2047, hh = n0 >> 6, dd = n0 & 63;
                const size_t idx = (((size_t)(bb * 16 + hh)) * 2048 + ss) * 64 + dd;
                *(__half2*)&g_q16[idx] = __floats2half2_rn(v0 * 0.125f, v1 * 0.125f);
            });
    } else if (z == 1) {
        GemmCore<false>::run(a, cD, b, nullptr, cD, mBase, nBase, cD, smem,
            [](int m, int n0, float v0, float v1) {
                const int bb = m >> 11, ss = m & 2047, hh = n0 >> 6, dd = n0 & 63;
                const size_t idx = (((size_t)(bb * 16 + hh)) * 2048 + ss) * 64 + dd;
                *(__half2*)&g_k16[idx] = __floats2half2_rn(v0, v1);
            });
    } else {
        GemmCore<false>::run(a, cD, b, nullptr, cD, mBase, nBase, cD, smem,
            [](int m, int n0, float v0, float v1) {
                const int bb = m >> 11, ss = m & 2047, hh = n0 >> 6, dd = n0 & 63;
                g_v16[(((size_t)(bb * 16 + hh)) * 64 + dd)     * 2048 + ss] = __float2half_rn(v0);
                g_v16[(((size_t)(bb * 16 + hh)) * 64 + dd + 1) * 2048 + ss] = __float2half_rn(v1);
            });
    }
}

// ---------------------------------------------------------------------------
// Output projection (dual-B, precision insurance): C fp32 = ctx16 * (Whi+Wlo)^T
// ---------------------------------------------------------------------------
__global__ __launch_bounds__(256, 2)
void outproj_kernel(float* __restrict__ out)
{
    extern __shared__ __align__(16) uint8_t smem[];
    const int mBase = blockIdx.y * 128;
    const int nBase = blockIdx.x * 128;

    GemmCore<true>::run(g_c16, cD, g_wohi, g_wolo, cD, mBase, nBase, cD, smem,
        [out](int m, int n0, float v0, float v1) {
            *(float2*)&out[(size_t)m * cD + n0] = make_float2(v0, v1);
        });
}

// ---------------------------------------------------------------------------
// Flash attention: per (q-tile 128, bh).  Q, K, V all single fp16.
// 3-stage K/V cp.async.
// ---------------------------------------------------------------------------
__global__ __launch_bounds__(256)
void flash_kernel()
{
    constexpr int QROWB = 144;
    constexpr int VROWB = 272;
    constexpr uint32_t OFF_ST0 = 128u * QROWB;          // 18432 (Q)
    constexpr uint32_t V_OFF   = 128u * QROWB;          // within stage (after K)
    constexpr uint32_t STAGE   = V_OFF + 64u * VROWB;   // 35840

    extern __shared__ __align__(16) uint8_t smem[];
    const uint32_t sm = smem_u32(smem);

    const int tid = threadIdx.x, lane = tid & 31, warp = tid >> 5;
    const int qt = blockIdx.x, bh = blockIdx.y;
    const int qBase = qt * 128;
    const int b = bh >> 4, h = bh & 15;
    const int lr = lane >> 2;
    const int lc2 = (lane & 3) * 2;
    const int row0 = qBase + warp * 16 + lr;
    const int row1 = row0 + 8;

    const __half* q16 = g_q16 + (size_t)bh * cS * cDK;
    const __half* k16 = g_k16 + (size_t)bh * cS * cDK;
    const __half* v16 = g_v16 + (size_t)bh * cDK * cS;

    auto issueKV = [&](int kt) {
        const uint32_t sb = sm + OFF_ST0 + (uint32_t)(kt % 3) * STAGE;
        const int kB = kt * 128;
#pragma unroll
        for (int i = 0; i < 4; i++) {
            int idx = tid + i * 256;
            int r = idx >> 3, ch = idx & 7;
            cpa16(sb + (uint32_t)(r * QROWB + ch * 16),
                  k16 + (size_t)(kB + r) * 64 + ch * 8);
        }
#pragma unroll
        for (int i = 0; i < 4; i++) {
            int idx = tid + i * 256;
            int dd = idx >> 4, ch = idx & 15;
            cpa16(sb + V_OFF + (uint32_t)(dd * VROWB + ch * 16),
                  v16 + (size_t)dd * cS + kB + ch * 8);
        }
        cpa_commit();
    };

    // group 0: Q + KV(0)
    {
#pragma unroll
        for (int i = 0; i < 4; i++) {
            int idx = tid + i * 256;
            int r = idx >> 3, ch = idx & 7;
            cpa16(sm + (uint32_t)(r * QROWB + ch * 16),
                  q16 + (size_t)(qBase + r) * 64 + ch * 8);
        }
        const uint32_t sb = sm + OFF_ST0;
#pragma unroll
        for (int i = 0; i < 4; i++) {
            int idx = tid + i * 256;
            int r = idx >> 3, ch = idx & 7;
            cpa16(sb + (uint32_t)(r * QROWB + ch * 16),
                  k16 + (size_t)r * 64 + ch * 8);
        }
#pragma unroll
        for (int i = 0; i < 4; i++) {
            int idx = tid + i * 256;
            int dd = idx >> 4, ch = idx & 15;
            cpa16(sb + V_OFF + (uint32_t)(dd * VROWB + ch * 16),
                  v16 + (size_t)dd * cS + ch * 8);
        }
        cpa_commit();
    }
    int issued = 1;
    issueKV(1); issued = 2;
    issueKV(2); issued = 3;

    float o[8][4];
#pragma unroll
    for (int dt = 0; dt < 8; dt++)
#pragma unroll
        for (int i = 0; i < 4; i++) o[dt][i] = 0.0f;
    float m0 = -1e30f, m1 = -1e30f, l0 = 0.0f, l1 = 0.0f;

    uint32_t qf[4][4];
    const uint32_t qaddr = sm + (uint32_t)((warp * 16 + (lane & 15)) * QROWB) + ((lane & 16) ? 16u : 0u);

    for (int kt = 0; kt < 16; ++kt) {
        cpa_wait(issued - kt - 1);
        __syncthreads();

        if (kt == 0) {
#pragma unroll
            for (int ks = 0; ks < 4; ks++)
                ldsm4(qf[ks], qaddr + ks * 32);
        }

        const uint32_t sb = sm + OFF_ST0 + (uint32_t)(kt % 3) * STAGE;
        const uint32_t kbo = sb + (uint32_t)((lane & 15) * QROWB) + ((lane & 16) ? 16u : 0u);
        const uint32_t vbo = sb + V_OFF + (uint32_t)((lane & 15) * VROWB) + ((lane & 16) ? 16u : 0u);

        // ---- S = Q K^T (single x single) ----
        float s[16][4];
#pragma unroll
        for (int nt = 0; nt < 16; nt++)
#pragma unroll
            for (int i = 0; i < 4; i++) s[nt][i] = 0.0f;

#pragma unroll
        for (int g = 0; g < 8; g++) {
#pragma unroll
            for (int ks = 0; ks < 4; ks++) {
                uint32_t kh[4];
                ldsm4(kh, kbo + (uint32_t)(g * 16 * QROWB) + ks * 32);
#pragma unroll
                for (int st2 = 0; st2 < 2; st2++)
                    mma16816(s[2 * g + st2], qf[ks], kh[0 + st2], kh[2 + st2]);
            }
        }

        // ---- online softmax ----
        float rm0 = -1e30f, rm1 = -1e30f;
#pragma unroll
        for (int nt = 0; nt < 16; nt++) {
            rm0 = fmaxf(rm0, fmaxf(s[nt][0], s[nt][1]));
            rm1 = fmaxf(rm1, fmaxf(s[nt][2], s[nt][3]));
        }
        rm0 = fmaxf(rm0, __shfl_xor_sync(0xffffffffu, rm0, 1));
        rm0 = fmaxf(rm0, __shfl_xor_sync(0xffffffffu, rm0, 2));
        rm1 = fmaxf(rm1, __shfl_xor_sync(0xffffffffu, rm1, 1));
        rm1 = fmaxf(rm1, __shfl_xor_sync(0xffffffffu, rm1, 2));

        const float mn0 = fmaxf(m0, rm0), mn1 = fmaxf(m1, rm1);
        const float sc0 = __expf(m0 - mn0), sc1 = __expf(m1 - mn1);
        m0 = mn0; m1 = mn1;

        float rs0 = 0.0f, rs1 = 0.0f;
#pragma unroll
        for (int nt = 0; nt < 16; nt++) {
            s[nt][0] = __expf(s[nt][0] - m0);
            s[nt][1] = __expf(s[nt][1] - m0);
            s[nt][2] = __expf(s[nt][2] - m1);
            s[nt][3] = __expf(s[nt][3] - m1);
            rs0 += s[nt][0] + s[nt][1];
            rs1 += s[nt][2] + s[nt][3];
        }
        rs0 += __shfl_xor_sync(0xffffffffu, rs0, 1);
        rs0 += __shfl_xor_sync(0xffffffffu, rs0, 2);
        rs1 += __shfl_xor_sync(0xffffffffu, rs1, 1);
        rs1 += __shfl_xor_sync(0xffffffffu, rs1, 2);
        l0 = l0 * sc0 + rs0;
        l1 = l1 * sc1 + rs1;

        // ---- store running max + unnormalized P (fp16) ----
        if ((lane & 3) == 0) {
            g_mrun[((size_t)bh * 16 + kt) * cS + row0] = m0;
            g_mrun[((size_t)bh * 16 + kt) * cS + row1] = m1;
        }
        {
            const int kB = kt * 128;
#pragma unroll
            for (int nt = 0; nt < 16; nt++) {
                const int col = kB + nt * 8 + lc2;
                *(__half2*)&g_ph[((size_t)bh * cS + row0) * cS + col] =
                    __floats2half2_rn(s[nt][0], s[nt][1]);
                *(__half2*)&g_ph[((size_t)bh * cS + row1) * cS + col] =
                    __floats2half2_rn(s[nt][2], s[nt][3]);
            }
        }

#pragma unroll
        for (int dt = 0; dt < 8; dt++) {
            o[dt][0] *= sc0; o[dt][1] *= sc0;
            o[dt][2] *= sc1; o[dt][3] *= sc1;
        }

        // ---- O += P16 V ----
#pragma unroll
        for (int ks2 = 0; ks2 < 8; ks2++) {
            uint32_t pa[4];
            pa[0] = pack2(s[2 * ks2][0],     s[2 * ks2][1]);
            pa[1] = pack2(s[2 * ks2][2],     s[2 * ks2][3]);
            pa[2] = pack2(s[2 * ks2 + 1][0], s[2 * ks2 + 1][1]);
            pa[3] = pack2(s[2 * ks2 + 1][2], s[2 * ks2 + 1][3]);
#pragma unroll
            for (int g = 0; g < 4; g++) {
                uint32_t vh[4];
                ldsm4(vh, vbo + (uint32_t)(g * 16 * VROWB) + ks2 * 32);
#pragma unroll
                for (int st2 = 0; st2 < 2; st2++)
                    mma16816(o[2 * g + st2], pa, vh[0 + st2], vh[2 + st2]);
            }
        }

        __syncthreads();
        if (issued < 16) { issueKV(issued); issued++; }
    }

    // ---- epilogue ----
    const float inv0 = 1.0f / l0, inv1 = 1.0f / l1;

    if ((lane & 3) == 0) {
        g_m[(size_t)bh * cS + row0] = m0;
        g_m[(size_t)bh * cS + row1] = m1;
        g_l[(size_t)bh * cS + row0] = l0;
        g_l[(size_t)bh * cS + row1] = l1;
    }

#pragma unroll
    for (int dt = 0; dt < 8; dt++) {
        const int d0 = dt * 8 + lc2;
        const size_t i0 = (((size_t)(b * cS + row0)) * cH + h) * cDK + d0;
        const size_t i1 = (((size_t)(b * cS + row1)) * cH + h) * cDK + d0;
        *(__half2*)&g_c16[i0] = __floats2half2_rn(o[dt][0] * inv0, o[dt][1] * inv0);
        *(__half2*)&g_c16[i1] = __floats2half2_rn(o[dt][2] * inv1, o[dt][3] * inv1);
    }
}

// ---------------------------------------------------------------------------
// Sim: sim[b,q,:] = sum_h g_ph[bh,q,:] * exp(m_run - m_final)/(16 l)
// ---------------------------------------------------------------------------
__global__ __launch_bounds__(256)
void simfast_kernel(float* __restrict__ sim)
{
    const int q = blockIdx.x;
    const int b = blockIdx.y;
    const int tid = threadIdx.x;
    const int kt  = tid >> 4;

    float acc[8] = {};

#pragma unroll 1
    for (int h = 0; h < cH; h++) {
        const int bh = b * cH + h;
        const float mf = __ldg(&g_m[(size_t)bh * cS + q]);
        const float mr = __ldg(&g_mrun[((size_t)bh * 16 + kt) * cS + q]);
        const float f  = __expf(mr - mf) / __ldg(&g_l[(size_t)bh * cS + q]) * 0.0625f;

        const uint4 raw = *(const uint4*)&g_ph[((size_t)bh * cS + q) * cS + tid * 8];
        const __half2* hp = (const __half2*)&raw;
#pragma unroll
        for (int i = 0; i < 4; i++) {
            float2 v = __half22float2(hp[i]);
            acc[2 * i + 0] += f * v.x;
            acc[2 * i + 1] += f * v.y;
        }
    }

    float* s = sim + ((size_t)b * cS + q) * cS + tid * 8;
    *(float4*)&s[0] = make_float4(acc[0], acc[1], acc[2], acc[3]);
    *(float4*)&s[4] = make_float4(acc[4], acc[5], acc[6], acc[7]);
}

// ---------------------------------------------------------------------------
// Launch — fork/join streams inside graph capture.
// ---------------------------------------------------------------------------
extern "C" void kernel_launch(void* const* d_in, const int* in_sizes, int n_in,
                              void* d_out, int out_size)
{
    const float* q_in  = (const float*)d_in[0];
    const float* k_in  = (const float*)d_in[1];
    const float* v_in  = (const float*)d_in[2];
    const float* w_in  = (const float*)d_in[3];
    const float* w_out = (const float*)d_in[4];

    float* out = (float*)d_out;
    float* sim = out + (size_t)cB * cS * cD;

    void *px, *pw, *pwh, *pwl;
    cudaGetSymbolAddress(&px, g_x16);
    cudaGetSymbolAddress(&pw, g_w16);
    cudaGetSymbolAddress(&pwh, g_wohi);
    cudaGetSymbolAddress(&pwl, g_wolo);
    __half *x16 = (__half*)px, *w16 = (__half*)pw;
    __half *wh = (__half*)pwh, *wl = (__half*)pwl;

    const int SMP = 2 * 128 * 80 * 2;            // 40960 proj (single-B, 2 stages)
    const int SMO = 3 * 128 * 80 * 2;            // 61440 outproj (dual-B)
    const int SMF = 18432 + 3 * 35840;           // 125952 flash
    cudaFuncSetAttribute((const void*)proj_kernel,    cudaFuncAttributeMaxDynamicSharedMemorySize, SMP);
    cudaFuncSetAttribute((const void*)outproj_kernel, cudaFuncAttributeMaxDynamicSharedMemorySize, SMO);
    cudaFuncSetAttribute((const void*)flash_kernel,   cudaFuncAttributeMaxDynamicSharedMemorySize, SMF);

    static cudaStream_t s1 = nullptr;
    static cudaEvent_t evFork = nullptr, evW = nullptr, evFlash = nullptr, evSim = nullptr;
    if (!s1) {
        cudaStreamCreateWithFlags(&s1, cudaStreamNonBlocking);
        cudaEventCreateWithFlags(&evFork,  cudaEventDisableTiming);
        cudaEventCreateWithFlags(&evW,     cudaEventDisableTiming);
        cudaEventCreateWithFlags(&evFlash, cudaEventDisableTiming);
        cudaEventCreateWithFlags(&evSim,   cudaEventDisableTiming);
    }

    // --- fork: weight converts on s1, input converts on stream 0 ---
    cudaEventRecord(evFork, 0);
    cudaStreamWaitEvent(s1, evFork, 0);

    const size_t nW3 = (size_t)3 * cD * cD;
    tofp16_kernel<<<(int)(nW3 / 4 / 256), 256, 0, s1>>>(w_in, w16, (int)(nW3 / 4));
    split16_kernel<<<(int)(cD * cD / 4 / 256), 256, 0, s1>>>(w_out, wh, wl, (int)(cD * cD / 4));

    tofp16_kernel<<<(int)(N_X1 / 4 / 256), 256>>>(q_in, x16,            (int)(N_X1 / 4));
    tofp16_kernel<<<(int)(N_X1 / 4 / 256), 256>>>(k_in, x16 + N_X1,     (int)(N_X1 / 4));
    tofp16_kernel<<<(int)(N_X1 / 4 / 256), 256>>>(v_in, x16 + 2 * N_X1, (int)(N_X1 / 4));

    cudaEventRecord(evW, s1);
    cudaStreamWaitEvent(0, evW, 0);

    // --- serial spine: proj -> flash ---
    proj_kernel<<<dim3(cD / 128, (cB * cS) / 128, 3), 256, SMP>>>();
    flash_kernel<<<dim3(cS / 128, cBH), 256, SMF>>>();

    // --- fork: simfast on s1 concurrent with outproj ---
    cudaEventRecord(evFlash, 0);
    cudaStreamWaitEvent(s1, evFlash, 0);

    simfast_kernel<<<dim3(cS, cB), 256, 0, s1>>>(sim);
    outproj_kernel<<<dim3(cD / 128, (cB * cS) / 128), 256, SMO>>>(out);

    cudaEventRecord(evSim, s1);
    cudaStreamWaitEvent(0, evSim, 0);
}